// round 8
// baseline (speedup 1.0000x reference)
#include <cuda_runtime.h>
#include <cstdint>

#define BATCH 2
#define SEQ   2048
#define NTOK  (BATCH * SEQ)
#define DM    1024
#define NC    3584

#define COL_QSA 0
#define COL_KSA 512
#define COL_VSA 1024
#define COL_QA  1536
#define COL_KA  2048
#define COL_QR  2560
#define COL_KR  3072

// Scratch (allocation-free rule: __device__ globals)
__device__ float g_proj [NTOK * NC];          // 7 fused projections of x
__device__ float g_sv   [NTOK * 512];         // symbols @ wv_ra^T
__device__ float g_sa   [NTOK * 512];         // SA context
__device__ float g_ra   [NTOK * 512];         // RA context
__device__ float g_attkr[16 * SEQ * 512];     // normalized alpha @ kr per (b,h)

struct W8 { const float* p[7]; };

// ---------------------------------------------------------------------------
// tf32 / mma / ldmatrix helpers
// ---------------------------------------------------------------------------
__device__ __forceinline__ float to_tf32(float x) {
    uint32_t u;
    asm("cvt.rna.tf32.f32 %0, %1;" : "=r"(u) : "f"(x));
    return __uint_as_float(u);
}
__device__ __forceinline__ float4 f4_tf32(float4 v) {
    return make_float4(to_tf32(v.x), to_tf32(v.y), to_tf32(v.z), to_tf32(v.w));
}
__device__ __forceinline__ void mma_tf32u(float* d, const uint32_t* a, const uint32_t* b) {
    asm volatile(
        "mma.sync.aligned.m16n8k8.row.col.f32.tf32.tf32.f32 "
        "{%0,%1,%2,%3}, {%4,%5,%6,%7}, {%8,%9}, {%0,%1,%2,%3};"
        : "+f"(d[0]), "+f"(d[1]), "+f"(d[2]), "+f"(d[3])
        : "r"(a[0]), "r"(a[1]), "r"(a[2]), "r"(a[3]), "r"(b[0]), "r"(b[1]));
}
__device__ __forceinline__ uint32_t sm_addr(const void* p) {
    return (uint32_t)__cvta_generic_to_shared(p);
}
__device__ __forceinline__ void ldsm4(uint32_t* r, uint32_t a) {
    asm volatile("ldmatrix.sync.aligned.m8n8.x4.shared.b16 {%0,%1,%2,%3}, [%4];"
        : "=r"(r[0]), "=r"(r[1]), "=r"(r[2]), "=r"(r[3]) : "r"(a));
}
__device__ __forceinline__ void ldsm2(uint32_t* r, uint32_t a) {
    asm volatile("ldmatrix.sync.aligned.m8n8.x2.shared.b16 {%0,%1}, [%2];"
        : "=r"(r[0]), "=r"(r[1]) : "r"(a));
}

// ---------------------------------------------------------------------------
// tf32 tensor-core GEMM:  C[M,N] = A[M,K] @ W^T  — ldmatrix fragment loads.
// A selected per 512-col block (A for block 0, A2 for block 1+) so two
// output projections can share one launch. W selected per 512-col block.
// ---------------------------------------------------------------------------
__global__ void __launch_bounds__(256) gemm_tf32(
    const float* __restrict__ A, const float* __restrict__ A2,
    W8 w, float* __restrict__ C, int K, int ldC, int cOff)
{
    __shared__ float As[128][36];
    __shared__ float Bs[128][36];

    const int tid   = threadIdx.x;
    const int lane  = tid & 31;
    const int wid   = tid >> 5;
    const int warpM = wid >> 2;
    const int warpN = wid & 3;
    const int g     = lane >> 2;
    const int tig   = lane & 3;

    const int mBase = blockIdx.y * 128;
    const int nBase = blockIdx.x * 128;
    const int blk   = nBase >> 9;
    const float* Wm = w.p[blk];
    const float* Ab = blk ? A2 : A;
    const int wrow  = nBase & 511;

    const float* Aptr = Ab + (size_t)mBase * K;
    const float* Bptr = Wm + (size_t)wrow  * K;

    float acc[4][4][4];
    #pragma unroll
    for (int mi = 0; mi < 4; mi++)
        #pragma unroll
        for (int ni = 0; ni < 4; ni++)
            #pragma unroll
            for (int c = 0; c < 4; c++) acc[mi][ni][c] = 0.f;

    const int lrow  = (lane & 7) + ((lane >> 3) & 1) * 8;
    const int lcol4 = (lane >> 4) * 4;
    const int bcol4 = ((lane >> 3) & 1) * 4;
    uint32_t aB[4], bB[4];
    #pragma unroll
    for (int mi = 0; mi < 4; mi++)
        aB[mi] = sm_addr(&As[warpM*64 + mi*16 + lrow][lcol4]);
    #pragma unroll
    for (int ni = 0; ni < 4; ni++)
        bB[ni] = sm_addr(&Bs[warpN*32 + ni*8 + (lane & 7)][bcol4]);

    const int nT = K >> 5;
    float4 pa[4], pb[4];
    #pragma unroll
    for (int u = 0; u < 4; u++) {
        int s_ = tid + (u << 8);
        int r = s_ >> 3, q = s_ & 7;
        pa[u] = *(const float4*)(Aptr + (size_t)r * K + q * 4);
        pb[u] = *(const float4*)(Bptr + (size_t)r * K + q * 4);
    }

    for (int t = 0; t < nT; t++) {
        #pragma unroll
        for (int u = 0; u < 4; u++) {
            int s_ = tid + (u << 8);
            int r = s_ >> 3, q = s_ & 7;
            *(float4*)&As[r][q * 4] = f4_tf32(pa[u]);
            *(float4*)&Bs[r][q * 4] = f4_tf32(pb[u]);
        }
        __syncthreads();

        if (t + 1 < nT) {
            int k0 = (t + 1) << 5;
            #pragma unroll
            for (int u = 0; u < 4; u++) {
                int s_ = tid + (u << 8);
                int r = s_ >> 3, q = s_ & 7;
                pa[u] = *(const float4*)(Aptr + (size_t)r * K + k0 + q * 4);
                pb[u] = *(const float4*)(Bptr + (size_t)r * K + k0 + q * 4);
            }
        }

        #pragma unroll
        for (int ks = 0; ks < 4; ks++) {
            uint32_t a4[4][4], b2[4][2];
            #pragma unroll
            for (int mi = 0; mi < 4; mi++) ldsm4(a4[mi], aB[mi] + ks * 32);
            #pragma unroll
            for (int ni = 0; ni < 4; ni++) ldsm2(b2[ni], bB[ni] + ks * 32);
            #pragma unroll
            for (int mi = 0; mi < 4; mi++)
                #pragma unroll
                for (int ni = 0; ni < 4; ni++)
                    mma_tf32u(acc[mi][ni], a4[mi], b2[ni]);
        }
        __syncthreads();
    }

    #pragma unroll
    for (int mi = 0; mi < 4; mi++) {
        int row = mBase + warpM * 64 + mi * 16 + g;
        #pragma unroll
        for (int ni = 0; ni < 4; ni++) {
            int col = cOff + nBase + warpN * 32 + ni * 8 + tig * 2;
            *(float2*)&C[(size_t)row * ldC + col] =
                make_float2(acc[mi][ni][0], acc[mi][ni][1]);
            *(float2*)&C[(size_t)(row + 8) * ldC + col] =
                make_float2(acc[mi][ni][2], acc[mi][ni][3]);
        }
    }
}

// ---------------------------------------------------------------------------
// RoPE in-place (unchanged)
// ---------------------------------------------------------------------------
__global__ void rope_kernel(const float* __restrict__ fc, const float* __restrict__ fs)
{
    int idx = blockIdx.x * blockDim.x + threadIdx.x;
    int token  = idx >> 10;
    int p      = idx & 1023;
    int range  = p >> 9;
    int within = p & 511;
    int col0   = (range ? 1536 : 0) + within * 2;
    int t      = within & 31;
    int s_idx  = token & (SEQ - 1);

    float c  = fc[s_idx * 32 + t];
    float sn = fs[s_idx * 32 + t];
    float* ptr = g_proj + (size_t)token * NC + col0;
    float x0 = ptr[0], x1 = ptr[1];
    ptr[0] = x0 * c - x1 * sn;
    ptr[1] = x0 * sn + x1 * c;
}

// ---------------------------------------------------------------------------
// SA flash v5: Br=Bc=64, 256 thr / 8 warps. K and P share one smem buffer
// (K consumed before P written; existing syncs cover it) -> 55KB smem,
// 4 CTAs/SM.
// ---------------------------------------------------------------------------
#define SA5_SMEM ((64*68*2 + 64*72 + 64*3 + 256) * 4)

__global__ void __launch_bounds__(256) sa_flash5()
{
    extern __shared__ float sm[];
    float* sQ    = sm;               // [64][68]
    float* sKP   = sQ + 64*68;       // [64][68]  K then P
    float* sV    = sKP + 64*68;      // [64][72]
    float* sM    = sV + 64*72;       // [64]
    float* sL    = sM + 64;          // [64]
    float* sCorr = sL + 64;          // [64]
    float* sMaxP = sCorr + 64;       // [2][64]
    float* sSumP = sMaxP + 128;      // [2][64]

    const int tid  = threadIdx.x;
    const int lane = tid & 31, wid = tid >> 5;
    const int g    = lane >> 2, tig = lane & 3;
    const int wband = wid & 3, whalf = wid >> 2;
    const int r0   = wband * 16;
    const int b    = blockIdx.y >> 3, h = blockIdx.y & 7;
    const int bx   = gridDim.x - 1 - blockIdx.x;
    const int i0   = bx * 64;
    const int tbase = b * SEQ + i0;

    if (tid < 64) { sM[tid] = -1e30f; sL[tid] = 0.f; }

    #pragma unroll
    for (int u = 0; u < 4; u++) {
        int e = tid + (u << 8);
        int rr = e >> 4, d4 = e & 15;
        *(float4*)&sQ[rr*68 + d4*4] =
            f4_tf32(*(const float4*)(g_proj + (size_t)(tbase+rr)*NC + COL_QSA + h*64 + d4*4));
    }

    const int lrow  = (lane & 7) + ((lane >> 3) & 1) * 8;
    const int lcol4 = (lane >> 4) * 4;
    const int bcol4 = ((lane >> 3) & 1) * 4;
    const uint32_t aQb = sm_addr(&sQ[(r0 + lrow)*68 + lcol4]);
    const uint32_t aPb = sm_addr(&sKP[(r0 + lrow)*68 + lcol4]);
    uint32_t bKb[4];
    #pragma unroll
    for (int nt = 0; nt < 4; nt++)
        bKb[nt] = sm_addr(&sKP[(whalf*32 + nt*8 + (lane & 7))*68 + bcol4]);

    const int rA = r0 + g, rB = rA + 8;

    float o[4][4];
    #pragma unroll
    for (int nt = 0; nt < 4; nt++)
        #pragma unroll
        for (int c = 0; c < 4; c++) o[nt][c] = 0.f;

    const int nJT = bx + 1;
    for (int jt = 0; jt < nJT; jt++) {
        __syncthreads();                       // A: sKP/sV free for reload
        const int jb = b * SEQ + jt * 64;
        #pragma unroll
        for (int u = 0; u < 4; u++) {
            int e = tid + (u << 8);
            int rr = e >> 4, d4 = e & 15;
            const float* base = g_proj + (size_t)(jb+rr)*NC + h*64;
            *(float4*)&sKP[rr*68 + d4*4] = f4_tf32(*(const float4*)(base + COL_KSA + d4*4));
            *(float4*)&sV[rr*72 + d4*4]  = f4_tf32(*(const float4*)(base + COL_VSA + d4*4));
        }
        __syncthreads();                       // B

        // ---- S: each warp m16 x n32 ----
        float c_[4][4];
        #pragma unroll
        for (int nt = 0; nt < 4; nt++)
            #pragma unroll
            for (int q = 0; q < 4; q++) c_[nt][q] = 0.f;
        #pragma unroll
        for (int ks = 0; ks < 8; ks++) {
            uint32_t a4[4];
            ldsm4(a4, aQb + ks * 32);
            #pragma unroll
            for (int nt = 0; nt < 4; nt++) {
                uint32_t b2[2];
                ldsm2(b2, bKb[nt] + ks * 32);
                mma_tf32u(c_[nt], a4, b2);
            }
        }
        const int rowA = i0 + rA, rowB = i0 + rB;
        float rmA = -1e30f, rmB = -1e30f;
        #pragma unroll
        for (int nt = 0; nt < 4; nt++) {
            int col = jt*64 + whalf*32 + nt*8 + tig*2;
            c_[nt][0] = (col     <= rowA) ? c_[nt][0]*0.125f : -1e30f;
            c_[nt][1] = (col + 1 <= rowA) ? c_[nt][1]*0.125f : -1e30f;
            c_[nt][2] = (col     <= rowB) ? c_[nt][2]*0.125f : -1e30f;
            c_[nt][3] = (col + 1 <= rowB) ? c_[nt][3]*0.125f : -1e30f;
            rmA = fmaxf(rmA, fmaxf(c_[nt][0], c_[nt][1]));
            rmB = fmaxf(rmB, fmaxf(c_[nt][2], c_[nt][3]));
        }
        rmA = fmaxf(rmA, __shfl_xor_sync(0xffffffffu, rmA, 1));
        rmA = fmaxf(rmA, __shfl_xor_sync(0xffffffffu, rmA, 2));
        rmB = fmaxf(rmB, __shfl_xor_sync(0xffffffffu, rmB, 1));
        rmB = fmaxf(rmB, __shfl_xor_sync(0xffffffffu, rmB, 2));
        if (tig == 0) { sMaxP[whalf*64 + rA] = rmA; sMaxP[whalf*64 + rB] = rmB; }
        __syncthreads();                       // C: K fully consumed

        float newmA = fmaxf(sM[rA], fmaxf(sMaxP[rA], sMaxP[64 + rA]));
        float newmB = fmaxf(sM[rB], fmaxf(sMaxP[rB], sMaxP[64 + rB]));
        float corrA = __expf(sM[rA] - newmA);
        float corrB = __expf(sM[rB] - newmB);
        float sAcc = 0.f, sBcc = 0.f;
        #pragma unroll
        for (int nt = 0; nt < 4; nt++) {
            float p0 = __expf(c_[nt][0] - newmA);
            float p1 = __expf(c_[nt][1] - newmA);
            float p2 = __expf(c_[nt][2] - newmB);
            float p3 = __expf(c_[nt][3] - newmB);
            sAcc += p0 + p1; sBcc += p2 + p3;
            *(float2*)&sKP[rA*68 + whalf*32 + nt*8 + tig*2] = make_float2(to_tf32(p0), to_tf32(p1));
            *(float2*)&sKP[rB*68 + whalf*32 + nt*8 + tig*2] = make_float2(to_tf32(p2), to_tf32(p3));
        }
        sAcc += __shfl_xor_sync(0xffffffffu, sAcc, 1);
        sAcc += __shfl_xor_sync(0xffffffffu, sAcc, 2);
        sBcc += __shfl_xor_sync(0xffffffffu, sBcc, 1);
        sBcc += __shfl_xor_sync(0xffffffffu, sBcc, 2);
        if (tig == 0) { sSumP[whalf*64 + rA] = sAcc; sSumP[whalf*64 + rB] = sBcc; }
        if (whalf == 0 && tig == 0) { sCorr[rA] = corrA; sCorr[rB] = corrB; }
        __syncthreads();                       // D: P visible

        if (whalf == 0 && tig == 0) {
            sM[rA] = newmA; sL[rA] = sL[rA]*corrA + sSumP[rA] + sSumP[64 + rA];
            sM[rB] = newmB; sL[rB] = sL[rB]*corrB + sSumP[rB] + sSumP[64 + rB];
        }

        // ---- PV: each warp m16 x n32 ----
        {
            float cA = sCorr[rA], cB = sCorr[rB];
            #pragma unroll
            for (int nt = 0; nt < 4; nt++) {
                o[nt][0] *= cA; o[nt][1] *= cA;
                o[nt][2] *= cB; o[nt][3] *= cB;
            }
        }
        #pragma unroll
        for (int ks = 0; ks < 8; ks++) {
            uint32_t a4[4];
            ldsm4(a4, aPb + ks * 32);
            const int kc = ks*8 + tig;
            #pragma unroll
            for (int nt = 0; nt < 4; nt++) {
                const int n_ = whalf*32 + nt*8 + g;
                uint32_t b2[2];
                b2[0] = __float_as_uint(sV[kc*72 + n_]);
                b2[1] = __float_as_uint(sV[(kc+4)*72 + n_]);
                mma_tf32u(o[nt], a4, b2);
            }
        }
    }

    __syncthreads();
    {
        const float invA = 1.f / sL[rA];
        const float invB = 1.f / sL[rB];
        #pragma unroll
        for (int nt = 0; nt < 4; nt++) {
            int col = whalf*32 + nt*8 + tig*2;
            *(float2*)&g_sa[(size_t)(tbase+rA)*512 + h*64 + col] =
                make_float2(o[nt][0]*invA, o[nt][1]*invA);
            *(float2*)&g_sa[(size_t)(tbase+rB)*512 + h*64 + col] =
                make_float2(o[nt][2]*invB, o[nt][3]*invB);
        }
    }
}

// ---------------------------------------------------------------------------
// RA flash v5: extended V = [sv(64) | kr(512)], d_v=576. Br=Bc=64,
// 1024 thr / 32 warps = 4 row-bands x 8 column-groups (72 d-cols each,
// o[9][4] = 36 accum regs). K/P share a buffer. 8-way softmax combine.
// ---------------------------------------------------------------------------
#define RA5_SMEM ((64*68*2 + 64*584 + 64*3 + 8*64*2) * 4)

__global__ void __launch_bounds__(1024) ra_flash5()
{
    extern __shared__ float sm[];
    float* sQ    = sm;               // [64][68]
    float* sKP   = sQ + 64*68;       // [64][68]  K then P
    float* sV    = sKP + 64*68;      // [64][584]
    float* sM    = sV + 64*584;      // [64]
    float* sL    = sM + 64;          // [64]
    float* sCorr = sL + 64;          // [64]
    float* sMaxP = sCorr + 64;       // [8][64]
    float* sSumP = sMaxP + 512;      // [8][64]

    const int tid  = threadIdx.x;
    const int lane = tid & 31, wid = tid >> 5;
    const int g    = lane >> 2, tig = lane & 3;
    const int wband = wid & 3, grp = wid >> 2;      // 4 bands x 8 groups
    const int r0   = wband * 16;
    const int b    = blockIdx.y >> 3, h = blockIdx.y & 7;
    const int bx   = gridDim.x - 1 - blockIdx.x;
    const int i0   = bx * 64;
    const int tbase = b * SEQ + i0;

    if (tid < 64) { sM[tid] = -1e30f; sL[tid] = 0.f; }

    {
        int rr = tid >> 4, d4 = tid & 15;           // 1024 = 64 x 16
        *(float4*)&sQ[rr*68 + d4*4] =
            f4_tf32(*(const float4*)(g_proj + (size_t)(tbase+rr)*NC + COL_QA + h*64 + d4*4));
    }

    const int lrow  = (lane & 7) + ((lane >> 3) & 1) * 8;
    const int lcol4 = (lane >> 4) * 4;
    const int bcol4 = ((lane >> 3) & 1) * 4;
    const uint32_t aQb = sm_addr(&sQ[(r0 + lrow)*68 + lcol4]);
    const uint32_t aPb = sm_addr(&sKP[(r0 + lrow)*68 + lcol4]);
    const uint32_t bKb = sm_addr(&sKP[(grp*8 + (lane & 7))*68 + bcol4]);

    const int rA = r0 + g, rB = rA + 8;

    float o[9][4];
    #pragma unroll
    for (int nt = 0; nt < 9; nt++)
        #pragma unroll
        for (int c = 0; c < 4; c++) o[nt][c] = 0.f;

    const int nJT = bx + 1;
    for (int jt = 0; jt < nJT; jt++) {
        __syncthreads();                       // A
        const int jb = b * SEQ + jt * 64;
        {
            int rr = tid >> 4, d4 = tid & 15;
            *(float4*)&sKP[rr*68 + d4*4] =
                f4_tf32(*(const float4*)(g_proj + (size_t)(jb+rr)*NC + COL_KA + h*64 + d4*4));
        }
        for (int e = tid; e < 64 * 146; e += 1024) {
            int rr = e / 146, c4 = e - rr * 146;
            float4 v;
            if (c4 < 16)
                v = *(const float4*)(g_sv + (size_t)(jb+rr)*512 + h*64 + c4*4);
            else
                v = *(const float4*)(g_proj + (size_t)(jb+rr)*NC + COL_KR + (c4-16)*4);
            *(float4*)&sV[rr*584 + c4*4] = f4_tf32(v);
        }
        __syncthreads();                       // B

        // ---- S: each warp m16 x n8 ----
        float c_[4] = {0.f, 0.f, 0.f, 0.f};
        #pragma unroll
        for (int ks = 0; ks < 8; ks++) {
            uint32_t a4[4], b2[2];
            ldsm4(a4, aQb + ks * 32);
            ldsm2(b2, bKb + ks * 32);
            mma_tf32u(c_, a4, b2);
        }
        const int rowA = i0 + rA, rowB = i0 + rB;
        {
            int col = jt*64 + grp*8 + tig*2;
            c_[0] = (col     <= rowA) ? c_[0]*0.125f : -1e30f;
            c_[1] = (col + 1 <= rowA) ? c_[1]*0.125f : -1e30f;
            c_[2] = (col     <= rowB) ? c_[2]*0.125f : -1e30f;
            c_[3] = (col + 1 <= rowB) ? c_[3]*0.125f : -1e30f;
        }
        float rmA = fmaxf(c_[0], c_[1]);
        float rmB = fmaxf(c_[2], c_[3]);
        rmA = fmaxf(rmA, __shfl_xor_sync(0xffffffffu, rmA, 1));
        rmA = fmaxf(rmA, __shfl_xor_sync(0xffffffffu, rmA, 2));
        rmB = fmaxf(rmB, __shfl_xor_sync(0xffffffffu, rmB, 1));
        rmB = fmaxf(rmB, __shfl_xor_sync(0xffffffffu, rmB, 2));
        if (tig == 0) { sMaxP[grp*64 + rA] = rmA; sMaxP[grp*64 + rB] = rmB; }
        __syncthreads();                       // C: K consumed

        float newmA = sM[rA], newmB = sM[rB];
        #pragma unroll
        for (int q2 = 0; q2 < 8; q2++) {
            newmA = fmaxf(newmA, sMaxP[q2*64 + rA]);
            newmB = fmaxf(newmB, sMaxP[q2*64 + rB]);
        }
        float corrA = __expf(sM[rA] - newmA);
        float corrB = __expf(sM[rB] - newmB);
        float p0 = __expf(c_[0] - newmA);
        float p1 = __expf(c_[1] - newmA);
        float p2 = __expf(c_[2] - newmB);
        float p3 = __expf(c_[3] - newmB);
        *(float2*)&sKP[rA*68 + grp*8 + tig*2] = make_float2(to_tf32(p0), to_tf32(p1));
        *(float2*)&sKP[rB*68 + grp*8 + tig*2] = make_float2(to_tf32(p2), to_tf32(p3));
        float sAcc = p0 + p1, sBcc = p2 + p3;
        sAcc += __shfl_xor_sync(0xffffffffu, sAcc, 1);
        sAcc += __shfl_xor_sync(0xffffffffu, sAcc, 2);
        sBcc += __shfl_xor_sync(0xffffffffu, sBcc, 1);
        sBcc += __shfl_xor_sync(0xffffffffu, sBcc, 2);
        if (tig == 0) { sSumP[grp*64 + rA] = sAcc; sSumP[grp*64 + rB] = sBcc; }
        if (grp == 0 && tig == 0) { sCorr[rA] = corrA; sCorr[rB] = corrB; }
        __syncthreads();                       // D: P visible

        if (grp == 0 && tig == 0) {
            float la = sL[rA]*corrA, lb = sL[rB]*corrB;
            #pragma unroll
            for (int q2 = 0; q2 < 8; q2++) {
                la += sSumP[q2*64 + rA];
                lb += sSumP[q2*64 + rB];
            }
            sM[rA] = newmA; sL[rA] = la;
            sM[rB] = newmB; sL[rB] = lb;
        }

        // ---- PV: warp (band rows, 72-col group) ----
        {
            float cA = sCorr[rA], cB = sCorr[rB];
            #pragma unroll
            for (int nt = 0; nt < 9; nt++) {
                o[nt][0] *= cA; o[nt][1] *= cA;
                o[nt][2] *= cB; o[nt][3] *= cB;
            }
        }
        #pragma unroll
        for (int ks = 0; ks < 8; ks++) {
            uint32_t a4[4];
            ldsm4(a4, aPb + ks * 32);
            const int kc = ks*8 + tig;
            #pragma unroll
            for (int nt = 0; nt < 9; nt++) {
                const int n_ = grp*72 + nt*8 + g;
                uint32_t b2[2];
                b2[0] = __float_as_uint(sV[kc*584 + n_]);
                b2[1] = __float_as_uint(sV[(kc+4)*584 + n_]);
                mma_tf32u(o[nt], a4, b2);
            }
        }
    }

    __syncthreads();
    {
        const float invA = 1.f / sL[rA];
        const float invB = 1.f / sL[rB];
        const size_t akBase = ((size_t)blockIdx.y * SEQ + i0);
        #pragma unroll
        for (int nt = 0; nt < 9; nt++) {
            int col = grp*72 + nt*8 + tig*2;
            float2 vA = make_float2(o[nt][0]*invA, o[nt][1]*invA);
            float2 vB = make_float2(o[nt][2]*invB, o[nt][3]*invB);
            if (col < 64) {
                *(float2*)&g_ra[(size_t)(tbase+rA)*512 + h*64 + col] = vA;
                *(float2*)&g_ra[(size_t)(tbase+rB)*512 + h*64 + col] = vB;
            } else {
                *(float2*)&g_attkr[(akBase + rA)*512 + col - 64] = vA;
                *(float2*)&g_attkr[(akBase + rB)*512 + col - 64] = vB;
            }
        }
    }
}

// ---------------------------------------------------------------------------
// ra_post (unchanged): rel epilogue via wr into g_ra.
// ---------------------------------------------------------------------------
__global__ void __launch_bounds__(256) ra_post(const float* __restrict__ wr)
{
    const int lane = threadIdx.x & 31;
    const int wid  = threadIdx.x >> 5;
    const int job  = blockIdx.x * 8 + wid;
    const int h     = job & 7;
    const int token = job >> 3;
    const int bb    = token >> 11;
    const int ii    = token & (SEQ - 1);

    const int r = lane >> 2, q = lane & 3;
    const float* qr = g_proj + (size_t)token * NC + COL_QR;
    const float* ak = g_attkr + (((size_t)(bb*8 + h)) * SEQ + ii) * 512;

    float part = 0.f;
    #pragma unroll
    for (int u = 0; u < 4; u++) {
        float4 qv = *(const float4*)(qr + r*64 + q*16 + u*4);
        float4 av = *(const float4*)(ak + r*64 + q*16 + u*4);
        part += qv.x*av.x + qv.y*av.y + qv.z*av.z + qv.w*av.w;
    }
    part += __shfl_xor_sync(0xffffffffu, part, 1);
    part += __shfl_xor_sync(0xffffffffu, part, 2);
    part *= 0.125f;

    float pr[8];
    #pragma unroll
    for (int r2 = 0; r2 < 8; r2++)
        pr[r2] = __shfl_sync(0xffffffffu, part, r2 << 2);

    const float* wrh = wr + h * 512;
    float* dst = g_ra + (size_t)token * 512 + h * 64;
    #pragma unroll
    for (int dd = 0; dd < 2; dd++) {
        int d = lane * 2 + dd;
        float ro = 0.f;
        #pragma unroll
        for (int r2 = 0; r2 < 8; r2++)
            ro += pr[r2] * wrh[d*8 + r2];
        dst[d] += ro;
    }
}

// ---------------------------------------------------------------------------
extern "C" void kernel_launch(void* const* d_in, const int* in_sizes, int n_in,
                              void* d_out, int out_size)
{
    (void)in_sizes; (void)n_in; (void)out_size;
    const float* x      = (const float*)d_in[0];
    const float* symb   = (const float*)d_in[1];
    const float* fc     = (const float*)d_in[2];
    const float* fs     = (const float*)d_in[3];
    const float* wq_sa  = (const float*)d_in[4];
    const float* wk_sa  = (const float*)d_in[5];
    const float* wv_sa  = (const float*)d_in[6];
    const float* wo_sa  = (const float*)d_in[7];
    const float* wq_at  = (const float*)d_in[8];
    const float* wk_at  = (const float*)d_in[9];
    const float* wq_rel = (const float*)d_in[10];
    const float* wk_rel = (const float*)d_in[11];
    const float* wr     = (const float*)d_in[12];
    const float* wv_ra  = (const float*)d_in[13];
    const float* wo_ra  = (const float*)d_in[14];
    float* out = (float*)d_out;

    float *proj, *svb, *sab, *rab;
    cudaGetSymbolAddress((void**)&proj, g_proj);
    cudaGetSymbolAddress((void**)&svb,  g_sv);
    cudaGetSymbolAddress((void**)&sab,  g_sa);
    cudaGetSymbolAddress((void**)&rab,  g_ra);

    cudaFuncSetAttribute(sa_flash5, cudaFuncAttributeMaxDynamicSharedMemorySize, SA5_SMEM);
    cudaFuncSetAttribute(ra_flash5, cudaFuncAttributeMaxDynamicSharedMemorySize, RA5_SMEM);

    // 1) fused projections of x
    W8 w7;
    w7.p[0] = wq_sa; w7.p[1] = wk_sa; w7.p[2] = wv_sa;
    w7.p[3] = wq_at; w7.p[4] = wk_at; w7.p[5] = wq_rel; w7.p[6] = wk_rel;
    gemm_tf32<<<dim3(NC / 128, NTOK / 128), 256>>>(x, x, w7, proj, DM, NC, 0);

    // 2) sv = symbols @ wv_ra^T
    W8 wv; for (int i = 0; i < 7; i++) wv.p[i] = wv_ra;
    gemm_tf32<<<dim3(4, NTOK / 128), 256>>>(symb, symb, wv, svb, DM, 512, 0);

    // 3) RoPE
    rope_kernel<<<(NTOK * 1024) / 256, 256>>>(fc, fs);

    // 4) SA flash
    sa_flash5<<<dim3(SEQ / 64, BATCH * 8), 256, SA5_SMEM>>>();

    // 5) RA flash + rel post pass
    ra_flash5<<<dim3(SEQ / 64, BATCH * 8), 1024, RA5_SMEM>>>();
    ra_post<<<NTOK, 256>>>(wr);

    // 6) both output projections in ONE launch (A/W selected per 512-col blk)
    W8 wo;
    wo.p[0] = wo_sa; wo.p[1] = wo_ra;
    for (int i = 2; i < 7; i++) wo.p[i] = wo_sa;
    gemm_tf32<<<dim3(8, NTOK / 128), 256>>>(sab, rab, wo, out, 512, 1024, 0);
}

// round 9
// speedup vs baseline: 1.0623x; 1.0623x over previous
#include <cuda_runtime.h>
#include <cstdint>

#define BATCH 2
#define SEQ   2048
#define NTOK  (BATCH * SEQ)
#define DM    1024
#define NC    3584

#define COL_QSA 0
#define COL_KSA 512
#define COL_VSA 1024
#define COL_QA  1536
#define COL_KA  2048
#define COL_QR  2560
#define COL_KR  3072

// Scratch (allocation-free rule: __device__ globals)
__device__ float g_proj [NTOK * NC];          // 7 fused projections of x
__device__ float g_sv   [NTOK * 512];         // symbols @ wv_ra^T
__device__ float g_sa   [NTOK * 512];         // SA context
__device__ float g_ra   [NTOK * 512];         // RA context
__device__ float g_attkr[16 * SEQ * 512];     // normalized alpha @ kr per (b,h)

struct W8 { const float* p[8]; };

// ---------------------------------------------------------------------------
// tf32 / mma / ldmatrix helpers
// ---------------------------------------------------------------------------
__device__ __forceinline__ float to_tf32(float x) {
    uint32_t u;
    asm("cvt.rna.tf32.f32 %0, %1;" : "=r"(u) : "f"(x));
    return __uint_as_float(u);
}
__device__ __forceinline__ float4 f4_tf32(float4 v) {
    return make_float4(to_tf32(v.x), to_tf32(v.y), to_tf32(v.z), to_tf32(v.w));
}
__device__ __forceinline__ void mma_tf32u(float* d, const uint32_t* a, const uint32_t* b) {
    asm volatile(
        "mma.sync.aligned.m16n8k8.row.col.f32.tf32.tf32.f32 "
        "{%0,%1,%2,%3}, {%4,%5,%6,%7}, {%8,%9}, {%0,%1,%2,%3};"
        : "+f"(d[0]), "+f"(d[1]), "+f"(d[2]), "+f"(d[3])
        : "r"(a[0]), "r"(a[1]), "r"(a[2]), "r"(a[3]), "r"(b[0]), "r"(b[1]));
}
__device__ __forceinline__ uint32_t sm_addr(const void* p) {
    return (uint32_t)__cvta_generic_to_shared(p);
}
__device__ __forceinline__ void ldsm4(uint32_t* r, uint32_t a) {
    asm volatile("ldmatrix.sync.aligned.m8n8.x4.shared.b16 {%0,%1,%2,%3}, [%4];"
        : "=r"(r[0]), "=r"(r[1]), "=r"(r[2]), "=r"(r[3]) : "r"(a));
}
__device__ __forceinline__ void ldsm2(uint32_t* r, uint32_t a) {
    asm volatile("ldmatrix.sync.aligned.m8n8.x2.shared.b16 {%0,%1}, [%2];"
        : "=r"(r[0]), "=r"(r[1]) : "r"(a));
}

// ---------------------------------------------------------------------------
// tf32 tensor-core GEMM:  C[M,N] = A[M,K] @ W^T  — ldmatrix fragment loads.
// Per 512-col block `blk`:
//   blk < 7 : A (x), writes C (g_proj cols blk*512..), fused RoPE if fc!=null
//   blk == 7: A2 (symbols), writes C2 (g_sv, ldC 512)
// For output projections (grid.x=8): blk 0 -> A, blk 1 -> A2, writes C.
// ---------------------------------------------------------------------------
__global__ void __launch_bounds__(256) gemm_tf32(
    const float* __restrict__ A, const float* __restrict__ A2,
    W8 w, float* __restrict__ C, float* __restrict__ C2,
    int K, int ldC,
    const float* __restrict__ fc, const float* __restrict__ fs)
{
    __shared__ float As[128][36];
    __shared__ float Bs[128][36];

    const int tid   = threadIdx.x;
    const int lane  = tid & 31;
    const int wid   = tid >> 5;
    const int warpM = wid >> 2;
    const int warpN = wid & 3;
    const int g     = lane >> 2;
    const int tig   = lane & 3;

    const int mBase = blockIdx.y * 128;
    const int nBase = blockIdx.x * 128;
    const int blk   = nBase >> 9;
    const float* Wm = w.p[blk];
    const float* Ab = blk ? A2 : A;
    const bool  svBlk = (blk == 7) && (C2 != nullptr);
    if (svBlk) Ab = A2;
    else if (C2 != nullptr) Ab = A;          // proj launch: blocks 0..6 use x
    const int wrow  = nBase & 511;

    const float* Aptr = Ab + (size_t)mBase * K;
    const float* Bptr = Wm + (size_t)wrow  * K;

    float acc[4][4][4];
    #pragma unroll
    for (int mi = 0; mi < 4; mi++)
        #pragma unroll
        for (int ni = 0; ni < 4; ni++)
            #pragma unroll
            for (int c = 0; c < 4; c++) acc[mi][ni][c] = 0.f;

    const int lrow  = (lane & 7) + ((lane >> 3) & 1) * 8;
    const int lcol4 = (lane >> 4) * 4;
    const int bcol4 = ((lane >> 3) & 1) * 4;
    uint32_t aB[4], bB[4];
    #pragma unroll
    for (int mi = 0; mi < 4; mi++)
        aB[mi] = sm_addr(&As[warpM*64 + mi*16 + lrow][lcol4]);
    #pragma unroll
    for (int ni = 0; ni < 4; ni++)
        bB[ni] = sm_addr(&Bs[warpN*32 + ni*8 + (lane & 7)][bcol4]);

    const int nT = K >> 5;
    float4 pa[4], pb[4];
    #pragma unroll
    for (int u = 0; u < 4; u++) {
        int s_ = tid + (u << 8);
        int r = s_ >> 3, q = s_ & 7;
        pa[u] = *(const float4*)(Aptr + (size_t)r * K + q * 4);
        pb[u] = *(const float4*)(Bptr + (size_t)r * K + q * 4);
    }

    for (int t = 0; t < nT; t++) {
        #pragma unroll
        for (int u = 0; u < 4; u++) {
            int s_ = tid + (u << 8);
            int r = s_ >> 3, q = s_ & 7;
            *(float4*)&As[r][q * 4] = f4_tf32(pa[u]);
            *(float4*)&Bs[r][q * 4] = f4_tf32(pb[u]);
        }
        __syncthreads();

        if (t + 1 < nT) {
            int k0 = (t + 1) << 5;
            #pragma unroll
            for (int u = 0; u < 4; u++) {
                int s_ = tid + (u << 8);
                int r = s_ >> 3, q = s_ & 7;
                pa[u] = *(const float4*)(Aptr + (size_t)r * K + k0 + q * 4);
                pb[u] = *(const float4*)(Bptr + (size_t)r * K + k0 + q * 4);
            }
        }

        #pragma unroll
        for (int ks = 0; ks < 4; ks++) {
            uint32_t a4[4][4], b2[4][2];
            #pragma unroll
            for (int mi = 0; mi < 4; mi++) ldsm4(a4[mi], aB[mi] + ks * 32);
            #pragma unroll
            for (int ni = 0; ni < 4; ni++) ldsm2(b2[ni], bB[ni] + ks * 32);
            #pragma unroll
            for (int mi = 0; mi < 4; mi++)
                #pragma unroll
                for (int ni = 0; ni < 4; ni++)
                    mma_tf32u(acc[mi][ni], a4[mi], b2[ni]);
        }
        __syncthreads();
    }

    // ------------------- epilogue (fused RoPE / sv redirect) ----------------
    #pragma unroll
    for (int mi = 0; mi < 4; mi++) {
        int row = mBase + warpM * 64 + mi * 16 + g;
        int s0 = row & (SEQ - 1);
        int s1 = (row + 8) & (SEQ - 1);
        #pragma unroll
        for (int ni = 0; ni < 4; ni++) {
            int col = nBase + warpN * 32 + ni * 8 + tig * 2;
            float v0 = acc[mi][ni][0], v1 = acc[mi][ni][1];
            float v2 = acc[mi][ni][2], v3 = acc[mi][ni][3];
            if (fc != nullptr && !svBlk &&
                (col < 1024 || (col >= 1536 && col < 2560))) {
                int tt = (col & 63) >> 1;
                float c0 = fc[s0*32 + tt], sn0 = fs[s0*32 + tt];
                float c1 = fc[s1*32 + tt], sn1 = fs[s1*32 + tt];
                float n0 = v0*c0 - v1*sn0, n1 = v0*sn0 + v1*c0;
                float n2 = v2*c1 - v3*sn1, n3 = v2*sn1 + v3*c1;
                v0 = n0; v1 = n1; v2 = n2; v3 = n3;
            }
            if (svBlk) {
                int csv = (nBase - 3584) + warpN * 32 + ni * 8 + tig * 2;
                *(float2*)&C2[(size_t)row * 512 + csv] = make_float2(v0, v1);
                *(float2*)&C2[(size_t)(row + 8) * 512 + csv] = make_float2(v2, v3);
            } else {
                *(float2*)&C[(size_t)row * ldC + col] = make_float2(v0, v1);
                *(float2*)&C[(size_t)(row + 8) * ldC + col] = make_float2(v2, v3);
            }
        }
    }
}

// ---------------------------------------------------------------------------
// SA flash v4 (reverted, proven): Br=Bc=64, 256 thr / 8 warps.
// ---------------------------------------------------------------------------
#define SA4_SMEM ((64*68*3 + 64*72 + 512) * 4)

__global__ void __launch_bounds__(256) sa_flash4()
{
    extern __shared__ float sm[];
    float* sQ    = sm;               // [64][68]
    float* sK    = sQ + 64*68;       // [64][68]
    float* sP    = sK + 64*68;       // [64][68]
    float* sV    = sP + 64*68;       // [64][72]
    float* sM    = sV + 64*72;       // [64]
    float* sL    = sM + 64;          // [64]
    float* sCorr = sL + 64;          // [64]
    float* sMaxP = sCorr + 64;       // [2][64]
    float* sSumP = sMaxP + 128;      // [2][64]

    const int tid  = threadIdx.x;
    const int lane = tid & 31, wid = tid >> 5;
    const int g    = lane >> 2, tig = lane & 3;
    const int wband = wid & 3, whalf = wid >> 2;
    const int r0   = wband * 16;
    const int b    = blockIdx.y >> 3, h = blockIdx.y & 7;
    const int bx   = gridDim.x - 1 - blockIdx.x;
    const int i0   = bx * 64;
    const int tbase = b * SEQ + i0;

    if (tid < 64) { sM[tid] = -1e30f; sL[tid] = 0.f; }

    #pragma unroll
    for (int u = 0; u < 4; u++) {
        int e = tid + (u << 8);
        int rr = e >> 4, d4 = e & 15;
        *(float4*)&sQ[rr*68 + d4*4] =
            f4_tf32(*(const float4*)(g_proj + (size_t)(tbase+rr)*NC + COL_QSA + h*64 + d4*4));
    }

    const int lrow  = (lane & 7) + ((lane >> 3) & 1) * 8;
    const int lcol4 = (lane >> 4) * 4;
    const int bcol4 = ((lane >> 3) & 1) * 4;
    const uint32_t aQb = sm_addr(&sQ[(r0 + lrow)*68 + lcol4]);
    const uint32_t aPb = sm_addr(&sP[(r0 + lrow)*68 + lcol4]);
    uint32_t bKb[4];
    #pragma unroll
    for (int nt = 0; nt < 4; nt++)
        bKb[nt] = sm_addr(&sK[(whalf*32 + nt*8 + (lane & 7))*68 + bcol4]);

    const int rA = r0 + g, rB = rA + 8;

    float o[4][4];
    #pragma unroll
    for (int nt = 0; nt < 4; nt++)
        #pragma unroll
        for (int c = 0; c < 4; c++) o[nt][c] = 0.f;

    const int nJT = bx + 1;
    for (int jt = 0; jt < nJT; jt++) {
        __syncthreads();
        const int jb = b * SEQ + jt * 64;
        #pragma unroll
        for (int u = 0; u < 4; u++) {
            int e = tid + (u << 8);
            int rr = e >> 4, d4 = e & 15;
            const float* base = g_proj + (size_t)(jb+rr)*NC + h*64;
            *(float4*)&sK[rr*68 + d4*4] = f4_tf32(*(const float4*)(base + COL_KSA + d4*4));
            *(float4*)&sV[rr*72 + d4*4] = f4_tf32(*(const float4*)(base + COL_VSA + d4*4));
        }
        __syncthreads();

        float c_[4][4];
        #pragma unroll
        for (int nt = 0; nt < 4; nt++)
            #pragma unroll
            for (int q = 0; q < 4; q++) c_[nt][q] = 0.f;
        #pragma unroll
        for (int ks = 0; ks < 8; ks++) {
            uint32_t a4[4];
            ldsm4(a4, aQb + ks * 32);
            #pragma unroll
            for (int nt = 0; nt < 4; nt++) {
                uint32_t b2[2];
                ldsm2(b2, bKb[nt] + ks * 32);
                mma_tf32u(c_[nt], a4, b2);
            }
        }
        const int rowA = i0 + rA, rowB = i0 + rB;
        float rmA = -1e30f, rmB = -1e30f;
        #pragma unroll
        for (int nt = 0; nt < 4; nt++) {
            int col = jt*64 + whalf*32 + nt*8 + tig*2;
            c_[nt][0] = (col     <= rowA) ? c_[nt][0]*0.125f : -1e30f;
            c_[nt][1] = (col + 1 <= rowA) ? c_[nt][1]*0.125f : -1e30f;
            c_[nt][2] = (col     <= rowB) ? c_[nt][2]*0.125f : -1e30f;
            c_[nt][3] = (col + 1 <= rowB) ? c_[nt][3]*0.125f : -1e30f;
            rmA = fmaxf(rmA, fmaxf(c_[nt][0], c_[nt][1]));
            rmB = fmaxf(rmB, fmaxf(c_[nt][2], c_[nt][3]));
        }
        rmA = fmaxf(rmA, __shfl_xor_sync(0xffffffffu, rmA, 1));
        rmA = fmaxf(rmA, __shfl_xor_sync(0xffffffffu, rmA, 2));
        rmB = fmaxf(rmB, __shfl_xor_sync(0xffffffffu, rmB, 1));
        rmB = fmaxf(rmB, __shfl_xor_sync(0xffffffffu, rmB, 2));
        if (tig == 0) { sMaxP[whalf*64 + rA] = rmA; sMaxP[whalf*64 + rB] = rmB; }
        __syncthreads();

        float newmA = fmaxf(sM[rA], fmaxf(sMaxP[rA], sMaxP[64 + rA]));
        float newmB = fmaxf(sM[rB], fmaxf(sMaxP[rB], sMaxP[64 + rB]));
        float corrA = __expf(sM[rA] - newmA);
        float corrB = __expf(sM[rB] - newmB);
        float sAcc = 0.f, sBcc = 0.f;
        #pragma unroll
        for (int nt = 0; nt < 4; nt++) {
            float p0 = __expf(c_[nt][0] - newmA);
            float p1 = __expf(c_[nt][1] - newmA);
            float p2 = __expf(c_[nt][2] - newmB);
            float p3 = __expf(c_[nt][3] - newmB);
            sAcc += p0 + p1; sBcc += p2 + p3;
            *(float2*)&sP[rA*68 + whalf*32 + nt*8 + tig*2] = make_float2(to_tf32(p0), to_tf32(p1));
            *(float2*)&sP[rB*68 + whalf*32 + nt*8 + tig*2] = make_float2(to_tf32(p2), to_tf32(p3));
        }
        sAcc += __shfl_xor_sync(0xffffffffu, sAcc, 1);
        sAcc += __shfl_xor_sync(0xffffffffu, sAcc, 2);
        sBcc += __shfl_xor_sync(0xffffffffu, sBcc, 1);
        sBcc += __shfl_xor_sync(0xffffffffu, sBcc, 2);
        if (tig == 0) { sSumP[whalf*64 + rA] = sAcc; sSumP[whalf*64 + rB] = sBcc; }
        if (whalf == 0 && tig == 0) { sCorr[rA] = corrA; sCorr[rB] = corrB; }
        __syncthreads();

        if (whalf == 0 && tig == 0) {
            sM[rA] = newmA; sL[rA] = sL[rA]*corrA + sSumP[rA] + sSumP[64 + rA];
            sM[rB] = newmB; sL[rB] = sL[rB]*corrB + sSumP[rB] + sSumP[64 + rB];
        }

        {
            float cA = sCorr[rA], cB = sCorr[rB];
            #pragma unroll
            for (int nt = 0; nt < 4; nt++) {
                o[nt][0] *= cA; o[nt][1] *= cA;
                o[nt][2] *= cB; o[nt][3] *= cB;
            }
        }
        #pragma unroll
        for (int ks = 0; ks < 8; ks++) {
            uint32_t a4[4];
            ldsm4(a4, aPb + ks * 32);
            const int kc = ks*8 + tig;
            #pragma unroll
            for (int nt = 0; nt < 4; nt++) {
                const int n_ = whalf*32 + nt*8 + g;
                uint32_t b2[2];
                b2[0] = __float_as_uint(sV[kc*72 + n_]);
                b2[1] = __float_as_uint(sV[(kc+4)*72 + n_]);
                mma_tf32u(o[nt], a4, b2);
            }
        }
    }

    __syncthreads();
    {
        const float invA = 1.f / sL[rA];
        const float invB = 1.f / sL[rB];
        #pragma unroll
        for (int nt = 0; nt < 4; nt++) {
            int col = whalf*32 + nt*8 + tig*2;
            *(float2*)&g_sa[(size_t)(tbase+rA)*512 + h*64 + col] =
                make_float2(o[nt][0]*invA, o[nt][1]*invA);
            *(float2*)&g_sa[(size_t)(tbase+rB)*512 + h*64 + col] =
                make_float2(o[nt][2]*invB, o[nt][3]*invB);
        }
    }
}

// ---------------------------------------------------------------------------
// RA flash v4 (reverted, proven): extended V = [sv(64) | kr(512)], d_v=576.
// Br=Bc=64, 512 thr / 16 warps.
// ---------------------------------------------------------------------------
#define RA4_SMEM ((64*68*3 + 64*584 + 704) * 4)

__global__ void __launch_bounds__(512) ra_flash4()
{
    extern __shared__ float sm[];
    float* sQ    = sm;               // [64][68]
    float* sK    = sQ + 64*68;       // [64][68]
    float* sP    = sK + 64*68;       // [64][68]
    float* sV    = sP + 64*68;       // [64][584]
    float* sM    = sV + 64*584;      // [64]
    float* sL    = sM + 64;          // [64]
    float* sCorr = sL + 64;          // [64]
    float* sMaxP = sCorr + 64;       // [4][64]
    float* sSumP = sMaxP + 256;      // [4][64]

    const int tid  = threadIdx.x;
    const int lane = tid & 31, wid = tid >> 5;
    const int g    = lane >> 2, tig = lane & 3;
    const int wband = wid & 3, wq = wid >> 2;
    const int r0   = wband * 16;
    const int b    = blockIdx.y >> 3, h = blockIdx.y & 7;
    const int bx   = gridDim.x - 1 - blockIdx.x;
    const int i0   = bx * 64;
    const int tbase = b * SEQ + i0;

    if (tid < 64) { sM[tid] = -1e30f; sL[tid] = 0.f; }

    #pragma unroll
    for (int u = 0; u < 2; u++) {
        int e = tid + (u << 9);
        int rr = e >> 4, d4 = e & 15;
        *(float4*)&sQ[rr*68 + d4*4] =
            f4_tf32(*(const float4*)(g_proj + (size_t)(tbase+rr)*NC + COL_QA + h*64 + d4*4));
    }

    const int lrow  = (lane & 7) + ((lane >> 3) & 1) * 8;
    const int lcol4 = (lane >> 4) * 4;
    const int bcol4 = ((lane >> 3) & 1) * 4;
    const uint32_t aQb = sm_addr(&sQ[(r0 + lrow)*68 + lcol4]);
    const uint32_t aPb = sm_addr(&sP[(r0 + lrow)*68 + lcol4]);
    uint32_t bKb[2];
    #pragma unroll
    for (int nt = 0; nt < 2; nt++)
        bKb[nt] = sm_addr(&sK[(wq*16 + nt*8 + (lane & 7))*68 + bcol4]);

    const int rA = r0 + g, rB = rA + 8;

    float o[18][4];
    #pragma unroll
    for (int nt = 0; nt < 18; nt++)
        #pragma unroll
        for (int c = 0; c < 4; c++) o[nt][c] = 0.f;

    const int nJT = bx + 1;
    for (int jt = 0; jt < nJT; jt++) {
        __syncthreads();
        const int jb = b * SEQ + jt * 64;
        #pragma unroll
        for (int u = 0; u < 2; u++) {
            int e = tid + (u << 9);
            int rr = e >> 4, d4 = e & 15;
            *(float4*)&sK[rr*68 + d4*4] =
                f4_tf32(*(const float4*)(g_proj + (size_t)(jb+rr)*NC + COL_KA + h*64 + d4*4));
        }
        for (int e = tid; e < 64 * 146; e += 512) {
            int rr = e / 146, c4 = e - rr * 146;
            float4 v;
            if (c4 < 16)
                v = *(const float4*)(g_sv + (size_t)(jb+rr)*512 + h*64 + c4*4);
            else
                v = *(const float4*)(g_proj + (size_t)(jb+rr)*NC + COL_KR + (c4-16)*4);
            *(float4*)&sV[rr*584 + c4*4] = f4_tf32(v);
        }
        __syncthreads();

        float c_[2][4];
        #pragma unroll
        for (int nt = 0; nt < 2; nt++)
            #pragma unroll
            for (int q = 0; q < 4; q++) c_[nt][q] = 0.f;
        #pragma unroll
        for (int ks = 0; ks < 8; ks++) {
            uint32_t a4[4];
            ldsm4(a4, aQb + ks * 32);
            #pragma unroll
            for (int nt = 0; nt < 2; nt++) {
                uint32_t b2[2];
                ldsm2(b2, bKb[nt] + ks * 32);
                mma_tf32u(c_[nt], a4, b2);
            }
        }
        const int rowA = i0 + rA, rowB = i0 + rB;
        float rmA = -1e30f, rmB = -1e30f;
        #pragma unroll
        for (int nt = 0; nt < 2; nt++) {
            int col = jt*64 + wq*16 + nt*8 + tig*2;
            c_[nt][0] = (col     <= rowA) ? c_[nt][0]*0.125f : -1e30f;
            c_[nt][1] = (col + 1 <= rowA) ? c_[nt][1]*0.125f : -1e30f;
            c_[nt][2] = (col     <= rowB) ? c_[nt][2]*0.125f : -1e30f;
            c_[nt][3] = (col + 1 <= rowB) ? c_[nt][3]*0.125f : -1e30f;
            rmA = fmaxf(rmA, fmaxf(c_[nt][0], c_[nt][1]));
            rmB = fmaxf(rmB, fmaxf(c_[nt][2], c_[nt][3]));
        }
        rmA = fmaxf(rmA, __shfl_xor_sync(0xffffffffu, rmA, 1));
        rmA = fmaxf(rmA, __shfl_xor_sync(0xffffffffu, rmA, 2));
        rmB = fmaxf(rmB, __shfl_xor_sync(0xffffffffu, rmB, 1));
        rmB = fmaxf(rmB, __shfl_xor_sync(0xffffffffu, rmB, 2));
        if (tig == 0) { sMaxP[wq*64 + rA] = rmA; sMaxP[wq*64 + rB] = rmB; }
        __syncthreads();

        float newmA = sM[rA], newmB = sM[rB];
        #pragma unroll
        for (int q2 = 0; q2 < 4; q2++) {
            newmA = fmaxf(newmA, sMaxP[q2*64 + rA]);
            newmB = fmaxf(newmB, sMaxP[q2*64 + rB]);
        }
        float corrA = __expf(sM[rA] - newmA);
        float corrB = __expf(sM[rB] - newmB);
        float sAcc = 0.f, sBcc = 0.f;
        #pragma unroll
        for (int nt = 0; nt < 2; nt++) {
            float p0 = __expf(c_[nt][0] - newmA);
            float p1 = __expf(c_[nt][1] - newmA);
            float p2 = __expf(c_[nt][2] - newmB);
            float p3 = __expf(c_[nt][3] - newmB);
            sAcc += p0 + p1; sBcc += p2 + p3;
            *(float2*)&sP[rA*68 + wq*16 + nt*8 + tig*2] = make_float2(to_tf32(p0), to_tf32(p1));
            *(float2*)&sP[rB*68 + wq*16 + nt*8 + tig*2] = make_float2(to_tf32(p2), to_tf32(p3));
        }
        sAcc += __shfl_xor_sync(0xffffffffu, sAcc, 1);
        sAcc += __shfl_xor_sync(0xffffffffu, sAcc, 2);
        sBcc += __shfl_xor_sync(0xffffffffu, sBcc, 1);
        sBcc += __shfl_xor_sync(0xffffffffu, sBcc, 2);
        if (tig == 0) { sSumP[wq*64 + rA] = sAcc; sSumP[wq*64 + rB] = sBcc; }
        if (wq == 0 && tig == 0) { sCorr[rA] = corrA; sCorr[rB] = corrB; }
        __syncthreads();

        if (wq == 0 && tig == 0) {
            float la = sL[rA]*corrA, lb = sL[rB]*corrB;
            #pragma unroll
            for (int q2 = 0; q2 < 4; q2++) {
                la += sSumP[q2*64 + rA];
                lb += sSumP[q2*64 + rB];
            }
            sM[rA] = newmA; sL[rA] = la;
            sM[rB] = newmB; sL[rB] = lb;
        }

        {
            float cA = sCorr[rA], cB = sCorr[rB];
            #pragma unroll
            for (int nt = 0; nt < 18; nt++) {
                o[nt][0] *= cA; o[nt][1] *= cA;
                o[nt][2] *= cB; o[nt][3] *= cB;
            }
        }
        #pragma unroll
        for (int ks = 0; ks < 8; ks++) {
            uint32_t a4[4];
            ldsm4(a4, aPb + ks * 32);
            const int kc = ks*8 + tig;
            #pragma unroll
            for (int nt = 0; nt < 18; nt++) {
                const int n_ = wq*144 + nt*8 + g;
                uint32_t b2[2];
                b2[0] = __float_as_uint(sV[kc*584 + n_]);
                b2[1] = __float_as_uint(sV[(kc+4)*584 + n_]);
                mma_tf32u(o[nt], a4, b2);
            }
        }
    }

    __syncthreads();
    {
        const float invA = 1.f / sL[rA];
        const float invB = 1.f / sL[rB];
        const size_t akBase = ((size_t)blockIdx.y * SEQ + i0);
        #pragma unroll
        for (int nt = 0; nt < 18; nt++) {
            int col = wq*144 + nt*8 + tig*2;
            float2 vA = make_float2(o[nt][0]*invA, o[nt][1]*invA);
            float2 vB = make_float2(o[nt][2]*invB, o[nt][3]*invB);
            if (col < 64) {
                *(float2*)&g_ra[(size_t)(tbase+rA)*512 + h*64 + col] = vA;
                *(float2*)&g_ra[(size_t)(tbase+rB)*512 + h*64 + col] = vB;
            } else {
                *(float2*)&g_attkr[(akBase + rA)*512 + col - 64] = vA;
                *(float2*)&g_attkr[(akBase + rB)*512 + col - 64] = vB;
            }
        }
    }
}

// ---------------------------------------------------------------------------
// ra_post (unchanged): rel epilogue via wr into g_ra.
// ---------------------------------------------------------------------------
__global__ void __launch_bounds__(256) ra_post(const float* __restrict__ wr)
{
    const int lane = threadIdx.x & 31;
    const int wid  = threadIdx.x >> 5;
    const int job  = blockIdx.x * 8 + wid;
    const int h     = job & 7;
    const int token = job >> 3;
    const int bb    = token >> 11;
    const int ii    = token & (SEQ - 1);

    const int r = lane >> 2, q = lane & 3;
    const float* qr = g_proj + (size_t)token * NC + COL_QR;
    const float* ak = g_attkr + (((size_t)(bb*8 + h)) * SEQ + ii) * 512;

    float part = 0.f;
    #pragma unroll
    for (int u = 0; u < 4; u++) {
        float4 qv = *(const float4*)(qr + r*64 + q*16 + u*4);
        float4 av = *(const float4*)(ak + r*64 + q*16 + u*4);
        part += qv.x*av.x + qv.y*av.y + qv.z*av.z + qv.w*av.w;
    }
    part += __shfl_xor_sync(0xffffffffu, part, 1);
    part += __shfl_xor_sync(0xffffffffu, part, 2);
    part *= 0.125f;

    float pr[8];
    #pragma unroll
    for (int r2 = 0; r2 < 8; r2++)
        pr[r2] = __shfl_sync(0xffffffffu, part, r2 << 2);

    const float* wrh = wr + h * 512;
    float* dst = g_ra + (size_t)token * 512 + h * 64;
    #pragma unroll
    for (int dd = 0; dd < 2; dd++) {
        int d = lane * 2 + dd;
        float ro = 0.f;
        #pragma unroll
        for (int r2 = 0; r2 < 8; r2++)
            ro += pr[r2] * wrh[d*8 + r2];
        dst[d] += ro;
    }
}

// ---------------------------------------------------------------------------
extern "C" void kernel_launch(void* const* d_in, const int* in_sizes, int n_in,
                              void* d_out, int out_size)
{
    (void)in_sizes; (void)n_in; (void)out_size;
    const float* x      = (const float*)d_in[0];
    const float* symb   = (const float*)d_in[1];
    const float* fc     = (const float*)d_in[2];
    const float* fs     = (const float*)d_in[3];
    const float* wq_sa  = (const float*)d_in[4];
    const float* wk_sa  = (const float*)d_in[5];
    const float* wv_sa  = (const float*)d_in[6];
    const float* wo_sa  = (const float*)d_in[7];
    const float* wq_at  = (const float*)d_in[8];
    const float* wk_at  = (const float*)d_in[9];
    const float* wq_rel = (const float*)d_in[10];
    const float* wk_rel = (const float*)d_in[11];
    const float* wr     = (const float*)d_in[12];
    const float* wv_ra  = (const float*)d_in[13];
    const float* wo_ra  = (const float*)d_in[14];
    float* out = (float*)d_out;

    float *proj, *svb, *sab, *rab;
    cudaGetSymbolAddress((void**)&proj, g_proj);
    cudaGetSymbolAddress((void**)&svb,  g_sv);
    cudaGetSymbolAddress((void**)&sab,  g_sa);
    cudaGetSymbolAddress((void**)&rab,  g_ra);

    cudaFuncSetAttribute(sa_flash4, cudaFuncAttributeMaxDynamicSharedMemorySize, SA4_SMEM);
    cudaFuncSetAttribute(ra_flash4, cudaFuncAttributeMaxDynamicSharedMemorySize, RA4_SMEM);

    // 1) fused projections of x (blocks 0..6, RoPE fused) + sv (block 7)
    W8 w8;
    w8.p[0] = wq_sa; w8.p[1] = wk_sa; w8.p[2] = wv_sa;
    w8.p[3] = wq_at; w8.p[4] = wk_at; w8.p[5] = wq_rel; w8.p[6] = wk_rel;
    w8.p[7] = wv_ra;
    gemm_tf32<<<dim3(32, NTOK / 128), 256>>>(x, symb, w8, proj, svb, DM, NC, fc, fs);

    // 2) SA flash
    sa_flash4<<<dim3(SEQ / 64, BATCH * 8), 256, SA4_SMEM>>>();

    // 3) RA flash + rel post pass
    ra_flash4<<<dim3(SEQ / 64, BATCH * 8), 512, RA4_SMEM>>>();
    ra_post<<<NTOK, 256>>>(wr);

    // 4) both output projections in ONE launch
    W8 wo;
    wo.p[0] = wo_sa; wo.p[1] = wo_ra;
    for (int i = 2; i < 8; i++) wo.p[i] = wo_sa;
    gemm_tf32<<<dim3(8, NTOK / 128), 256>>>(sab, rab, wo, out, nullptr,
                                            512, 1024, nullptr, nullptr);
}

// round 11
// speedup vs baseline: 1.6412x; 1.5450x over previous
#include <cuda_runtime.h>
#include <cuda_fp16.h>
#include <cstdint>

#define BATCH 2
#define SEQ   2048
#define NTOK  (BATCH * SEQ)
#define DM    1024
#define NC    3584

#define COL_QSA 0
#define COL_KSA 512
#define COL_VSA 1024
#define COL_QA  1536
#define COL_KA  2048
#define COL_QR  2560
#define COL_KR  3072

// Scratch (allocation-free rule: __device__ globals)
__device__ __half g_projh [NTOK * NC];        // 7 fused projections of x (fp16)
__device__ __half g_svh   [NTOK * 512];       // symbols @ wv_ra^T (fp16)
__device__ float  g_sa    [NTOK * 512];       // SA context (fp32)
__device__ float  g_ra    [NTOK * 512];       // RA context (fp32)
__device__ __half g_attkrh[16 * SEQ * 512];   // normalized alpha @ kr (fp16)

struct W8 { const float* p[8]; };

// ---------------------------------------------------------------------------
// fp16 / mma / ldmatrix helpers
// ---------------------------------------------------------------------------
__device__ __forceinline__ uint32_t pk2h(float a, float b) {
    __half2 h = __floats2half2_rn(a, b);
    return *reinterpret_cast<uint32_t*>(&h);
}
__device__ __forceinline__ void mma_f16(float* d, const uint32_t* a, const uint32_t* b) {
    asm volatile(
        "mma.sync.aligned.m16n8k16.row.col.f32.f16.f16.f32 "
        "{%0,%1,%2,%3}, {%4,%5,%6,%7}, {%8,%9}, {%0,%1,%2,%3};"
        : "+f"(d[0]), "+f"(d[1]), "+f"(d[2]), "+f"(d[3])
        : "r"(a[0]), "r"(a[1]), "r"(a[2]), "r"(a[3]), "r"(b[0]), "r"(b[1]));
}
__device__ __forceinline__ uint32_t sm_addr(const void* p) {
    return (uint32_t)__cvta_generic_to_shared(p);
}
__device__ __forceinline__ void ldsm4(uint32_t* r, uint32_t a) {
    asm volatile("ldmatrix.sync.aligned.m8n8.x4.shared.b16 {%0,%1,%2,%3}, [%4];"
        : "=r"(r[0]), "=r"(r[1]), "=r"(r[2]), "=r"(r[3]) : "r"(a));
}
__device__ __forceinline__ void ldsm2(uint32_t* r, uint32_t a) {
    asm volatile("ldmatrix.sync.aligned.m8n8.x2.shared.b16 {%0,%1}, [%2];"
        : "=r"(r[0]), "=r"(r[1]) : "r"(a));
}
__device__ __forceinline__ void ldsm2t(uint32_t* r, uint32_t a) {
    asm volatile("ldmatrix.sync.aligned.m8n8.x2.trans.shared.b16 {%0,%1}, [%2];"
        : "=r"(r[0]), "=r"(r[1]) : "r"(a));
}

// ---------------------------------------------------------------------------
// fp16 tensor-core GEMM:  C = A[M,K] @ W^T.  Inputs fp32 (converted in the
// load path), smem fp16, mma m16n8k16, fp32 accum.
// Proj mode (Ch != null): blocks 0..6 use A (x) -> Ch (g_projh, RoPE fused),
//   block 7 uses A2 (symbols) -> Ch2 (g_svh).
// Out mode (Ch == null): block 0 -> A, block 1 -> A2, fp32 C output.
// ---------------------------------------------------------------------------
__global__ void __launch_bounds__(256) gemm_h(
    const float* __restrict__ A, const float* __restrict__ A2,
    W8 w, float* __restrict__ C, __half* __restrict__ Ch,
    __half* __restrict__ Ch2, int K, int ldC,
    const float* __restrict__ fc, const float* __restrict__ fs)
{
    __shared__ __half As[128][40];
    __shared__ __half Bs[128][40];

    const int tid   = threadIdx.x;
    const int lane  = tid & 31;
    const int wid   = tid >> 5;
    const int warpM = wid >> 2;
    const int warpN = wid & 3;
    const int g     = lane >> 2;
    const int tig   = lane & 3;

    const int mBase = blockIdx.y * 128;
    const int nBase = blockIdx.x * 128;
    const int blk   = nBase >> 9;
    const float* Wm = w.p[blk];
    const bool projMode = (Ch != nullptr);
    const bool svBlk = projMode && (blk == 7);
    const float* Ab = projMode ? (svBlk ? A2 : A) : (blk ? A2 : A);
    const int wrow  = nBase & 511;

    const float* Aptr = Ab + (size_t)mBase * K;
    const float* Bptr = Wm + (size_t)wrow  * K;

    float acc[4][4][4];
    #pragma unroll
    for (int mi = 0; mi < 4; mi++)
        #pragma unroll
        for (int ni = 0; ni < 4; ni++)
            #pragma unroll
            for (int c = 0; c < 4; c++) acc[mi][ni][c] = 0.f;

    const int lrow  = (lane & 7) + ((lane >> 3) & 1) * 8;
    uint32_t aB[4], bB[4];
    #pragma unroll
    for (int mi = 0; mi < 4; mi++)
        aB[mi] = sm_addr(&As[warpM*64 + mi*16 + lrow][(lane >> 4) * 8]);
    #pragma unroll
    for (int ni = 0; ni < 4; ni++)
        bB[ni] = sm_addr(&Bs[warpN*32 + ni*8 + (lane & 7)][((lane >> 3) & 1) * 8]);

    const int nT = K >> 5;
    float4 pa[4], pb[4];
    #pragma unroll
    for (int u = 0; u < 4; u++) {
        int s_ = tid + (u << 8);
        int r = s_ >> 3, q = s_ & 7;
        pa[u] = *(const float4*)(Aptr + (size_t)r * K + q * 4);
        pb[u] = *(const float4*)(Bptr + (size_t)r * K + q * 4);
    }

    for (int t = 0; t < nT; t++) {
        #pragma unroll
        for (int u = 0; u < 4; u++) {
            int s_ = tid + (u << 8);
            int r = s_ >> 3, q = s_ & 7;
            *(uint2*)&As[r][q * 4] = make_uint2(pk2h(pa[u].x, pa[u].y), pk2h(pa[u].z, pa[u].w));
            *(uint2*)&Bs[r][q * 4] = make_uint2(pk2h(pb[u].x, pb[u].y), pk2h(pb[u].z, pb[u].w));
        }
        __syncthreads();

        if (t + 1 < nT) {
            int k0 = (t + 1) << 5;
            #pragma unroll
            for (int u = 0; u < 4; u++) {
                int s_ = tid + (u << 8);
                int r = s_ >> 3, q = s_ & 7;
                pa[u] = *(const float4*)(Aptr + (size_t)r * K + k0 + q * 4);
                pb[u] = *(const float4*)(Bptr + (size_t)r * K + k0 + q * 4);
            }
        }

        #pragma unroll
        for (int ks = 0; ks < 2; ks++) {
            uint32_t a4[4][4], b2[4][2];
            #pragma unroll
            for (int mi = 0; mi < 4; mi++) ldsm4(a4[mi], aB[mi] + ks * 32);
            #pragma unroll
            for (int ni = 0; ni < 4; ni++) ldsm2(b2[ni], bB[ni] + ks * 32);
            #pragma unroll
            for (int mi = 0; mi < 4; mi++)
                #pragma unroll
                for (int ni = 0; ni < 4; ni++)
                    mma_f16(acc[mi][ni], a4[mi], b2[ni]);
        }
        __syncthreads();
    }

    // ------------------- epilogue (fused RoPE / half or float out) ----------
    #pragma unroll
    for (int mi = 0; mi < 4; mi++) {
        int row = mBase + warpM * 64 + mi * 16 + g;
        int s0 = row & (SEQ - 1);
        int s1 = (row + 8) & (SEQ - 1);
        #pragma unroll
        for (int ni = 0; ni < 4; ni++) {
            int col = nBase + warpN * 32 + ni * 8 + tig * 2;
            float v0 = acc[mi][ni][0], v1 = acc[mi][ni][1];
            float v2 = acc[mi][ni][2], v3 = acc[mi][ni][3];
            if (projMode && !svBlk &&
                (col < 1024 || (col >= 1536 && col < 2560))) {
                int tt = (col & 63) >> 1;
                float c0 = fc[s0*32 + tt], sn0 = fs[s0*32 + tt];
                float c1 = fc[s1*32 + tt], sn1 = fs[s1*32 + tt];
                float n0 = v0*c0 - v1*sn0, n1 = v0*sn0 + v1*c0;
                float n2 = v2*c1 - v3*sn1, n3 = v2*sn1 + v3*c1;
                v0 = n0; v1 = n1; v2 = n2; v3 = n3;
            }
            if (projMode) {
                __half* dst = svBlk ? Ch2 : Ch;
                int ld     = svBlk ? 512 : ldC;
                int colOut = svBlk ? (col - 3584) : col;
                *(uint32_t*)&dst[(size_t)row * ld + colOut]       = pk2h(v0, v1);
                *(uint32_t*)&dst[(size_t)(row + 8) * ld + colOut] = pk2h(v2, v3);
            } else {
                *(float2*)&C[(size_t)row * ldC + col]       = make_float2(v0, v1);
                *(float2*)&C[(size_t)(row + 8) * ldC + col] = make_float2(v2, v3);
            }
        }
    }
}

// ---------------------------------------------------------------------------
// SA flash v6 (fp16): Br=Bc=64, 256 thr / 8 warps, m16n8k16, ldmatrix.trans
// for the PV V-operand.
// ---------------------------------------------------------------------------
#define SA6_SMEM (4*64*72*2 + 448*4)

__global__ void __launch_bounds__(256) sa_flash6()
{
    extern __shared__ char smraw[];
    __half* sQ = (__half*)smraw;           // [64][72]
    __half* sK = sQ + 64*72;               // [64][72]
    __half* sP = sK + 64*72;               // [64][72]
    __half* sV = sP + 64*72;               // [64][72]  (j rows, d cols)
    float* sM    = (float*)(smraw + 4*64*72*2);   // [64]
    float* sL    = sM + 64;
    float* sCorr = sL + 64;
    float* sMaxP = sCorr + 64;             // [2][64]
    float* sSumP = sMaxP + 128;            // [2][64]

    const int tid  = threadIdx.x;
    const int lane = tid & 31, wid = tid >> 5;
    const int g    = lane >> 2, tig = lane & 3;
    const int wband = wid & 3, whalf = wid >> 2;
    const int r0   = wband * 16;
    const int b    = blockIdx.y >> 3, h = blockIdx.y & 7;
    const int bx   = gridDim.x - 1 - blockIdx.x;
    const int i0   = bx * 64;
    const int tbase = b * SEQ + i0;

    if (tid < 64) { sM[tid] = -1e30f; sL[tid] = 0.f; }

    #pragma unroll
    for (int u = 0; u < 2; u++) {
        int e = tid + (u << 8);
        int rr = e >> 3, c8 = e & 7;
        *(uint4*)&sQ[rr*72 + c8*8] =
            *(const uint4*)(g_projh + (size_t)(tbase+rr)*NC + COL_QSA + h*64 + c8*8);
    }

    const int lrow = (lane & 7) + ((lane >> 3) & 1) * 8;
    const uint32_t aQb = sm_addr(&sQ[(r0 + lrow)*72 + (lane >> 4) * 8]);
    const uint32_t aPb = sm_addr(&sP[(r0 + lrow)*72 + (lane >> 4) * 8]);
    uint32_t bKb[4];
    #pragma unroll
    for (int nt = 0; nt < 4; nt++)
        bKb[nt] = sm_addr(&sK[(whalf*32 + nt*8 + (lane & 7))*72 + ((lane >> 3) & 1) * 8]);
    const uint32_t bVb = sm_addr(&sV[(lane & 15) * 72]);

    const int rA = r0 + g, rB = rA + 8;

    float o[4][4];
    #pragma unroll
    for (int nt = 0; nt < 4; nt++)
        #pragma unroll
        for (int c = 0; c < 4; c++) o[nt][c] = 0.f;

    const int nJT = bx + 1;
    for (int jt = 0; jt < nJT; jt++) {
        __syncthreads();
        const int jb = b * SEQ + jt * 64;
        #pragma unroll
        for (int u = 0; u < 2; u++) {
            int e = tid + (u << 8);
            int rr = e >> 3, c8 = e & 7;
            const __half* base = g_projh + (size_t)(jb+rr)*NC + h*64 + c8*8;
            *(uint4*)&sK[rr*72 + c8*8] = *(const uint4*)(base + COL_KSA);
            *(uint4*)&sV[rr*72 + c8*8] = *(const uint4*)(base + COL_VSA);
        }
        __syncthreads();

        // ---- S: each warp m16 x n32 ----
        float c_[4][4];
        #pragma unroll
        for (int nt = 0; nt < 4; nt++)
            #pragma unroll
            for (int q = 0; q < 4; q++) c_[nt][q] = 0.f;
        #pragma unroll
        for (int ks = 0; ks < 4; ks++) {
            uint32_t a4[4];
            ldsm4(a4, aQb + ks * 32);
            #pragma unroll
            for (int nt = 0; nt < 4; nt++) {
                uint32_t b2[2];
                ldsm2(b2, bKb[nt] + ks * 32);
                mma_f16(c_[nt], a4, b2);
            }
        }
        const int rowA = i0 + rA, rowB = i0 + rB;
        float rmA = -1e30f, rmB = -1e30f;
        #pragma unroll
        for (int nt = 0; nt < 4; nt++) {
            int col = jt*64 + whalf*32 + nt*8 + tig*2;
            c_[nt][0] = (col     <= rowA) ? c_[nt][0]*0.125f : -1e30f;
            c_[nt][1] = (col + 1 <= rowA) ? c_[nt][1]*0.125f : -1e30f;
            c_[nt][2] = (col     <= rowB) ? c_[nt][2]*0.125f : -1e30f;
            c_[nt][3] = (col + 1 <= rowB) ? c_[nt][3]*0.125f : -1e30f;
            rmA = fmaxf(rmA, fmaxf(c_[nt][0], c_[nt][1]));
            rmB = fmaxf(rmB, fmaxf(c_[nt][2], c_[nt][3]));
        }
        rmA = fmaxf(rmA, __shfl_xor_sync(0xffffffffu, rmA, 1));
        rmA = fmaxf(rmA, __shfl_xor_sync(0xffffffffu, rmA, 2));
        rmB = fmaxf(rmB, __shfl_xor_sync(0xffffffffu, rmB, 1));
        rmB = fmaxf(rmB, __shfl_xor_sync(0xffffffffu, rmB, 2));
        if (tig == 0) { sMaxP[whalf*64 + rA] = rmA; sMaxP[whalf*64 + rB] = rmB; }
        __syncthreads();

        float newmA = fmaxf(sM[rA], fmaxf(sMaxP[rA], sMaxP[64 + rA]));
        float newmB = fmaxf(sM[rB], fmaxf(sMaxP[rB], sMaxP[64 + rB]));
        float corrA = __expf(sM[rA] - newmA);
        float corrB = __expf(sM[rB] - newmB);
        float sAcc = 0.f, sBcc = 0.f;
        #pragma unroll
        for (int nt = 0; nt < 4; nt++) {
            float p0 = __expf(c_[nt][0] - newmA);
            float p1 = __expf(c_[nt][1] - newmA);
            float p2 = __expf(c_[nt][2] - newmB);
            float p3 = __expf(c_[nt][3] - newmB);
            sAcc += p0 + p1; sBcc += p2 + p3;
            *(uint32_t*)&sP[rA*72 + whalf*32 + nt*8 + tig*2] = pk2h(p0, p1);
            *(uint32_t*)&sP[rB*72 + whalf*32 + nt*8 + tig*2] = pk2h(p2, p3);
        }
        sAcc += __shfl_xor_sync(0xffffffffu, sAcc, 1);
        sAcc += __shfl_xor_sync(0xffffffffu, sAcc, 2);
        sBcc += __shfl_xor_sync(0xffffffffu, sBcc, 1);
        sBcc += __shfl_xor_sync(0xffffffffu, sBcc, 2);
        if (tig == 0) { sSumP[whalf*64 + rA] = sAcc; sSumP[whalf*64 + rB] = sBcc; }
        if (whalf == 0 && tig == 0) { sCorr[rA] = corrA; sCorr[rB] = corrB; }
        __syncthreads();

        if (whalf == 0 && tig == 0) {
            sM[rA] = newmA; sL[rA] = sL[rA]*corrA + sSumP[rA] + sSumP[64 + rA];
            sM[rB] = newmB; sL[rB] = sL[rB]*corrB + sSumP[rB] + sSumP[64 + rB];
        }

        // ---- PV: each warp m16 x n32 (V via ldmatrix.trans) ----
        {
            float cA = sCorr[rA], cB = sCorr[rB];
            #pragma unroll
            for (int nt = 0; nt < 4; nt++) {
                o[nt][0] *= cA; o[nt][1] *= cA;
                o[nt][2] *= cB; o[nt][3] *= cB;
            }
        }
        #pragma unroll
        for (int ks = 0; ks < 4; ks++) {
            uint32_t a4[4];
            ldsm4(a4, aPb + ks * 32);
            #pragma unroll
            for (int nt = 0; nt < 4; nt++) {
                uint32_t b2[2];
                ldsm2t(b2, bVb + ks * 2304 + (whalf*32 + nt*8) * 2);
                mma_f16(o[nt], a4, b2);
            }
        }
    }

    __syncthreads();
    {
        const float invA = 1.f / sL[rA];
        const float invB = 1.f / sL[rB];
        #pragma unroll
        for (int nt = 0; nt < 4; nt++) {
            int col = whalf*32 + nt*8 + tig*2;
            *(float2*)&g_sa[(size_t)(tbase+rA)*512 + h*64 + col] =
                make_float2(o[nt][0]*invA, o[nt][1]*invA);
            *(float2*)&g_sa[(size_t)(tbase+rB)*512 + h*64 + col] =
                make_float2(o[nt][2]*invB, o[nt][3]*invB);
        }
    }
}

// ---------------------------------------------------------------------------
// RA flash v6 (fp16): extended V = [sv(64) | kr(512)], d_v=576. Br=Bc=64,
// 512 thr / 16 warps, m16n8k16, ldmatrix.trans V-operand.
// ---------------------------------------------------------------------------
#define RA6_SMEM ((3*64*72 + 64*584)*2 + 704*4)

__global__ void __launch_bounds__(512) ra_flash6()
{
    extern __shared__ char smraw[];
    __half* sQ = (__half*)smraw;           // [64][72]
    __half* sK = sQ + 64*72;               // [64][72]
    __half* sP = sK + 64*72;               // [64][72]
    __half* sV = sP + 64*72;               // [64][584]
    float* sM    = (float*)(smraw + (3*64*72 + 64*584)*2);
    float* sL    = sM + 64;
    float* sCorr = sL + 64;
    float* sMaxP = sCorr + 64;             // [4][64]
    float* sSumP = sMaxP + 256;            // [4][64]

    const int tid  = threadIdx.x;
    const int lane = tid & 31, wid = tid >> 5;
    const int g    = lane >> 2, tig = lane & 3;
    const int wband = wid & 3, wq = wid >> 2;
    const int r0   = wband * 16;
    const int b    = blockIdx.y >> 3, h = blockIdx.y & 7;
    const int bx   = gridDim.x - 1 - blockIdx.x;
    const int i0   = bx * 64;
    const int tbase = b * SEQ + i0;

    if (tid < 64) { sM[tid] = -1e30f; sL[tid] = 0.f; }

    {
        int rr = tid >> 3, c8 = tid & 7;
        *(uint4*)&sQ[rr*72 + c8*8] =
            *(const uint4*)(g_projh + (size_t)(tbase+rr)*NC + COL_QA + h*64 + c8*8);
    }

    const int lrow = (lane & 7) + ((lane >> 3) & 1) * 8;
    const uint32_t aQb = sm_addr(&sQ[(r0 + lrow)*72 + (lane >> 4) * 8]);
    const uint32_t aPb = sm_addr(&sP[(r0 + lrow)*72 + (lane >> 4) * 8]);
    uint32_t bKb[2];
    #pragma unroll
    for (int nt = 0; nt < 2; nt++)
        bKb[nt] = sm_addr(&sK[(wq*16 + nt*8 + (lane & 7))*72 + ((lane >> 3) & 1) * 8]);
    const uint32_t bVb = sm_addr(&sV[(lane & 15) * 584]);

    const int rA = r0 + g, rB = rA + 8;

    float o[18][4];
    #pragma unroll
    for (int nt = 0; nt < 18; nt++)
        #pragma unroll
        for (int c = 0; c < 4; c++) o[nt][c] = 0.f;

    const int nJT = bx + 1;
    for (int jt = 0; jt < nJT; jt++) {
        __syncthreads();
        const int jb = b * SEQ + jt * 64;
        {
            int rr = tid >> 3, c8 = tid & 7;
            *(uint4*)&sK[rr*72 + c8*8] =
                *(const uint4*)(g_projh + (size_t)(jb+rr)*NC + COL_KA + h*64 + c8*8);
        }
        for (int e = tid; e < 64 * 72; e += 512) {
            int rr = e / 72, c8 = e - rr * 72;
            uint4 v;
            if (c8 < 8)
                v = *(const uint4*)(g_svh + (size_t)(jb+rr)*512 + h*64 + c8*8);
            else
                v = *(const uint4*)(g_projh + (size_t)(jb+rr)*NC + COL_KR + (c8-8)*8);
            *(uint4*)&sV[rr*584 + c8*8] = v;
        }
        __syncthreads();

        // ---- S: each warp m16 x n16 ----
        float c_[2][4];
        #pragma unroll
        for (int nt = 0; nt < 2; nt++)
            #pragma unroll
            for (int q = 0; q < 4; q++) c_[nt][q] = 0.f;
        #pragma unroll
        for (int ks = 0; ks < 4; ks++) {
            uint32_t a4[4];
            ldsm4(a4, aQb + ks * 32);
            #pragma unroll
            for (int nt = 0; nt < 2; nt++) {
                uint32_t b2[2];
                ldsm2(b2, bKb[nt] + ks * 32);
                mma_f16(c_[nt], a4, b2);
            }
        }
        const int rowA = i0 + rA, rowB = i0 + rB;
        float rmA = -1e30f, rmB = -1e30f;
        #pragma unroll
        for (int nt = 0; nt < 2; nt++) {
            int col = jt*64 + wq*16 + nt*8 + tig*2;
            c_[nt][0] = (col     <= rowA) ? c_[nt][0]*0.125f : -1e30f;
            c_[nt][1] = (col + 1 <= rowA) ? c_[nt][1]*0.125f : -1e30f;
            c_[nt][2] = (col     <= rowB) ? c_[nt][2]*0.125f : -1e30f;
            c_[nt][3] = (col + 1 <= rowB) ? c_[nt][3]*0.125f : -1e30f;
            rmA = fmaxf(rmA, fmaxf(c_[nt][0], c_[nt][1]));
            rmB = fmaxf(rmB, fmaxf(c_[nt][2], c_[nt][3]));
        }
        rmA = fmaxf(rmA, __shfl_xor_sync(0xffffffffu, rmA, 1));
        rmA = fmaxf(rmA, __shfl_xor_sync(0xffffffffu, rmA, 2));
        rmB = fmaxf(rmB, __shfl_xor_sync(0xffffffffu, rmB, 1));
        rmB = fmaxf(rmB, __shfl_xor_sync(0xffffffffu, rmB, 2));
        if (tig == 0) { sMaxP[wq*64 + rA] = rmA; sMaxP[wq*64 + rB] = rmB; }
        __syncthreads();

        float newmA = sM[rA], newmB = sM[rB];
        #pragma unroll
        for (int q2 = 0; q2 < 4; q2++) {
            newmA = fmaxf(newmA, sMaxP[q2*64 + rA]);
            newmB = fmaxf(newmB, sMaxP[q2*64 + rB]);
        }
        float corrA = __expf(sM[rA] - newmA);
        float corrB = __expf(sM[rB] - newmB);
        float sAcc = 0.f, sBcc = 0.f;
        #pragma unroll
        for (int nt = 0; nt < 2; nt++) {
            float p0 = __expf(c_[nt][0] - newmA);
            float p1 = __expf(c_[nt][1] - newmA);
            float p2 = __expf(c_[nt][2] - newmB);
            float p3 = __expf(c_[nt][3] - newmB);
            sAcc += p0 + p1; sBcc += p2 + p3;
            *(uint32_t*)&sP[rA*72 + wq*16 + nt*8 + tig*2] = pk2h(p0, p1);
            *(uint32_t*)&sP[rB*72 + wq*16 + nt*8 + tig*2] = pk2h(p2, p3);
        }
        sAcc += __shfl_xor_sync(0xffffffffu, sAcc, 1);
        sAcc += __shfl_xor_sync(0xffffffffu, sAcc, 2);
        sBcc += __shfl_xor_sync(0xffffffffu, sBcc, 1);
        sBcc += __shfl_xor_sync(0xffffffffu, sBcc, 2);
        if (tig == 0) { sSumP[wq*64 + rA] = sAcc; sSumP[wq*64 + rB] = sBcc; }
        if (wq == 0 && tig == 0) { sCorr[rA] = corrA; sCorr[rB] = corrB; }
        __syncthreads();

        if (wq == 0 && tig == 0) {
            float la = sL[rA]*corrA, lb = sL[rB]*corrB;
            #pragma unroll
            for (int q2 = 0; q2 < 4; q2++) {
                la += sSumP[q2*64 + rA];
                lb += sSumP[q2*64 + rB];
            }
            sM[rA] = newmA; sL[rA] = la;
            sM[rB] = newmB; sL[rB] = lb;
        }

        // ---- PV: warp (wband rows, wq 144-col d-quarter) ----
        {
            float cA = sCorr[rA], cB = sCorr[rB];
            #pragma unroll
            for (int nt = 0; nt < 18; nt++) {
                o[nt][0] *= cA; o[nt][1] *= cA;
                o[nt][2] *= cB; o[nt][3] *= cB;
            }
        }
        #pragma unroll
        for (int ks = 0; ks < 4; ks++) {
            uint32_t a4[4];
            ldsm4(a4, aPb + ks * 32);
            #pragma unroll
            for (int nt = 0; nt < 18; nt++) {
                uint32_t b2[2];
                ldsm2t(b2, bVb + ks * 18688 + (wq*144 + nt*8) * 2);
                mma_f16(o[nt], a4, b2);
            }
        }
    }

    __syncthreads();
    {
        const float invA = 1.f / sL[rA];
        const float invB = 1.f / sL[rB];
        const size_t akBase = ((size_t)blockIdx.y * SEQ + i0);
        #pragma unroll
        for (int nt = 0; nt < 18; nt++) {
            int col = wq*144 + nt*8 + tig*2;
            if (col < 64) {
                *(float2*)&g_ra[(size_t)(tbase+rA)*512 + h*64 + col] =
                    make_float2(o[nt][0]*invA, o[nt][1]*invA);
                *(float2*)&g_ra[(size_t)(tbase+rB)*512 + h*64 + col] =
                    make_float2(o[nt][2]*invB, o[nt][3]*invB);
            } else {
                *(uint32_t*)&g_attkrh[(akBase + rA)*512 + col - 64] =
                    pk2h(o[nt][0]*invA, o[nt][1]*invA);
                *(uint32_t*)&g_attkrh[(akBase + rB)*512 + col - 64] =
                    pk2h(o[nt][2]*invB, o[nt][3]*invB);
            }
        }
    }
}

// ---------------------------------------------------------------------------
// ra_post: rel epilogue via wr into g_ra (fp16 inputs).
// ---------------------------------------------------------------------------
__global__ void __launch_bounds__(256) ra_post(const float* __restrict__ wr)
{
    const int lane = threadIdx.x & 31;
    const int wid  = threadIdx.x >> 5;
    const int job  = blockIdx.x * 8 + wid;
    const int h     = job & 7;
    const int token = job >> 3;
    const int bb    = token >> 11;
    const int ii    = token & (SEQ - 1);

    const int r = lane >> 2, q = lane & 3;
    const __half2* q2 = (const __half2*)(g_projh + (size_t)token * NC + COL_QR + r*64 + q*16);
    const __half2* a2 = (const __half2*)(g_attkrh + (((size_t)(bb*8 + h)) * SEQ + ii) * 512 + r*64 + q*16);

    float part = 0.f;
    #pragma unroll
    for (int u = 0; u < 8; u++) {
        float2 qv = __half22float2(q2[u]);
        float2 av = __half22float2(a2[u]);
        part += qv.x*av.x + qv.y*av.y;
    }
    part += __shfl_xor_sync(0xffffffffu, part, 1);
    part += __shfl_xor_sync(0xffffffffu, part, 2);
    part *= 0.125f;

    float pr[8];
    #pragma unroll
    for (int r2 = 0; r2 < 8; r2++)
        pr[r2] = __shfl_sync(0xffffffffu, part, r2 << 2);

    const float* wrh = wr + h * 512;
    float* dst = g_ra + (size_t)token * 512 + h * 64;
    #pragma unroll
    for (int dd = 0; dd < 2; dd++) {
        int d = lane * 2 + dd;
        float ro = 0.f;
        #pragma unroll
        for (int r2 = 0; r2 < 8; r2++)
            ro += pr[r2] * wrh[d*8 + r2];
        dst[d] += ro;
    }
}

// ---------------------------------------------------------------------------
extern "C" void kernel_launch(void* const* d_in, const int* in_sizes, int n_in,
                              void* d_out, int out_size)
{
    (void)in_sizes; (void)n_in; (void)out_size;
    const float* x      = (const float*)d_in[0];
    const float* symb   = (const float*)d_in[1];
    const float* fc     = (const float*)d_in[2];
    const float* fs     = (const float*)d_in[3];
    const float* wq_sa  = (const float*)d_in[4];
    const float* wk_sa  = (const float*)d_in[5];
    const float* wv_sa  = (const float*)d_in[6];
    const float* wo_sa  = (const float*)d_in[7];
    const float* wq_at  = (const float*)d_in[8];
    const float* wk_at  = (const float*)d_in[9];
    const float* wq_rel = (const float*)d_in[10];
    const float* wk_rel = (const float*)d_in[11];
    const float* wr     = (const float*)d_in[12];
    const float* wv_ra  = (const float*)d_in[13];
    const float* wo_ra  = (const float*)d_in[14];
    float* out = (float*)d_out;

    __half *projh, *svh;
    float *sab, *rab;
    cudaGetSymbolAddress((void**)&projh, g_projh);
    cudaGetSymbolAddress((void**)&svh,   g_svh);
    cudaGetSymbolAddress((void**)&sab,   g_sa);
    cudaGetSymbolAddress((void**)&rab,   g_ra);

    cudaFuncSetAttribute(sa_flash6, cudaFuncAttributeMaxDynamicSharedMemorySize, SA6_SMEM);
    cudaFuncSetAttribute(ra_flash6, cudaFuncAttributeMaxDynamicSharedMemorySize, RA6_SMEM);

    // 1) fused projections of x (blocks 0..6, RoPE fused) + sv (block 7)
    W8 w8;
    w8.p[0] = wq_sa; w8.p[1] = wk_sa; w8.p[2] = wv_sa;
    w8.p[3] = wq_at; w8.p[4] = wk_at; w8.p[5] = wq_rel; w8.p[6] = wk_rel;
    w8.p[7] = wv_ra;
    gemm_h<<<dim3(32, NTOK / 128), 256>>>(x, symb, w8, nullptr, projh, svh,
                                          DM, NC, fc, fs);

    // 2) SA flash (fp16)
    sa_flash6<<<dim3(SEQ / 64, BATCH * 8), 256, SA6_SMEM>>>();

    // 3) RA flash (fp16) + rel post pass
    ra_flash6<<<dim3(SEQ / 64, BATCH * 8), 512, RA6_SMEM>>>();
    ra_post<<<NTOK, 256>>>(wr);

    // 4) both output projections in ONE launch (fp32 out)
    W8 wo;
    wo.p[0] = wo_sa; wo.p[1] = wo_ra;
    for (int i = 2; i < 8; i++) wo.p[i] = wo_sa;
    gemm_h<<<dim3(8, NTOK / 128), 256>>>(sab, rab, wo, out, nullptr, nullptr,
                                         512, 1024, nullptr, nullptr);
}

// round 12
// speedup vs baseline: 1.8366x; 1.1190x over previous
#include <cuda_runtime.h>
#include <cuda_fp16.h>
#include <cstdint>

#define BATCH 2
#define SEQ   2048
#define NTOK  (BATCH * SEQ)
#define DM    1024
#define NC    3584

#define COL_QSA 0
#define COL_KSA 512
#define COL_VSA 1024
#define COL_QA  1536
#define COL_KA  2048
#define COL_QR  2560
#define COL_KR  3072

// fp16 operand pool layout (halves)
#define OFF_X    0                         // x:        4096x1024
#define OFF_SY   (NTOK*DM)                 // symbols:  4096x1024
#define OFF_W    (2*NTOK*DM)               // 8 x (512x1024): qsa,ksa,vsa,qat,kat,qrel,krel,wv_ra
#define W_SZ     (512*DM)
#define OFF_WOSA (OFF_W + 8*W_SZ)          // 512x512
#define OFF_WORA (OFF_WOSA + 512*512)
#define H16_TOTAL (OFF_WORA + 512*512)     // 13,107,200 halves

// Scratch (allocation-free rule: __device__ globals)
__device__ __half g_h16   [H16_TOTAL];        // fp16 inputs + weights
__device__ __half g_projh [NTOK * NC];        // 7 fused projections of x (fp16)
__device__ __half g_svh   [NTOK * 512];       // symbols @ wv_ra^T (fp16)
__device__ __half g_sah   [NTOK * 512];       // SA context (fp16)
__device__ float  g_ra    [NTOK * 512];       // RA sym context (fp32)
__device__ __half g_rah   [NTOK * 512];       // final RA context (fp16)
__device__ __half g_attkrh[16 * SEQ * 512];   // normalized alpha @ kr (fp16)

struct W8h { const __half* p[8]; };
struct CvtArgs { const float* src[12]; int off[13]; };

// ---------------------------------------------------------------------------
// fp16 / mma / ldmatrix helpers
// ---------------------------------------------------------------------------
__device__ __forceinline__ uint32_t pk2h(float a, float b) {
    __half2 h = __floats2half2_rn(a, b);
    return *reinterpret_cast<uint32_t*>(&h);
}
__device__ __forceinline__ void mma_f16(float* d, const uint32_t* a, const uint32_t* b) {
    asm volatile(
        "mma.sync.aligned.m16n8k16.row.col.f32.f16.f16.f32 "
        "{%0,%1,%2,%3}, {%4,%5,%6,%7}, {%8,%9}, {%0,%1,%2,%3};"
        : "+f"(d[0]), "+f"(d[1]), "+f"(d[2]), "+f"(d[3])
        : "r"(a[0]), "r"(a[1]), "r"(a[2]), "r"(a[3]), "r"(b[0]), "r"(b[1]));
}
__device__ __forceinline__ uint32_t sm_addr(const void* p) {
    return (uint32_t)__cvta_generic_to_shared(p);
}
__device__ __forceinline__ void ldsm4(uint32_t* r, uint32_t a) {
    asm volatile("ldmatrix.sync.aligned.m8n8.x4.shared.b16 {%0,%1,%2,%3}, [%4];"
        : "=r"(r[0]), "=r"(r[1]), "=r"(r[2]), "=r"(r[3]) : "r"(a));
}
__device__ __forceinline__ void ldsm2(uint32_t* r, uint32_t a) {
    asm volatile("ldmatrix.sync.aligned.m8n8.x2.shared.b16 {%0,%1}, [%2];"
        : "=r"(r[0]), "=r"(r[1]) : "r"(a));
}
__device__ __forceinline__ void ldsm2t(uint32_t* r, uint32_t a) {
    asm volatile("ldmatrix.sync.aligned.m8n8.x2.trans.shared.b16 {%0,%1}, [%2];"
        : "=r"(r[0]), "=r"(r[1]) : "r"(a));
}

// ---------------------------------------------------------------------------
// cvt: fp32 -> fp16 pool. 12 segments, float4-granular.
// ---------------------------------------------------------------------------
__global__ void __launch_bounds__(256) cvt_kernel(CvtArgs a)
{
    int e4 = (blockIdx.x * 256 + threadIdx.x) * 4;
    if (e4 >= a.off[12]) return;
    int seg = 0;
    #pragma unroll
    for (int s = 1; s < 12; s++) seg += (e4 >= a.off[s]);
    float4 v = *(const float4*)(a.src[seg] + (e4 - a.off[seg]));
    *(uint2*)&g_h16[e4] = make_uint2(pk2h(v.x, v.y), pk2h(v.z, v.w));
}

// ---------------------------------------------------------------------------
// fp16 tensor-core GEMM: C = A[M,K] @ W^T, all operands fp16, fp32 accum.
// Proj mode (Ch != null): blocks 0..6 use A -> Ch (g_projh, RoPE fused),
//   block 7 uses A2 -> Ch2 (g_svh). Out mode: blk0->A, blk1->A2, fp32 C.
// ---------------------------------------------------------------------------
__global__ void __launch_bounds__(256) gemm_h(
    const __half* __restrict__ A, const __half* __restrict__ A2,
    W8h w, float* __restrict__ C, __half* __restrict__ Ch,
    __half* __restrict__ Ch2, int K, int ldC,
    const float* __restrict__ fc, const float* __restrict__ fs)
{
    __shared__ __half As[128][40];
    __shared__ __half Bs[128][40];

    const int tid   = threadIdx.x;
    const int lane  = tid & 31;
    const int wid   = tid >> 5;
    const int warpM = wid >> 2;
    const int warpN = wid & 3;
    const int g     = lane >> 2;
    const int tig   = lane & 3;

    const int mBase = blockIdx.y * 128;
    const int nBase = blockIdx.x * 128;
    const int blk   = nBase >> 9;
    const __half* Wm = w.p[blk];
    const bool projMode = (Ch != nullptr);
    const bool svBlk = projMode && (blk == 7);
    const __half* Ab = projMode ? (svBlk ? A2 : A) : (blk ? A2 : A);
    const int wrow  = nBase & 511;

    const __half* Aptr = Ab + (size_t)mBase * K;
    const __half* Bptr = Wm + (size_t)wrow  * K;

    float acc[4][4][4];
    #pragma unroll
    for (int mi = 0; mi < 4; mi++)
        #pragma unroll
        for (int ni = 0; ni < 4; ni++)
            #pragma unroll
            for (int c = 0; c < 4; c++) acc[mi][ni][c] = 0.f;

    const int lrow  = (lane & 7) + ((lane >> 3) & 1) * 8;
    uint32_t aB[4], bB[4];
    #pragma unroll
    for (int mi = 0; mi < 4; mi++)
        aB[mi] = sm_addr(&As[warpM*64 + mi*16 + lrow][(lane >> 4) * 8]);
    #pragma unroll
    for (int ni = 0; ni < 4; ni++)
        bB[ni] = sm_addr(&Bs[warpN*32 + ni*8 + (lane & 7)][((lane >> 3) & 1) * 8]);

    const int nT = K >> 5;
    uint4 pa[2], pb[2];
    #pragma unroll
    for (int u = 0; u < 2; u++) {
        int s_ = tid + (u << 8);
        int r = s_ >> 2, q = s_ & 3;
        pa[u] = *(const uint4*)(Aptr + (size_t)r * K + q * 8);
        pb[u] = *(const uint4*)(Bptr + (size_t)r * K + q * 8);
    }

    for (int t = 0; t < nT; t++) {
        #pragma unroll
        for (int u = 0; u < 2; u++) {
            int s_ = tid + (u << 8);
            int r = s_ >> 2, q = s_ & 3;
            *(uint4*)&As[r][q * 8] = pa[u];
            *(uint4*)&Bs[r][q * 8] = pb[u];
        }
        __syncthreads();

        if (t + 1 < nT) {
            int k0 = (t + 1) << 5;
            #pragma unroll
            for (int u = 0; u < 2; u++) {
                int s_ = tid + (u << 8);
                int r = s_ >> 2, q = s_ & 3;
                pa[u] = *(const uint4*)(Aptr + (size_t)r * K + k0 + q * 8);
                pb[u] = *(const uint4*)(Bptr + (size_t)r * K + k0 + q * 8);
            }
        }

        #pragma unroll
        for (int ks = 0; ks < 2; ks++) {
            uint32_t a4[4][4], b2[4][2];
            #pragma unroll
            for (int mi = 0; mi < 4; mi++) ldsm4(a4[mi], aB[mi] + ks * 32);
            #pragma unroll
            for (int ni = 0; ni < 4; ni++) ldsm2(b2[ni], bB[ni] + ks * 32);
            #pragma unroll
            for (int mi = 0; mi < 4; mi++)
                #pragma unroll
                for (int ni = 0; ni < 4; ni++)
                    mma_f16(acc[mi][ni], a4[mi], b2[ni]);
        }
        __syncthreads();
    }

    // ------------------- epilogue (fused RoPE / half or float out) ----------
    #pragma unroll
    for (int mi = 0; mi < 4; mi++) {
        int row = mBase + warpM * 64 + mi * 16 + g;
        int s0 = row & (SEQ - 1);
        int s1 = (row + 8) & (SEQ - 1);
        #pragma unroll
        for (int ni = 0; ni < 4; ni++) {
            int col = nBase + warpN * 32 + ni * 8 + tig * 2;
            float v0 = acc[mi][ni][0], v1 = acc[mi][ni][1];
            float v2 = acc[mi][ni][2], v3 = acc[mi][ni][3];
            if (projMode && !svBlk &&
                (col < 1024 || (col >= 1536 && col < 2560))) {
                int tt = (col & 63) >> 1;
                float c0 = fc[s0*32 + tt], sn0 = fs[s0*32 + tt];
                float c1 = fc[s1*32 + tt], sn1 = fs[s1*32 + tt];
                float n0 = v0*c0 - v1*sn0, n1 = v0*sn0 + v1*c0;
                float n2 = v2*c1 - v3*sn1, n3 = v2*sn1 + v3*c1;
                v0 = n0; v1 = n1; v2 = n2; v3 = n3;
            }
            if (projMode) {
                __half* dst = svBlk ? Ch2 : Ch;
                int ld     = svBlk ? 512 : ldC;
                int colOut = svBlk ? (col - 3584) : col;
                *(uint32_t*)&dst[(size_t)row * ld + colOut]       = pk2h(v0, v1);
                *(uint32_t*)&dst[(size_t)(row + 8) * ld + colOut] = pk2h(v2, v3);
            } else {
                *(float2*)&C[(size_t)row * ldC + col]       = make_float2(v0, v1);
                *(float2*)&C[(size_t)(row + 8) * ldC + col] = make_float2(v2, v3);
            }
        }
    }
}

// ---------------------------------------------------------------------------
// SA flash v6 (fp16): Br=Bc=64, 256 thr / 8 warps, m16n8k16, ldmatrix.trans
// for the PV V-operand. Emits fp16 context.
// ---------------------------------------------------------------------------
#define SA6_SMEM (4*64*72*2 + 448*4)

__global__ void __launch_bounds__(256) sa_flash6()
{
    extern __shared__ char smraw[];
    __half* sQ = (__half*)smraw;           // [64][72]
    __half* sK = sQ + 64*72;               // [64][72]
    __half* sP = sK + 64*72;               // [64][72]
    __half* sV = sP + 64*72;               // [64][72]  (j rows, d cols)
    float* sM    = (float*)(smraw + 4*64*72*2);   // [64]
    float* sL    = sM + 64;
    float* sCorr = sL + 64;
    float* sMaxP = sCorr + 64;             // [2][64]
    float* sSumP = sMaxP + 128;            // [2][64]

    const int tid  = threadIdx.x;
    const int lane = tid & 31, wid = tid >> 5;
    const int g    = lane >> 2, tig = lane & 3;
    const int wband = wid & 3, whalf = wid >> 2;
    const int r0   = wband * 16;
    const int b    = blockIdx.y >> 3, h = blockIdx.y & 7;
    const int bx   = gridDim.x - 1 - blockIdx.x;
    const int i0   = bx * 64;
    const int tbase = b * SEQ + i0;

    if (tid < 64) { sM[tid] = -1e30f; sL[tid] = 0.f; }

    #pragma unroll
    for (int u = 0; u < 2; u++) {
        int e = tid + (u << 8);
        int rr = e >> 3, c8 = e & 7;
        *(uint4*)&sQ[rr*72 + c8*8] =
            *(const uint4*)(g_projh + (size_t)(tbase+rr)*NC + COL_QSA + h*64 + c8*8);
    }

    const int lrow = (lane & 7) + ((lane >> 3) & 1) * 8;
    const uint32_t aQb = sm_addr(&sQ[(r0 + lrow)*72 + (lane >> 4) * 8]);
    const uint32_t aPb = sm_addr(&sP[(r0 + lrow)*72 + (lane >> 4) * 8]);
    uint32_t bKb[4];
    #pragma unroll
    for (int nt = 0; nt < 4; nt++)
        bKb[nt] = sm_addr(&sK[(whalf*32 + nt*8 + (lane & 7))*72 + ((lane >> 3) & 1) * 8]);
    const uint32_t bVb = sm_addr(&sV[(lane & 15) * 72]);

    const int rA = r0 + g, rB = rA + 8;

    float o[4][4];
    #pragma unroll
    for (int nt = 0; nt < 4; nt++)
        #pragma unroll
        for (int c = 0; c < 4; c++) o[nt][c] = 0.f;

    const int nJT = bx + 1;
    for (int jt = 0; jt < nJT; jt++) {
        __syncthreads();
        const int jb = b * SEQ + jt * 64;
        #pragma unroll
        for (int u = 0; u < 2; u++) {
            int e = tid + (u << 8);
            int rr = e >> 3, c8 = e & 7;
            const __half* base = g_projh + (size_t)(jb+rr)*NC + h*64 + c8*8;
            *(uint4*)&sK[rr*72 + c8*8] = *(const uint4*)(base + COL_KSA);
            *(uint4*)&sV[rr*72 + c8*8] = *(const uint4*)(base + COL_VSA);
        }
        __syncthreads();

        float c_[4][4];
        #pragma unroll
        for (int nt = 0; nt < 4; nt++)
            #pragma unroll
            for (int q = 0; q < 4; q++) c_[nt][q] = 0.f;
        #pragma unroll
        for (int ks = 0; ks < 4; ks++) {
            uint32_t a4[4];
            ldsm4(a4, aQb + ks * 32);
            #pragma unroll
            for (int nt = 0; nt < 4; nt++) {
                uint32_t b2[2];
                ldsm2(b2, bKb[nt] + ks * 32);
                mma_f16(c_[nt], a4, b2);
            }
        }
        const int rowA = i0 + rA, rowB = i0 + rB;
        float rmA = -1e30f, rmB = -1e30f;
        #pragma unroll
        for (int nt = 0; nt < 4; nt++) {
            int col = jt*64 + whalf*32 + nt*8 + tig*2;
            c_[nt][0] = (col     <= rowA) ? c_[nt][0]*0.125f : -1e30f;
            c_[nt][1] = (col + 1 <= rowA) ? c_[nt][1]*0.125f : -1e30f;
            c_[nt][2] = (col     <= rowB) ? c_[nt][2]*0.125f : -1e30f;
            c_[nt][3] = (col + 1 <= rowB) ? c_[nt][3]*0.125f : -1e30f;
            rmA = fmaxf(rmA, fmaxf(c_[nt][0], c_[nt][1]));
            rmB = fmaxf(rmB, fmaxf(c_[nt][2], c_[nt][3]));
        }
        rmA = fmaxf(rmA, __shfl_xor_sync(0xffffffffu, rmA, 1));
        rmA = fmaxf(rmA, __shfl_xor_sync(0xffffffffu, rmA, 2));
        rmB = fmaxf(rmB, __shfl_xor_sync(0xffffffffu, rmB, 1));
        rmB = fmaxf(rmB, __shfl_xor_sync(0xffffffffu, rmB, 2));
        if (tig == 0) { sMaxP[whalf*64 + rA] = rmA; sMaxP[whalf*64 + rB] = rmB; }
        __syncthreads();

        float newmA = fmaxf(sM[rA], fmaxf(sMaxP[rA], sMaxP[64 + rA]));
        float newmB = fmaxf(sM[rB], fmaxf(sMaxP[rB], sMaxP[64 + rB]));
        float corrA = __expf(sM[rA] - newmA);
        float corrB = __expf(sM[rB] - newmB);
        float sAcc = 0.f, sBcc = 0.f;
        #pragma unroll
        for (int nt = 0; nt < 4; nt++) {
            float p0 = __expf(c_[nt][0] - newmA);
            float p1 = __expf(c_[nt][1] - newmA);
            float p2 = __expf(c_[nt][2] - newmB);
            float p3 = __expf(c_[nt][3] - newmB);
            sAcc += p0 + p1; sBcc += p2 + p3;
            *(uint32_t*)&sP[rA*72 + whalf*32 + nt*8 + tig*2] = pk2h(p0, p1);
            *(uint32_t*)&sP[rB*72 + whalf*32 + nt*8 + tig*2] = pk2h(p2, p3);
        }
        sAcc += __shfl_xor_sync(0xffffffffu, sAcc, 1);
        sAcc += __shfl_xor_sync(0xffffffffu, sAcc, 2);
        sBcc += __shfl_xor_sync(0xffffffffu, sBcc, 1);
        sBcc += __shfl_xor_sync(0xffffffffu, sBcc, 2);
        if (tig == 0) { sSumP[whalf*64 + rA] = sAcc; sSumP[whalf*64 + rB] = sBcc; }
        if (whalf == 0 && tig == 0) { sCorr[rA] = corrA; sCorr[rB] = corrB; }
        __syncthreads();

        if (whalf == 0 && tig == 0) {
            sM[rA] = newmA; sL[rA] = sL[rA]*corrA + sSumP[rA] + sSumP[64 + rA];
            sM[rB] = newmB; sL[rB] = sL[rB]*corrB + sSumP[rB] + sSumP[64 + rB];
        }

        {
            float cA = sCorr[rA], cB = sCorr[rB];
            #pragma unroll
            for (int nt = 0; nt < 4; nt++) {
                o[nt][0] *= cA; o[nt][1] *= cA;
                o[nt][2] *= cB; o[nt][3] *= cB;
            }
        }
        #pragma unroll
        for (int ks = 0; ks < 4; ks++) {
            uint32_t a4[4];
            ldsm4(a4, aPb + ks * 32);
            #pragma unroll
            for (int nt = 0; nt < 4; nt++) {
                uint32_t b2[2];
                ldsm2t(b2, bVb + ks * 2304 + (whalf*32 + nt*8) * 2);
                mma_f16(o[nt], a4, b2);
            }
        }
    }

    __syncthreads();
    {
        const float invA = 1.f / sL[rA];
        const float invB = 1.f / sL[rB];
        #pragma unroll
        for (int nt = 0; nt < 4; nt++) {
            int col = whalf*32 + nt*8 + tig*2;
            *(uint32_t*)&g_sah[(size_t)(tbase+rA)*512 + h*64 + col] =
                pk2h(o[nt][0]*invA, o[nt][1]*invA);
            *(uint32_t*)&g_sah[(size_t)(tbase+rB)*512 + h*64 + col] =
                pk2h(o[nt][2]*invB, o[nt][3]*invB);
        }
    }
}

// ---------------------------------------------------------------------------
// RA flash v6 (fp16): extended V = [sv(64) | kr(512)], d_v=576. Br=Bc=64,
// 512 thr / 16 warps, m16n8k16, ldmatrix.trans V-operand.
// ---------------------------------------------------------------------------
#define RA6_SMEM ((3*64*72 + 64*584)*2 + 704*4)

__global__ void __launch_bounds__(512) ra_flash6()
{
    extern __shared__ char smraw[];
    __half* sQ = (__half*)smraw;           // [64][72]
    __half* sK = sQ + 64*72;               // [64][72]
    __half* sP = sK + 64*72;               // [64][72]
    __half* sV = sP + 64*72;               // [64][584]
    float* sM    = (float*)(smraw + (3*64*72 + 64*584)*2);
    float* sL    = sM + 64;
    float* sCorr = sL + 64;
    float* sMaxP = sCorr + 64;             // [4][64]
    float* sSumP = sMaxP + 256;            // [4][64]

    const int tid  = threadIdx.x;
    const int lane = tid & 31, wid = tid >> 5;
    const int g    = lane >> 2, tig = lane & 3;
    const int wband = wid & 3, wq = wid >> 2;
    const int r0   = wband * 16;
    const int b    = blockIdx.y >> 3, h = blockIdx.y & 7;
    const int bx   = gridDim.x - 1 - blockIdx.x;
    const int i0   = bx * 64;
    const int tbase = b * SEQ + i0;

    if (tid < 64) { sM[tid] = -1e30f; sL[tid] = 0.f; }

    {
        int rr = tid >> 3, c8 = tid & 7;
        *(uint4*)&sQ[rr*72 + c8*8] =
            *(const uint4*)(g_projh + (size_t)(tbase+rr)*NC + COL_QA + h*64 + c8*8);
    }

    const int lrow = (lane & 7) + ((lane >> 3) & 1) * 8;
    const uint32_t aQb = sm_addr(&sQ[(r0 + lrow)*72 + (lane >> 4) * 8]);
    const uint32_t aPb = sm_addr(&sP[(r0 + lrow)*72 + (lane >> 4) * 8]);
    uint32_t bKb[2];
    #pragma unroll
    for (int nt = 0; nt < 2; nt++)
        bKb[nt] = sm_addr(&sK[(wq*16 + nt*8 + (lane & 7))*72 + ((lane >> 3) & 1) * 8]);
    const uint32_t bVb = sm_addr(&sV[(lane & 15) * 584]);

    const int rA = r0 + g, rB = rA + 8;

    float o[18][4];
    #pragma unroll
    for (int nt = 0; nt < 18; nt++)
        #pragma unroll
        for (int c = 0; c < 4; c++) o[nt][c] = 0.f;

    const int nJT = bx + 1;
    for (int jt = 0; jt < nJT; jt++) {
        __syncthreads();
        const int jb = b * SEQ + jt * 64;
        {
            int rr = tid >> 3, c8 = tid & 7;
            *(uint4*)&sK[rr*72 + c8*8] =
                *(const uint4*)(g_projh + (size_t)(jb+rr)*NC + COL_KA + h*64 + c8*8);
        }
        for (int e = tid; e < 64 * 72; e += 512) {
            int rr = e / 72, c8 = e - rr * 72;
            uint4 v;
            if (c8 < 8)
                v = *(const uint4*)(g_svh + (size_t)(jb+rr)*512 + h*64 + c8*8);
            else
                v = *(const uint4*)(g_projh + (size_t)(jb+rr)*NC + COL_KR + (c8-8)*8);
            *(uint4*)&sV[rr*584 + c8*8] = v;
        }
        __syncthreads();

        float c_[2][4];
        #pragma unroll
        for (int nt = 0; nt < 2; nt++)
            #pragma unroll
            for (int q = 0; q < 4; q++) c_[nt][q] = 0.f;
        #pragma unroll
        for (int ks = 0; ks < 4; ks++) {
            uint32_t a4[4];
            ldsm4(a4, aQb + ks * 32);
            #pragma unroll
            for (int nt = 0; nt < 2; nt++) {
                uint32_t b2[2];
                ldsm2(b2, bKb[nt] + ks * 32);
                mma_f16(c_[nt], a4, b2);
            }
        }
        const int rowA = i0 + rA, rowB = i0 + rB;
        float rmA = -1e30f, rmB = -1e30f;
        #pragma unroll
        for (int nt = 0; nt < 2; nt++) {
            int col = jt*64 + wq*16 + nt*8 + tig*2;
            c_[nt][0] = (col     <= rowA) ? c_[nt][0]*0.125f : -1e30f;
            c_[nt][1] = (col + 1 <= rowA) ? c_[nt][1]*0.125f : -1e30f;
            c_[nt][2] = (col     <= rowB) ? c_[nt][2]*0.125f : -1e30f;
            c_[nt][3] = (col + 1 <= rowB) ? c_[nt][3]*0.125f : -1e30f;
            rmA = fmaxf(rmA, fmaxf(c_[nt][0], c_[nt][1]));
            rmB = fmaxf(rmB, fmaxf(c_[nt][2], c_[nt][3]));
        }
        rmA = fmaxf(rmA, __shfl_xor_sync(0xffffffffu, rmA, 1));
        rmA = fmaxf(rmA, __shfl_xor_sync(0xffffffffu, rmA, 2));
        rmB = fmaxf(rmB, __shfl_xor_sync(0xffffffffu, rmB, 1));
        rmB = fmaxf(rmB, __shfl_xor_sync(0xffffffffu, rmB, 2));
        if (tig == 0) { sMaxP[wq*64 + rA] = rmA; sMaxP[wq*64 + rB] = rmB; }
        __syncthreads();

        float newmA = sM[rA], newmB = sM[rB];
        #pragma unroll
        for (int q2 = 0; q2 < 4; q2++) {
            newmA = fmaxf(newmA, sMaxP[q2*64 + rA]);
            newmB = fmaxf(newmB, sMaxP[q2*64 + rB]);
        }
        float corrA = __expf(sM[rA] - newmA);
        float corrB = __expf(sM[rB] - newmB);
        float sAcc = 0.f, sBcc = 0.f;
        #pragma unroll
        for (int nt = 0; nt < 2; nt++) {
            float p0 = __expf(c_[nt][0] - newmA);
            float p1 = __expf(c_[nt][1] - newmA);
            float p2 = __expf(c_[nt][2] - newmB);
            float p3 = __expf(c_[nt][3] - newmB);
            sAcc += p0 + p1; sBcc += p2 + p3;
            *(uint32_t*)&sP[rA*72 + wq*16 + nt*8 + tig*2] = pk2h(p0, p1);
            *(uint32_t*)&sP[rB*72 + wq*16 + nt*8 + tig*2] = pk2h(p2, p3);
        }
        sAcc += __shfl_xor_sync(0xffffffffu, sAcc, 1);
        sAcc += __shfl_xor_sync(0xffffffffu, sAcc, 2);
        sBcc += __shfl_xor_sync(0xffffffffu, sBcc, 1);
        sBcc += __shfl_xor_sync(0xffffffffu, sBcc, 2);
        if (tig == 0) { sSumP[wq*64 + rA] = sAcc; sSumP[wq*64 + rB] = sBcc; }
        if (wq == 0 && tig == 0) { sCorr[rA] = corrA; sCorr[rB] = corrB; }
        __syncthreads();

        if (wq == 0 && tig == 0) {
            float la = sL[rA]*corrA, lb = sL[rB]*corrB;
            #pragma unroll
            for (int q2 = 0; q2 < 4; q2++) {
                la += sSumP[q2*64 + rA];
                lb += sSumP[q2*64 + rB];
            }
            sM[rA] = newmA; sL[rA] = la;
            sM[rB] = newmB; sL[rB] = lb;
        }

        {
            float cA = sCorr[rA], cB = sCorr[rB];
            #pragma unroll
            for (int nt = 0; nt < 18; nt++) {
                o[nt][0] *= cA; o[nt][1] *= cA;
                o[nt][2] *= cB; o[nt][3] *= cB;
            }
        }
        #pragma unroll
        for (int ks = 0; ks < 4; ks++) {
            uint32_t a4[4];
            ldsm4(a4, aPb + ks * 32);
            #pragma unroll
            for (int nt = 0; nt < 18; nt++) {
                uint32_t b2[2];
                ldsm2t(b2, bVb + ks * 18688 + (wq*144 + nt*8) * 2);
                mma_f16(o[nt], a4, b2);
            }
        }
    }

    __syncthreads();
    {
        const float invA = 1.f / sL[rA];
        const float invB = 1.f / sL[rB];
        const size_t akBase = ((size_t)blockIdx.y * SEQ + i0);
        #pragma unroll
        for (int nt = 0; nt < 18; nt++) {
            int col = wq*144 + nt*8 + tig*2;
            if (col < 64) {
                *(float2*)&g_ra[(size_t)(tbase+rA)*512 + h*64 + col] =
                    make_float2(o[nt][0]*invA, o[nt][1]*invA);
                *(float2*)&g_ra[(size_t)(tbase+rB)*512 + h*64 + col] =
                    make_float2(o[nt][2]*invB, o[nt][3]*invB);
            } else {
                *(uint32_t*)&g_attkrh[(akBase + rA)*512 + col - 64] =
                    pk2h(o[nt][0]*invA, o[nt][1]*invA);
                *(uint32_t*)&g_attkrh[(akBase + rB)*512 + col - 64] =
                    pk2h(o[nt][2]*invB, o[nt][3]*invB);
            }
        }
    }
}

// ---------------------------------------------------------------------------
// ra_post v2: 4 tokens per block, wr staged transposed in smem, emits fp16.
// swr[h*512 + r*64 + d] = wr[h*512 + d*8 + r].
// ---------------------------------------------------------------------------
__global__ void __launch_bounds__(256) ra_post2(const float* __restrict__ wr)
{
    __shared__ float swr[4096];
    const int tid = threadIdx.x;
    for (int i = tid; i < 4096; i += 256) {
        int h = i >> 9, rem = i & 511, d = rem >> 3, r = rem & 7;
        swr[h*512 + r*64 + d] = wr[i];
    }
    __syncthreads();

    const int lane = tid & 31;
    const int h    = tid >> 5;

    #pragma unroll
    for (int t = 0; t < 4; t++) {
        const int token = blockIdx.x * 4 + t;
        const int bb = token >> 11;
        const int ii = token & (SEQ - 1);

        const int r = lane >> 2, q = lane & 3;
        const __half2* q2 = (const __half2*)(g_projh + (size_t)token * NC + COL_QR + r*64 + q*16);
        const __half2* a2 = (const __half2*)(g_attkrh + (((size_t)(bb*8 + h)) * SEQ + ii) * 512 + r*64 + q*16);

        float part = 0.f;
        #pragma unroll
        for (int u = 0; u < 8; u++) {
            float2 qv = __half22float2(q2[u]);
            float2 av = __half22float2(a2[u]);
            part += qv.x*av.x + qv.y*av.y;
        }
        part += __shfl_xor_sync(0xffffffffu, part, 1);
        part += __shfl_xor_sync(0xffffffffu, part, 2);
        part *= 0.125f;

        float pr[8];
        #pragma unroll
        for (int r2 = 0; r2 < 8; r2++)
            pr[r2] = __shfl_sync(0xffffffffu, part, r2 << 2);

        const float2* sym = (const float2*)(g_ra + (size_t)token * 512 + h * 64 + lane * 2);
        float2 sv2 = *sym;
        float ro0 = 0.f, ro1 = 0.f;
        #pragma unroll
        for (int r2 = 0; r2 < 8; r2++) {
            float2 wv = *(const float2*)&swr[h*512 + r2*64 + lane*2];
            ro0 += pr[r2] * wv.x;
            ro1 += pr[r2] * wv.y;
        }
        *(uint32_t*)&g_rah[(size_t)token * 512 + h * 64 + lane * 2] =
            pk2h(sv2.x + ro0, sv2.y + ro1);
    }
}

// ---------------------------------------------------------------------------
extern "C" void kernel_launch(void* const* d_in, const int* in_sizes, int n_in,
                              void* d_out, int out_size)
{
    (void)in_sizes; (void)n_in; (void)out_size;
    const float* x      = (const float*)d_in[0];
    const float* symb   = (const float*)d_in[1];
    const float* fc     = (const float*)d_in[2];
    const float* fs     = (const float*)d_in[3];
    const float* wq_sa  = (const float*)d_in[4];
    const float* wk_sa  = (const float*)d_in[5];
    const float* wv_sa  = (const float*)d_in[6];
    const float* wo_sa  = (const float*)d_in[7];
    const float* wq_at  = (const float*)d_in[8];
    const float* wk_at  = (const float*)d_in[9];
    const float* wq_rel = (const float*)d_in[10];
    const float* wk_rel = (const float*)d_in[11];
    const float* wr     = (const float*)d_in[12];
    const float* wv_ra  = (const float*)d_in[13];
    const float* wo_ra  = (const float*)d_in[14];
    float* out = (float*)d_out;

    __half *h16, *projh, *svh, *sah, *rah;
    cudaGetSymbolAddress((void**)&h16,   g_h16);
    cudaGetSymbolAddress((void**)&projh, g_projh);
    cudaGetSymbolAddress((void**)&svh,   g_svh);
    cudaGetSymbolAddress((void**)&sah,   g_sah);
    cudaGetSymbolAddress((void**)&rah,   g_rah);

    cudaFuncSetAttribute(sa_flash6, cudaFuncAttributeMaxDynamicSharedMemorySize, SA6_SMEM);
    cudaFuncSetAttribute(ra_flash6, cudaFuncAttributeMaxDynamicSharedMemorySize, RA6_SMEM);

    // 0) convert all fp32 operands to the fp16 pool
    CvtArgs ca;
    const float* srcs[12] = { x, symb, wq_sa, wk_sa, wv_sa, wq_at, wk_at,
                              wq_rel, wk_rel, wv_ra, wo_sa, wo_ra };
    int sizes[12] = { NTOK*DM, NTOK*DM, W_SZ, W_SZ, W_SZ, W_SZ, W_SZ,
                      W_SZ, W_SZ, W_SZ, 512*512, 512*512 };
    int off = 0;
    for (int i = 0; i < 12; i++) { ca.src[i] = srcs[i]; ca.off[i] = off; off += sizes[i]; }
    ca.off[12] = off;
    cvt_kernel<<<(off / 4 + 255) / 256, 256>>>(ca);

    // 1) fused projections (blocks 0..6 from x, RoPE fused) + sv (block 7)
    W8h w8;
    for (int i = 0; i < 8; i++) w8.p[i] = h16 + OFF_W + i * W_SZ;
    gemm_h<<<dim3(32, NTOK / 128), 256>>>(h16 + OFF_X, h16 + OFF_SY, w8,
                                          nullptr, projh, svh, DM, NC, fc, fs);

    // 2) SA flash (fp16 in/out)
    sa_flash6<<<dim3(SEQ / 64, BATCH * 8), 256, SA6_SMEM>>>();

    // 3) RA flash + rel post pass (emits fp16 RA context)
    ra_flash6<<<dim3(SEQ / 64, BATCH * 8), 512, RA6_SMEM>>>();
    ra_post2<<<NTOK / 4, 256>>>(wr);

    // 4) both output projections in ONE launch (fp32 out)
    W8h wo;
    wo.p[0] = h16 + OFF_WOSA; wo.p[1] = h16 + OFF_WORA;
    for (int i = 2; i < 8; i++) wo.p[i] = h16 + OFF_WOSA;
    gemm_h<<<dim3(8, NTOK / 128), 256>>>(sah, rah, wo, out, nullptr, nullptr,
                                         512, 1024, nullptr, nullptr);
}

// round 13
// speedup vs baseline: 1.9817x; 1.0790x over previous
#include <cuda_runtime.h>
#include <cuda_fp16.h>
#include <cstdint>

#define BATCH 2
#define SEQ   2048
#define NTOK  (BATCH * SEQ)
#define DM    1024
#define NC    3584

#define COL_QSA 0
#define COL_KSA 512
#define COL_VSA 1024
#define COL_QA  1536
#define COL_KA  2048
#define COL_QR  2560
#define COL_KR  3072

// fp16 operand pool layout (halves)
#define OFF_X    0
#define OFF_SY   (NTOK*DM)
#define OFF_W    (2*NTOK*DM)
#define W_SZ     (512*DM)
#define OFF_WOSA (OFF_W + 8*W_SZ)
#define OFF_WORA (OFF_WOSA + 512*512)
#define H16_TOTAL (OFF_WORA + 512*512)

// Scratch (allocation-free rule: __device__ globals)
__device__ __half g_h16   [H16_TOTAL];
__device__ __half g_projh [NTOK * NC];
__device__ __half g_svh   [NTOK * 512];
__device__ __half g_sah   [NTOK * 512];
__device__ float  g_ra    [NTOK * 512];
__device__ __half g_rah   [NTOK * 512];
__device__ __half g_attkrh[16 * SEQ * 512];

struct W8h { const __half* p[8]; };
struct CvtArgs { const float* src[12]; int off[13]; };

// ---------------------------------------------------------------------------
// fp16 / mma / ldmatrix / cp.async helpers
// ---------------------------------------------------------------------------
__device__ __forceinline__ uint32_t pk2h(float a, float b) {
    __half2 h = __floats2half2_rn(a, b);
    return *reinterpret_cast<uint32_t*>(&h);
}
__device__ __forceinline__ void mma_f16(float* d, const uint32_t* a, const uint32_t* b) {
    asm volatile(
        "mma.sync.aligned.m16n8k16.row.col.f32.f16.f16.f32 "
        "{%0,%1,%2,%3}, {%4,%5,%6,%7}, {%8,%9}, {%0,%1,%2,%3};"
        : "+f"(d[0]), "+f"(d[1]), "+f"(d[2]), "+f"(d[3])
        : "r"(a[0]), "r"(a[1]), "r"(a[2]), "r"(a[3]), "r"(b[0]), "r"(b[1]));
}
__device__ __forceinline__ uint32_t sm_addr(const void* p) {
    return (uint32_t)__cvta_generic_to_shared(p);
}
__device__ __forceinline__ void ldsm4(uint32_t* r, uint32_t a) {
    asm volatile("ldmatrix.sync.aligned.m8n8.x4.shared.b16 {%0,%1,%2,%3}, [%4];"
        : "=r"(r[0]), "=r"(r[1]), "=r"(r[2]), "=r"(r[3]) : "r"(a));
}
__device__ __forceinline__ void ldsm2(uint32_t* r, uint32_t a) {
    asm volatile("ldmatrix.sync.aligned.m8n8.x2.shared.b16 {%0,%1}, [%2];"
        : "=r"(r[0]), "=r"(r[1]) : "r"(a));
}
__device__ __forceinline__ void ldsm2t(uint32_t* r, uint32_t a) {
    asm volatile("ldmatrix.sync.aligned.m8n8.x2.trans.shared.b16 {%0,%1}, [%2];"
        : "=r"(r[0]), "=r"(r[1]) : "r"(a));
}
__device__ __forceinline__ void cp16(uint32_t dst, const void* src) {
    asm volatile("cp.async.ca.shared.global [%0], [%1], 16;" :: "r"(dst), "l"(src));
}
#define CP_COMMIT() asm volatile("cp.async.commit_group;")
#define CP_WAIT1()  asm volatile("cp.async.wait_group 1;")

// ---------------------------------------------------------------------------
// cvt: fp32 -> fp16 pool
// ---------------------------------------------------------------------------
__global__ void __launch_bounds__(256) cvt_kernel(CvtArgs a)
{
    int e4 = (blockIdx.x * 256 + threadIdx.x) * 4;
    if (e4 >= a.off[12]) return;
    int seg = 0;
    #pragma unroll
    for (int s = 1; s < 12; s++) seg += (e4 >= a.off[s]);
    float4 v = *(const float4*)(a.src[seg] + (e4 - a.off[seg]));
    *(uint2*)&g_h16[e4] = make_uint2(pk2h(v.x, v.y), pk2h(v.z, v.w));
}

// ---------------------------------------------------------------------------
// fp16 tensor-core GEMM (unchanged from R12, proven)
// ---------------------------------------------------------------------------
__global__ void __launch_bounds__(256) gemm_h(
    const __half* __restrict__ A, const __half* __restrict__ A2,
    W8h w, float* __restrict__ C, __half* __restrict__ Ch,
    __half* __restrict__ Ch2, int K, int ldC,
    const float* __restrict__ fc, const float* __restrict__ fs)
{
    __shared__ __half As[128][40];
    __shared__ __half Bs[128][40];

    const int tid   = threadIdx.x;
    const int lane  = tid & 31;
    const int wid   = tid >> 5;
    const int warpM = wid >> 2;
    const int warpN = wid & 3;
    const int g     = lane >> 2;
    const int tig   = lane & 3;

    const int mBase = blockIdx.y * 128;
    const int nBase = blockIdx.x * 128;
    const int blk   = nBase >> 9;
    const __half* Wm = w.p[blk];
    const bool projMode = (Ch != nullptr);
    const bool svBlk = projMode && (blk == 7);
    const __half* Ab = projMode ? (svBlk ? A2 : A) : (blk ? A2 : A);
    const int wrow  = nBase & 511;

    const __half* Aptr = Ab + (size_t)mBase * K;
    const __half* Bptr = Wm + (size_t)wrow  * K;

    float acc[4][4][4];
    #pragma unroll
    for (int mi = 0; mi < 4; mi++)
        #pragma unroll
        for (int ni = 0; ni < 4; ni++)
            #pragma unroll
            for (int c = 0; c < 4; c++) acc[mi][ni][c] = 0.f;

    const int lrow  = (lane & 7) + ((lane >> 3) & 1) * 8;
    uint32_t aB[4], bB[4];
    #pragma unroll
    for (int mi = 0; mi < 4; mi++)
        aB[mi] = sm_addr(&As[warpM*64 + mi*16 + lrow][(lane >> 4) * 8]);
    #pragma unroll
    for (int ni = 0; ni < 4; ni++)
        bB[ni] = sm_addr(&Bs[warpN*32 + ni*8 + (lane & 7)][((lane >> 3) & 1) * 8]);

    const int nT = K >> 5;
    uint4 pa[2], pb[2];
    #pragma unroll
    for (int u = 0; u < 2; u++) {
        int s_ = tid + (u << 8);
        int r = s_ >> 2, q = s_ & 3;
        pa[u] = *(const uint4*)(Aptr + (size_t)r * K + q * 8);
        pb[u] = *(const uint4*)(Bptr + (size_t)r * K + q * 8);
    }

    for (int t = 0; t < nT; t++) {
        #pragma unroll
        for (int u = 0; u < 2; u++) {
            int s_ = tid + (u << 8);
            int r = s_ >> 2, q = s_ & 3;
            *(uint4*)&As[r][q * 8] = pa[u];
            *(uint4*)&Bs[r][q * 8] = pb[u];
        }
        __syncthreads();

        if (t + 1 < nT) {
            int k0 = (t + 1) << 5;
            #pragma unroll
            for (int u = 0; u < 2; u++) {
                int s_ = tid + (u << 8);
                int r = s_ >> 2, q = s_ & 3;
                pa[u] = *(const uint4*)(Aptr + (size_t)r * K + k0 + q * 8);
                pb[u] = *(const uint4*)(Bptr + (size_t)r * K + k0 + q * 8);
            }
        }

        #pragma unroll
        for (int ks = 0; ks < 2; ks++) {
            uint32_t a4[4][4], b2[4][2];
            #pragma unroll
            for (int mi = 0; mi < 4; mi++) ldsm4(a4[mi], aB[mi] + ks * 32);
            #pragma unroll
            for (int ni = 0; ni < 4; ni++) ldsm2(b2[ni], bB[ni] + ks * 32);
            #pragma unroll
            for (int mi = 0; mi < 4; mi++)
                #pragma unroll
                for (int ni = 0; ni < 4; ni++)
                    mma_f16(acc[mi][ni], a4[mi], b2[ni]);
        }
        __syncthreads();
    }

    #pragma unroll
    for (int mi = 0; mi < 4; mi++) {
        int row = mBase + warpM * 64 + mi * 16 + g;
        int s0 = row & (SEQ - 1);
        int s1 = (row + 8) & (SEQ - 1);
        #pragma unroll
        for (int ni = 0; ni < 4; ni++) {
            int col = nBase + warpN * 32 + ni * 8 + tig * 2;
            float v0 = acc[mi][ni][0], v1 = acc[mi][ni][1];
            float v2 = acc[mi][ni][2], v3 = acc[mi][ni][3];
            if (projMode && !svBlk &&
                (col < 1024 || (col >= 1536 && col < 2560))) {
                int tt = (col & 63) >> 1;
                float c0 = fc[s0*32 + tt], sn0 = fs[s0*32 + tt];
                float c1 = fc[s1*32 + tt], sn1 = fs[s1*32 + tt];
                float n0 = v0*c0 - v1*sn0, n1 = v0*sn0 + v1*c0;
                float n2 = v2*c1 - v3*sn1, n3 = v2*sn1 + v3*c1;
                v0 = n0; v1 = n1; v2 = n2; v3 = n3;
            }
            if (projMode) {
                __half* dst = svBlk ? Ch2 : Ch;
                int ld     = svBlk ? 512 : ldC;
                int colOut = svBlk ? (col - 3584) : col;
                *(uint32_t*)&dst[(size_t)row * ld + colOut]       = pk2h(v0, v1);
                *(uint32_t*)&dst[(size_t)(row + 8) * ld + colOut] = pk2h(v2, v3);
            } else {
                *(float2*)&C[(size_t)row * ldC + col]       = make_float2(v0, v1);
                *(float2*)&C[(size_t)(row + 8) * ldC + col] = make_float2(v2, v3);
            }
        }
    }
}

// ---------------------------------------------------------------------------
// SA flash v7 (fp16, cp.async double-buffered K/V)
// ---------------------------------------------------------------------------
#define SA7_SMEM (6*64*72*2 + 448*4)

__global__ void __launch_bounds__(256) sa_flash7()
{
    extern __shared__ char smraw[];
    __half* sQ  = (__half*)smraw;          // [64][72]
    __half* sK0 = sQ  + 64*72;             // [64][72] x2
    __half* sK1 = sK0 + 64*72;
    __half* sP  = sK1 + 64*72;             // [64][72]
    __half* sV0 = sP  + 64*72;             // [64][72] x2
    __half* sV1 = sV0 + 64*72;
    float* sM    = (float*)(smraw + 6*64*72*2);
    float* sL    = sM + 64;
    float* sCorr = sL + 64;
    float* sMaxP = sCorr + 64;             // [2][64]
    float* sSumP = sMaxP + 128;            // [2][64]

    const int tid  = threadIdx.x;
    const int lane = tid & 31, wid = tid >> 5;
    const int g    = lane >> 2, tig = lane & 3;
    const int wband = wid & 3, whalf = wid >> 2;
    const int r0   = wband * 16;
    const int b    = blockIdx.y >> 3, h = blockIdx.y & 7;
    const int bx   = gridDim.x - 1 - blockIdx.x;
    const int i0   = bx * 64;
    const int tbase = b * SEQ + i0;

    if (tid < 64) { sM[tid] = -1e30f; sL[tid] = 0.f; }

    #pragma unroll
    for (int u = 0; u < 2; u++) {
        int e = tid + (u << 8);
        int rr = e >> 3, c8 = e & 7;
        *(uint4*)&sQ[rr*72 + c8*8] =
            *(const uint4*)(g_projh + (size_t)(tbase+rr)*NC + COL_QSA + h*64 + c8*8);
    }

    const uint32_t kBuf[2] = { sm_addr(sK0), sm_addr(sK1) };
    const uint32_t vBuf[2] = { sm_addr(sV0), sm_addr(sV1) };

    const int lrow = (lane & 7) + ((lane >> 3) & 1) * 8;
    const uint32_t aQb = sm_addr(&sQ[(r0 + lrow)*72 + (lane >> 4) * 8]);
    const uint32_t aPb = sm_addr(&sP[(r0 + lrow)*72 + (lane >> 4) * 8]);
    // K ldsm offsets relative to buffer base
    uint32_t bKo[4];
    #pragma unroll
    for (int nt = 0; nt < 4; nt++)
        bKo[nt] = ((whalf*32 + nt*8 + (lane & 7))*72 + ((lane >> 3) & 1) * 8) * 2;
    const uint32_t bVo = ((lane & 15) * 72) * 2;

    const int rA = r0 + g, rB = rA + 8;

    float o[4][4];
    #pragma unroll
    for (int nt = 0; nt < 4; nt++)
        #pragma unroll
        for (int c = 0; c < 4; c++) o[nt][c] = 0.f;

    const int nJT = bx + 1;

    // prefetch tile 0 into buf 0
    {
        const int jb = b * SEQ;
        #pragma unroll
        for (int u = 0; u < 2; u++) {
            int e = tid + (u << 8);
            int rr = e >> 3, c8 = e & 7;
            const __half* base = g_projh + (size_t)(jb+rr)*NC + h*64 + c8*8;
            cp16(kBuf[0] + (rr*72 + c8*8)*2, base + COL_KSA);
            cp16(vBuf[0] + (rr*72 + c8*8)*2, base + COL_VSA);
        }
        CP_COMMIT();
    }

    for (int jt = 0; jt < nJT; jt++) {
        const int cur = jt & 1, nxt = cur ^ 1;
        __syncthreads();                 // prev iter done with buf nxt & sP
        if (jt + 1 < nJT) {
            const int jb = b * SEQ + (jt + 1) * 64;
            #pragma unroll
            for (int u = 0; u < 2; u++) {
                int e = tid + (u << 8);
                int rr = e >> 3, c8 = e & 7;
                const __half* base = g_projh + (size_t)(jb+rr)*NC + h*64 + c8*8;
                cp16(kBuf[nxt] + (rr*72 + c8*8)*2, base + COL_KSA);
                cp16(vBuf[nxt] + (rr*72 + c8*8)*2, base + COL_VSA);
            }
        }
        CP_COMMIT();
        CP_WAIT1();                      // tile jt resident
        __syncthreads();

        float c_[4][4];
        #pragma unroll
        for (int nt = 0; nt < 4; nt++)
            #pragma unroll
            for (int q = 0; q < 4; q++) c_[nt][q] = 0.f;
        #pragma unroll
        for (int ks = 0; ks < 4; ks++) {
            uint32_t a4[4];
            ldsm4(a4, aQb + ks * 32);
            #pragma unroll
            for (int nt = 0; nt < 4; nt++) {
                uint32_t b2[2];
                ldsm2(b2, kBuf[cur] + bKo[nt] + ks * 32);
                mma_f16(c_[nt], a4, b2);
            }
        }
        const int rowA = i0 + rA, rowB = i0 + rB;
        float rmA = -1e30f, rmB = -1e30f;
        #pragma unroll
        for (int nt = 0; nt < 4; nt++) {
            int col = jt*64 + whalf*32 + nt*8 + tig*2;
            c_[nt][0] = (col     <= rowA) ? c_[nt][0]*0.125f : -1e30f;
            c_[nt][1] = (col + 1 <= rowA) ? c_[nt][1]*0.125f : -1e30f;
            c_[nt][2] = (col     <= rowB) ? c_[nt][2]*0.125f : -1e30f;
            c_[nt][3] = (col + 1 <= rowB) ? c_[nt][3]*0.125f : -1e30f;
            rmA = fmaxf(rmA, fmaxf(c_[nt][0], c_[nt][1]));
            rmB = fmaxf(rmB, fmaxf(c_[nt][2], c_[nt][3]));
        }
        rmA = fmaxf(rmA, __shfl_xor_sync(0xffffffffu, rmA, 1));
        rmA = fmaxf(rmA, __shfl_xor_sync(0xffffffffu, rmA, 2));
        rmB = fmaxf(rmB, __shfl_xor_sync(0xffffffffu, rmB, 1));
        rmB = fmaxf(rmB, __shfl_xor_sync(0xffffffffu, rmB, 2));
        if (tig == 0) { sMaxP[whalf*64 + rA] = rmA; sMaxP[whalf*64 + rB] = rmB; }
        __syncthreads();

        float newmA = fmaxf(sM[rA], fmaxf(sMaxP[rA], sMaxP[64 + rA]));
        float newmB = fmaxf(sM[rB], fmaxf(sMaxP[rB], sMaxP[64 + rB]));
        float corrA = __expf(sM[rA] - newmA);
        float corrB = __expf(sM[rB] - newmB);
        float sAcc = 0.f, sBcc = 0.f;
        #pragma unroll
        for (int nt = 0; nt < 4; nt++) {
            float p0 = __expf(c_[nt][0] - newmA);
            float p1 = __expf(c_[nt][1] - newmA);
            float p2 = __expf(c_[nt][2] - newmB);
            float p3 = __expf(c_[nt][3] - newmB);
            sAcc += p0 + p1; sBcc += p2 + p3;
            *(uint32_t*)&sP[rA*72 + whalf*32 + nt*8 + tig*2] = pk2h(p0, p1);
            *(uint32_t*)&sP[rB*72 + whalf*32 + nt*8 + tig*2] = pk2h(p2, p3);
        }
        sAcc += __shfl_xor_sync(0xffffffffu, sAcc, 1);
        sAcc += __shfl_xor_sync(0xffffffffu, sAcc, 2);
        sBcc += __shfl_xor_sync(0xffffffffu, sBcc, 1);
        sBcc += __shfl_xor_sync(0xffffffffu, sBcc, 2);
        if (tig == 0) { sSumP[whalf*64 + rA] = sAcc; sSumP[whalf*64 + rB] = sBcc; }
        if (whalf == 0 && tig == 0) { sCorr[rA] = corrA; sCorr[rB] = corrB; }
        __syncthreads();

        if (whalf == 0 && tig == 0) {
            sM[rA] = newmA; sL[rA] = sL[rA]*corrA + sSumP[rA] + sSumP[64 + rA];
            sM[rB] = newmB; sL[rB] = sL[rB]*corrB + sSumP[rB] + sSumP[64 + rB];
        }

        {
            float cA = sCorr[rA], cB = sCorr[rB];
            #pragma unroll
            for (int nt = 0; nt < 4; nt++) {
                o[nt][0] *= cA; o[nt][1] *= cA;
                o[nt][2] *= cB; o[nt][3] *= cB;
            }
        }
        #pragma unroll
        for (int ks = 0; ks < 4; ks++) {
            uint32_t a4[4];
            ldsm4(a4, aPb + ks * 32);
            #pragma unroll
            for (int nt = 0; nt < 4; nt++) {
                uint32_t b2[2];
                ldsm2t(b2, vBuf[cur] + bVo + ks * 2304 + (whalf*32 + nt*8) * 2);
                mma_f16(o[nt], a4, b2);
            }
        }
    }

    __syncthreads();
    {
        const float invA = 1.f / sL[rA];
        const float invB = 1.f / sL[rB];
        #pragma unroll
        for (int nt = 0; nt < 4; nt++) {
            int col = whalf*32 + nt*8 + tig*2;
            *(uint32_t*)&g_sah[(size_t)(tbase+rA)*512 + h*64 + col] =
                pk2h(o[nt][0]*invA, o[nt][1]*invA);
            *(uint32_t*)&g_sah[(size_t)(tbase+rB)*512 + h*64 + col] =
                pk2h(o[nt][2]*invB, o[nt][3]*invB);
        }
    }
}

// ---------------------------------------------------------------------------
// RA flash v7 (fp16, cp.async double-buffered K/V): extended V = [sv|kr],
// d_v=576, Br=Bc=64, 512 thr / 16 warps.
// ---------------------------------------------------------------------------
#define RA7_SMEM ((2*64*72 + 2*64*72 + 2*64*584)*2 + 704*4)

__global__ void __launch_bounds__(512) ra_flash7()
{
    extern __shared__ char smraw[];
    __half* sQ  = (__half*)smraw;          // [64][72]
    __half* sK0 = sQ  + 64*72;             // [64][72] x2
    __half* sK1 = sK0 + 64*72;
    __half* sP  = sK1 + 64*72;             // [64][72]
    __half* sV0 = sP  + 64*72;             // [64][584] x2
    __half* sV1 = sV0 + 64*584;
    float* sM    = (float*)(smraw + (4*64*72 + 2*64*584)*2);
    float* sL    = sM + 64;
    float* sCorr = sL + 64;
    float* sMaxP = sCorr + 64;             // [4][64]
    float* sSumP = sMaxP + 256;            // [4][64]

    const int tid  = threadIdx.x;
    const int lane = tid & 31, wid = tid >> 5;
    const int g    = lane >> 2, tig = lane & 3;
    const int wband = wid & 3, wq = wid >> 2;
    const int r0   = wband * 16;
    const int b    = blockIdx.y >> 3, h = blockIdx.y & 7;
    const int bx   = gridDim.x - 1 - blockIdx.x;
    const int i0   = bx * 64;
    const int tbase = b * SEQ + i0;

    if (tid < 64) { sM[tid] = -1e30f; sL[tid] = 0.f; }

    {
        int rr = tid >> 3, c8 = tid & 7;
        *(uint4*)&sQ[rr*72 + c8*8] =
            *(const uint4*)(g_projh + (size_t)(tbase+rr)*NC + COL_QA + h*64 + c8*8);
    }

    const uint32_t kBuf[2] = { sm_addr(sK0), sm_addr(sK1) };
    const uint32_t vBuf[2] = { sm_addr(sV0), sm_addr(sV1) };

    const int lrow = (lane & 7) + ((lane >> 3) & 1) * 8;
    const uint32_t aQb = sm_addr(&sQ[(r0 + lrow)*72 + (lane >> 4) * 8]);
    const uint32_t aPb = sm_addr(&sP[(r0 + lrow)*72 + (lane >> 4) * 8]);
    uint32_t bKo[2];
    #pragma unroll
    for (int nt = 0; nt < 2; nt++)
        bKo[nt] = ((wq*16 + nt*8 + (lane & 7))*72 + ((lane >> 3) & 1) * 8) * 2;
    const uint32_t bVo = ((lane & 15) * 584) * 2;

    const int rA = r0 + g, rB = rA + 8;

    float o[18][4];
    #pragma unroll
    for (int nt = 0; nt < 18; nt++)
        #pragma unroll
        for (int c = 0; c < 4; c++) o[nt][c] = 0.f;

    const int nJT = bx + 1;

    // prefetch tile 0 into buf 0
    {
        const int jb = b * SEQ;
        {
            int rr = tid >> 3, c8 = tid & 7;
            cp16(kBuf[0] + (rr*72 + c8*8)*2,
                 g_projh + (size_t)(jb+rr)*NC + COL_KA + h*64 + c8*8);
        }
        for (int e = tid; e < 64 * 72; e += 512) {
            int rr = e / 72, c8 = e - rr * 72;
            const __half* src = (c8 < 8)
                ? g_svh + (size_t)(jb+rr)*512 + h*64 + c8*8
                : g_projh + (size_t)(jb+rr)*NC + COL_KR + (c8-8)*8;
            cp16(vBuf[0] + (rr*584 + c8*8)*2, src);
        }
        CP_COMMIT();
    }

    for (int jt = 0; jt < nJT; jt++) {
        const int cur = jt & 1, nxt = cur ^ 1;
        __syncthreads();
        if (jt + 1 < nJT) {
            const int jb = b * SEQ + (jt + 1) * 64;
            {
                int rr = tid >> 3, c8 = tid & 7;
                cp16(kBuf[nxt] + (rr*72 + c8*8)*2,
                     g_projh + (size_t)(jb+rr)*NC + COL_KA + h*64 + c8*8);
            }
            for (int e = tid; e < 64 * 72; e += 512) {
                int rr = e / 72, c8 = e - rr * 72;
                const __half* src = (c8 < 8)
                    ? g_svh + (size_t)(jb+rr)*512 + h*64 + c8*8
                    : g_projh + (size_t)(jb+rr)*NC + COL_KR + (c8-8)*8;
                cp16(vBuf[nxt] + (rr*584 + c8*8)*2, src);
            }
        }
        CP_COMMIT();
        CP_WAIT1();
        __syncthreads();

        float c_[2][4];
        #pragma unroll
        for (int nt = 0; nt < 2; nt++)
            #pragma unroll
            for (int q = 0; q < 4; q++) c_[nt][q] = 0.f;
        #pragma unroll
        for (int ks = 0; ks < 4; ks++) {
            uint32_t a4[4];
            ldsm4(a4, aQb + ks * 32);
            #pragma unroll
            for (int nt = 0; nt < 2; nt++) {
                uint32_t b2[2];
                ldsm2(b2, kBuf[cur] + bKo[nt] + ks * 32);
                mma_f16(c_[nt], a4, b2);
            }
        }
        const int rowA = i0 + rA, rowB = i0 + rB;
        float rmA = -1e30f, rmB = -1e30f;
        #pragma unroll
        for (int nt = 0; nt < 2; nt++) {
            int col = jt*64 + wq*16 + nt*8 + tig*2;
            c_[nt][0] = (col     <= rowA) ? c_[nt][0]*0.125f : -1e30f;
            c_[nt][1] = (col + 1 <= rowA) ? c_[nt][1]*0.125f : -1e30f;
            c_[nt][2] = (col     <= rowB) ? c_[nt][2]*0.125f : -1e30f;
            c_[nt][3] = (col + 1 <= rowB) ? c_[nt][3]*0.125f : -1e30f;
            rmA = fmaxf(rmA, fmaxf(c_[nt][0], c_[nt][1]));
            rmB = fmaxf(rmB, fmaxf(c_[nt][2], c_[nt][3]));
        }
        rmA = fmaxf(rmA, __shfl_xor_sync(0xffffffffu, rmA, 1));
        rmA = fmaxf(rmA, __shfl_xor_sync(0xffffffffu, rmA, 2));
        rmB = fmaxf(rmB, __shfl_xor_sync(0xffffffffu, rmB, 1));
        rmB = fmaxf(rmB, __shfl_xor_sync(0xffffffffu, rmB, 2));
        if (tig == 0) { sMaxP[wq*64 + rA] = rmA; sMaxP[wq*64 + rB] = rmB; }
        __syncthreads();

        float newmA = sM[rA], newmB = sM[rB];
        #pragma unroll
        for (int q2 = 0; q2 < 4; q2++) {
            newmA = fmaxf(newmA, sMaxP[q2*64 + rA]);
            newmB = fmaxf(newmB, sMaxP[q2*64 + rB]);
        }
        float corrA = __expf(sM[rA] - newmA);
        float corrB = __expf(sM[rB] - newmB);
        float sAcc = 0.f, sBcc = 0.f;
        #pragma unroll
        for (int nt = 0; nt < 2; nt++) {
            float p0 = __expf(c_[nt][0] - newmA);
            float p1 = __expf(c_[nt][1] - newmA);
            float p2 = __expf(c_[nt][2] - newmB);
            float p3 = __expf(c_[nt][3] - newmB);
            sAcc += p0 + p1; sBcc += p2 + p3;
            *(uint32_t*)&sP[rA*72 + wq*16 + nt*8 + tig*2] = pk2h(p0, p1);
            *(uint32_t*)&sP[rB*72 + wq*16 + nt*8 + tig*2] = pk2h(p2, p3);
        }
        sAcc += __shfl_xor_sync(0xffffffffu, sAcc, 1);
        sAcc += __shfl_xor_sync(0xffffffffu, sAcc, 2);
        sBcc += __shfl_xor_sync(0xffffffffu, sBcc, 1);
        sBcc += __shfl_xor_sync(0xffffffffu, sBcc, 2);
        if (tig == 0) { sSumP[wq*64 + rA] = sAcc; sSumP[wq*64 + rB] = sBcc; }
        if (wq == 0 && tig == 0) { sCorr[rA] = corrA; sCorr[rB] = corrB; }
        __syncthreads();

        if (wq == 0 && tig == 0) {
            float la = sL[rA]*corrA, lb = sL[rB]*corrB;
            #pragma unroll
            for (int q2 = 0; q2 < 4; q2++) {
                la += sSumP[q2*64 + rA];
                lb += sSumP[q2*64 + rB];
            }
            sM[rA] = newmA; sL[rA] = la;
            sM[rB] = newmB; sL[rB] = lb;
        }

        {
            float cA = sCorr[rA], cB = sCorr[rB];
            #pragma unroll
            for (int nt = 0; nt < 18; nt++) {
                o[nt][0] *= cA; o[nt][1] *= cA;
                o[nt][2] *= cB; o[nt][3] *= cB;
            }
        }
        #pragma unroll
        for (int ks = 0; ks < 4; ks++) {
            uint32_t a4[4];
            ldsm4(a4, aPb + ks * 32);
            #pragma unroll
            for (int nt = 0; nt < 18; nt++) {
                uint32_t b2[2];
                ldsm2t(b2, vBuf[cur] + bVo + ks * 18688 + (wq*144 + nt*8) * 2);
                mma_f16(o[nt], a4, b2);
            }
        }
    }

    __syncthreads();
    {
        const float invA = 1.f / sL[rA];
        const float invB = 1.f / sL[rB];
        const size_t akBase = ((size_t)blockIdx.y * SEQ + i0);
        #pragma unroll
        for (int nt = 0; nt < 18; nt++) {
            int col = wq*144 + nt*8 + tig*2;
            if (col < 64) {
                *(float2*)&g_ra[(size_t)(tbase+rA)*512 + h*64 + col] =
                    make_float2(o[nt][0]*invA, o[nt][1]*invA);
                *(float2*)&g_ra[(size_t)(tbase+rB)*512 + h*64 + col] =
                    make_float2(o[nt][2]*invB, o[nt][3]*invB);
            } else {
                *(uint32_t*)&g_attkrh[(akBase + rA)*512 + col - 64] =
                    pk2h(o[nt][0]*invA, o[nt][1]*invA);
                *(uint32_t*)&g_attkrh[(akBase + rB)*512 + col - 64] =
                    pk2h(o[nt][2]*invB, o[nt][3]*invB);
            }
        }
    }
}

// ---------------------------------------------------------------------------
// ra_post v2 (unchanged from R12)
// ---------------------------------------------------------------------------
__global__ void __launch_bounds__(256) ra_post2(const float* __restrict__ wr)
{
    __shared__ float swr[4096];
    const int tid = threadIdx.x;
    for (int i = tid; i < 4096; i += 256) {
        int h = i >> 9, rem = i & 511, d = rem >> 3, r = rem & 7;
        swr[h*512 + r*64 + d] = wr[i];
    }
    __syncthreads();

    const int lane = tid & 31;
    const int h    = tid >> 5;

    #pragma unroll
    for (int t = 0; t < 4; t++) {
        const int token = blockIdx.x * 4 + t;
        const int bb = token >> 11;
        const int ii = token & (SEQ - 1);

        const int r = lane >> 2, q = lane & 3;
        const __half2* q2 = (const __half2*)(g_projh + (size_t)token * NC + COL_QR + r*64 + q*16);
        const __half2* a2 = (const __half2*)(g_attkrh + (((size_t)(bb*8 + h)) * SEQ + ii) * 512 + r*64 + q*16);

        float part = 0.f;
        #pragma unroll
        for (int u = 0; u < 8; u++) {
            float2 qv = __half22float2(q2[u]);
            float2 av = __half22float2(a2[u]);
            part += qv.x*av.x + qv.y*av.y;
        }
        part += __shfl_xor_sync(0xffffffffu, part, 1);
        part += __shfl_xor_sync(0xffffffffu, part, 2);
        part *= 0.125f;

        float pr[8];
        #pragma unroll
        for (int r2 = 0; r2 < 8; r2++)
            pr[r2] = __shfl_sync(0xffffffffu, part, r2 << 2);

        const float2* sym = (const float2*)(g_ra + (size_t)token * 512 + h * 64 + lane * 2);
        float2 sv2 = *sym;
        float ro0 = 0.f, ro1 = 0.f;
        #pragma unroll
        for (int r2 = 0; r2 < 8; r2++) {
            float2 wv = *(const float2*)&swr[h*512 + r2*64 + lane*2];
            ro0 += pr[r2] * wv.x;
            ro1 += pr[r2] * wv.y;
        }
        *(uint32_t*)&g_rah[(size_t)token * 512 + h * 64 + lane * 2] =
            pk2h(sv2.x + ro0, sv2.y + ro1);
    }
}

// ---------------------------------------------------------------------------
extern "C" void kernel_launch(void* const* d_in, const int* in_sizes, int n_in,
                              void* d_out, int out_size)
{
    (void)in_sizes; (void)n_in; (void)out_size;
    const float* x      = (const float*)d_in[0];
    const float* symb   = (const float*)d_in[1];
    const float* fc     = (const float*)d_in[2];
    const float* fs     = (const float*)d_in[3];
    const float* wq_sa  = (const float*)d_in[4];
    const float* wk_sa  = (const float*)d_in[5];
    const float* wv_sa  = (const float*)d_in[6];
    const float* wo_sa  = (const float*)d_in[7];
    const float* wq_at  = (const float*)d_in[8];
    const float* wk_at  = (const float*)d_in[9];
    const float* wq_rel = (const float*)d_in[10];
    const float* wk_rel = (const float*)d_in[11];
    const float* wr     = (const float*)d_in[12];
    const float* wv_ra  = (const float*)d_in[13];
    const float* wo_ra  = (const float*)d_in[14];
    float* out = (float*)d_out;

    __half *h16, *projh, *svh, *sah, *rah;
    cudaGetSymbolAddress((void**)&h16,   g_h16);
    cudaGetSymbolAddress((void**)&projh, g_projh);
    cudaGetSymbolAddress((void**)&svh,   g_svh);
    cudaGetSymbolAddress((void**)&sah,   g_sah);
    cudaGetSymbolAddress((void**)&rah,   g_rah);

    cudaFuncSetAttribute(sa_flash7, cudaFuncAttributeMaxDynamicSharedMemorySize, SA7_SMEM);
    cudaFuncSetAttribute(ra_flash7, cudaFuncAttributeMaxDynamicSharedMemorySize, RA7_SMEM);

    // 0) convert all fp32 operands to the fp16 pool
    CvtArgs ca;
    const float* srcs[12] = { x, symb, wq_sa, wk_sa, wv_sa, wq_at, wk_at,
                              wq_rel, wk_rel, wv_ra, wo_sa, wo_ra };
    int sizes[12] = { NTOK*DM, NTOK*DM, W_SZ, W_SZ, W_SZ, W_SZ, W_SZ,
                      W_SZ, W_SZ, W_SZ, 512*512, 512*512 };
    int off = 0;
    for (int i = 0; i < 12; i++) { ca.src[i] = srcs[i]; ca.off[i] = off; off += sizes[i]; }
    ca.off[12] = off;
    cvt_kernel<<<(off / 4 + 255) / 256, 256>>>(ca);

    // 1) fused projections (blocks 0..6 from x, RoPE fused) + sv (block 7)
    W8h w8;
    for (int i = 0; i < 8; i++) w8.p[i] = h16 + OFF_W + i * W_SZ;
    gemm_h<<<dim3(32, NTOK / 128), 256>>>(h16 + OFF_X, h16 + OFF_SY, w8,
                                          nullptr, projh, svh, DM, NC, fc, fs);

    // 2) SA flash (pipelined)
    sa_flash7<<<dim3(SEQ / 64, BATCH * 8), 256, SA7_SMEM>>>();

    // 3) RA flash (pipelined) + rel post pass
    ra_flash7<<<dim3(SEQ / 64, BATCH * 8), 512, RA7_SMEM>>>();
    ra_post2<<<NTOK / 4, 256>>>(wr);

    // 4) both output projections in ONE launch (fp32 out)
    W8h wo;
    wo.p[0] = h16 + OFF_WOSA; wo.p[1] = h16 + OFF_WORA;
    for (int i = 2; i < 8; i++) wo.p[i] = h16 + OFF_WOSA;
    gemm_h<<<dim3(8, NTOK / 128), 256>>>(sah, rah, wo, out, nullptr, nullptr,
                                         512, 1024, nullptr, nullptr);
}

// round 15
// speedup vs baseline: 2.0443x; 1.0315x over previous
#include <cuda_runtime.h>
#include <cuda_fp16.h>
#include <cstdint>

#define BATCH 2
#define SEQ   2048
#define NTOK  (BATCH * SEQ)
#define DM    1024
#define NC    3584

#define COL_QSA 0
#define COL_KSA 512
#define COL_VSA 1024
#define COL_QA  1536
#define COL_KA  2048
#define COL_QR  2560
#define COL_KR  3072

// fp16 operand pool layout (halves)
#define OFF_X    0
#define OFF_SY   (NTOK*DM)
#define OFF_W    (2*NTOK*DM)
#define W_SZ     (512*DM)
#define OFF_WOSA (OFF_W + 8*W_SZ)
#define OFF_WORA (OFF_WOSA + 512*512)
#define H16_TOTAL (OFF_WORA + 512*512)

// Scratch (allocation-free rule: __device__ globals)
__device__ __half g_h16   [H16_TOTAL];
__device__ __half g_projh [NTOK * NC];
__device__ __half g_svh   [NTOK * 512];
__device__ __half g_sah   [NTOK * 512];
__device__ float  g_ra    [NTOK * 512];
__device__ __half g_rah   [NTOK * 512];
__device__ __half g_attkrh[16 * SEQ * 512];

struct W8h { const __half* p[8]; };
struct CvtArgs { const float* src[12]; int off[13]; };

// ---------------------------------------------------------------------------
// fp16 / mma / ldmatrix / cp.async helpers
// ---------------------------------------------------------------------------
__device__ __forceinline__ uint32_t pk2h(float a, float b) {
    __half2 h = __floats2half2_rn(a, b);
    return *reinterpret_cast<uint32_t*>(&h);
}
__device__ __forceinline__ void mma_f16(float* d, const uint32_t* a, const uint32_t* b) {
    asm volatile(
        "mma.sync.aligned.m16n8k16.row.col.f32.f16.f16.f32 "
        "{%0,%1,%2,%3}, {%4,%5,%6,%7}, {%8,%9}, {%0,%1,%2,%3};"
        : "+f"(d[0]), "+f"(d[1]), "+f"(d[2]), "+f"(d[3])
        : "r"(a[0]), "r"(a[1]), "r"(a[2]), "r"(a[3]), "r"(b[0]), "r"(b[1]));
}
__device__ __forceinline__ uint32_t sm_addr(const void* p) {
    return (uint32_t)__cvta_generic_to_shared(p);
}
__device__ __forceinline__ void ldsm4(uint32_t* r, uint32_t a) {
    asm volatile("ldmatrix.sync.aligned.m8n8.x4.shared.b16 {%0,%1,%2,%3}, [%4];"
        : "=r"(r[0]), "=r"(r[1]), "=r"(r[2]), "=r"(r[3]) : "r"(a));
}
__device__ __forceinline__ void ldsm2(uint32_t* r, uint32_t a) {
    asm volatile("ldmatrix.sync.aligned.m8n8.x2.shared.b16 {%0,%1}, [%2];"
        : "=r"(r[0]), "=r"(r[1]) : "r"(a));
}
__device__ __forceinline__ void ldsm2t(uint32_t* r, uint32_t a) {
    asm volatile("ldmatrix.sync.aligned.m8n8.x2.trans.shared.b16 {%0,%1}, [%2];"
        : "=r"(r[0]), "=r"(r[1]) : "r"(a));
}
__device__ __forceinline__ void cp16(uint32_t dst, const void* src) {
    asm volatile("cp.async.ca.shared.global [%0], [%1], 16;" :: "r"(dst), "l"(src));
}
#define CP_COMMIT() asm volatile("cp.async.commit_group;")
#define CP_WAIT1()  asm volatile("cp.async.wait_group 1;")

// ---------------------------------------------------------------------------
// cvt: fp32 -> fp16 pool
// ---------------------------------------------------------------------------
__global__ void __launch_bounds__(256) cvt_kernel(CvtArgs a)
{
    int e4 = (blockIdx.x * 256 + threadIdx.x) * 4;
    if (e4 >= a.off[12]) return;
    int seg = 0;
    #pragma unroll
    for (int s = 1; s < 12; s++) seg += (e4 >= a.off[s]);
    float4 v = *(const float4*)(a.src[seg] + (e4 - a.off[seg]));
    *(uint2*)&g_h16[e4] = make_uint2(pk2h(v.x, v.y), pk2h(v.z, v.w));
}

// ---------------------------------------------------------------------------
// fp16 tensor-core GEMM (unchanged, proven)
// ---------------------------------------------------------------------------
__global__ void __launch_bounds__(256) gemm_h(
    const __half* __restrict__ A, const __half* __restrict__ A2,
    W8h w, float* __restrict__ C, __half* __restrict__ Ch,
    __half* __restrict__ Ch2, int K, int ldC,
    const float* __restrict__ fc, const float* __restrict__ fs)
{
    __shared__ __half As[128][40];
    __shared__ __half Bs[128][40];

    const int tid   = threadIdx.x;
    const int lane  = tid & 31;
    const int wid   = tid >> 5;
    const int warpM = wid >> 2;
    const int warpN = wid & 3;
    const int g     = lane >> 2;
    const int tig   = lane & 3;

    const int mBase = blockIdx.y * 128;
    const int nBase = blockIdx.x * 128;
    const int blk   = nBase >> 9;
    const __half* Wm = w.p[blk];
    const bool projMode = (Ch != nullptr);
    const bool svBlk = projMode && (blk == 7);
    const __half* Ab = projMode ? (svBlk ? A2 : A) : (blk ? A2 : A);
    const int wrow  = nBase & 511;

    const __half* Aptr = Ab + (size_t)mBase * K;
    const __half* Bptr = Wm + (size_t)wrow  * K;

    float acc[4][4][4];
    #pragma unroll
    for (int mi = 0; mi < 4; mi++)
        #pragma unroll
        for (int ni = 0; ni < 4; ni++)
            #pragma unroll
            for (int c = 0; c < 4; c++) acc[mi][ni][c] = 0.f;

    const int lrow  = (lane & 7) + ((lane >> 3) & 1) * 8;
    uint32_t aB[4], bB[4];
    #pragma unroll
    for (int mi = 0; mi < 4; mi++)
        aB[mi] = sm_addr(&As[warpM*64 + mi*16 + lrow][(lane >> 4) * 8]);
    #pragma unroll
    for (int ni = 0; ni < 4; ni++)
        bB[ni] = sm_addr(&Bs[warpN*32 + ni*8 + (lane & 7)][((lane >> 3) & 1) * 8]);

    const int nT = K >> 5;
    uint4 pa[2], pb[2];
    #pragma unroll
    for (int u = 0; u < 2; u++) {
        int s_ = tid + (u << 8);
        int r = s_ >> 2, q = s_ & 3;
        pa[u] = *(const uint4*)(Aptr + (size_t)r * K + q * 8);
        pb[u] = *(const uint4*)(Bptr + (size_t)r * K + q * 8);
    }

    for (int t = 0; t < nT; t++) {
        #pragma unroll
        for (int u = 0; u < 2; u++) {
            int s_ = tid + (u << 8);
            int r = s_ >> 2, q = s_ & 3;
            *(uint4*)&As[r][q * 8] = pa[u];
            *(uint4*)&Bs[r][q * 8] = pb[u];
        }
        __syncthreads();

        if (t + 1 < nT) {
            int k0 = (t + 1) << 5;
            #pragma unroll
            for (int u = 0; u < 2; u++) {
                int s_ = tid + (u << 8);
                int r = s_ >> 2, q = s_ & 3;
                pa[u] = *(const uint4*)(Aptr + (size_t)r * K + k0 + q * 8);
                pb[u] = *(const uint4*)(Bptr + (size_t)r * K + k0 + q * 8);
            }
        }

        #pragma unroll
        for (int ks = 0; ks < 2; ks++) {
            uint32_t a4[4][4], b2[4][2];
            #pragma unroll
            for (int mi = 0; mi < 4; mi++) ldsm4(a4[mi], aB[mi] + ks * 32);
            #pragma unroll
            for (int ni = 0; ni < 4; ni++) ldsm2(b2[ni], bB[ni] + ks * 32);
            #pragma unroll
            for (int mi = 0; mi < 4; mi++)
                #pragma unroll
                for (int ni = 0; ni < 4; ni++)
                    mma_f16(acc[mi][ni], a4[mi], b2[ni]);
        }
        __syncthreads();
    }

    #pragma unroll
    for (int mi = 0; mi < 4; mi++) {
        int row = mBase + warpM * 64 + mi * 16 + g;
        int s0 = row & (SEQ - 1);
        int s1 = (row + 8) & (SEQ - 1);
        #pragma unroll
        for (int ni = 0; ni < 4; ni++) {
            int col = nBase + warpN * 32 + ni * 8 + tig * 2;
            float v0 = acc[mi][ni][0], v1 = acc[mi][ni][1];
            float v2 = acc[mi][ni][2], v3 = acc[mi][ni][3];
            if (projMode && !svBlk &&
                (col < 1024 || (col >= 1536 && col < 2560))) {
                int tt = (col & 63) >> 1;
                float c0 = fc[s0*32 + tt], sn0 = fs[s0*32 + tt];
                float c1 = fc[s1*32 + tt], sn1 = fs[s1*32 + tt];
                float n0 = v0*c0 - v1*sn0, n1 = v0*sn0 + v1*c0;
                float n2 = v2*c1 - v3*sn1, n3 = v2*sn1 + v3*c1;
                v0 = n0; v1 = n1; v2 = n2; v3 = n3;
            }
            if (projMode) {
                __half* dst = svBlk ? Ch2 : Ch;
                int ld     = svBlk ? 512 : ldC;
                int colOut = svBlk ? (col - 3584) : col;
                *(uint32_t*)&dst[(size_t)row * ld + colOut]       = pk2h(v0, v1);
                *(uint32_t*)&dst[(size_t)(row + 8) * ld + colOut] = pk2h(v2, v3);
            } else {
                *(float2*)&C[(size_t)row * ldC + col]       = make_float2(v0, v1);
                *(float2*)&C[(size_t)(row + 8) * ldC + col] = make_float2(v2, v3);
            }
        }
    }
}

// ---------------------------------------------------------------------------
// SA flash v8: cp.async double-buffered; PV warp grid remapped to
// 2 row-bands x 4 col-groups (m32 x n16 per warp) to halve V smem reads.
// ---------------------------------------------------------------------------
#define SA8_SMEM (6*64*72*2 + 448*4)

__global__ void __launch_bounds__(256) sa_flash8()
{
    extern __shared__ char smraw[];
    __half* sQ  = (__half*)smraw;          // [64][72]
    __half* sK0 = sQ  + 64*72;             // [64][72] x2
    __half* sK1 = sK0 + 64*72;
    __half* sP  = sK1 + 64*72;             // [64][72]
    __half* sV0 = sP  + 64*72;             // [64][72] x2
    __half* sV1 = sV0 + 64*72;
    float* sM    = (float*)(smraw + 6*64*72*2);
    float* sL    = sM + 64;
    float* sCorr = sL + 64;
    float* sMaxP = sCorr + 64;             // [2][64]
    float* sSumP = sMaxP + 128;            // [2][64]

    const int tid  = threadIdx.x;
    const int lane = tid & 31, wid = tid >> 5;
    const int g    = lane >> 2, tig = lane & 3;
    const int wband = wid & 3, whalf = wid >> 2;      // S mapping
    const int wband2 = wid & 1, grp2 = wid >> 1;      // PV mapping (0..3)
    const int r0   = wband * 16;
    const int r32  = wband2 * 32;
    const int b    = blockIdx.y >> 3, h = blockIdx.y & 7;
    const int bx   = gridDim.x - 1 - blockIdx.x;
    const int i0   = bx * 64;
    const int tbase = b * SEQ + i0;

    if (tid < 64) { sM[tid] = -1e30f; sL[tid] = 0.f; }

    #pragma unroll
    for (int u = 0; u < 2; u++) {
        int e = tid + (u << 8);
        int rr = e >> 3, c8 = e & 7;
        *(uint4*)&sQ[rr*72 + c8*8] =
            *(const uint4*)(g_projh + (size_t)(tbase+rr)*NC + COL_QSA + h*64 + c8*8);
    }

    const uint32_t kBuf[2] = { sm_addr(sK0), sm_addr(sK1) };
    const uint32_t vBuf[2] = { sm_addr(sV0), sm_addr(sV1) };

    const int lrow = (lane & 7) + ((lane >> 3) & 1) * 8;
    const uint32_t aQb = sm_addr(&sQ[(r0 + lrow)*72 + (lane >> 4) * 8]);
    uint32_t aPb2[2];
    #pragma unroll
    for (int mi = 0; mi < 2; mi++)
        aPb2[mi] = sm_addr(&sP[(r32 + mi*16 + lrow)*72 + (lane >> 4) * 8]);
    uint32_t bKo[4];
    #pragma unroll
    for (int nt = 0; nt < 4; nt++)
        bKo[nt] = ((whalf*32 + nt*8 + (lane & 7))*72 + ((lane >> 3) & 1) * 8) * 2;
    const uint32_t bVo = ((lane & 15) * 72) * 2;

    const int rA = r0 + g, rB = rA + 8;

    float o[2][2][4];
    #pragma unroll
    for (int mi = 0; mi < 2; mi++)
        #pragma unroll
        for (int nt = 0; nt < 2; nt++)
            #pragma unroll
            for (int c = 0; c < 4; c++) o[mi][nt][c] = 0.f;

    const int nJT = bx + 1;

    {
        const int jb = b * SEQ;
        #pragma unroll
        for (int u = 0; u < 2; u++) {
            int e = tid + (u << 8);
            int rr = e >> 3, c8 = e & 7;
            const __half* base = g_projh + (size_t)(jb+rr)*NC + h*64 + c8*8;
            cp16(kBuf[0] + (rr*72 + c8*8)*2, base + COL_KSA);
            cp16(vBuf[0] + (rr*72 + c8*8)*2, base + COL_VSA);
        }
        CP_COMMIT();
    }

    for (int jt = 0; jt < nJT; jt++) {
        const int cur = jt & 1, nxt = cur ^ 1;
        __syncthreads();
        if (jt + 1 < nJT) {
            const int jb = b * SEQ + (jt + 1) * 64;
            #pragma unroll
            for (int u = 0; u < 2; u++) {
                int e = tid + (u << 8);
                int rr = e >> 3, c8 = e & 7;
                const __half* base = g_projh + (size_t)(jb+rr)*NC + h*64 + c8*8;
                cp16(kBuf[nxt] + (rr*72 + c8*8)*2, base + COL_KSA);
                cp16(vBuf[nxt] + (rr*72 + c8*8)*2, base + COL_VSA);
            }
        }
        CP_COMMIT();
        CP_WAIT1();
        __syncthreads();

        // ---- S: warp (wband, whalf) m16 x n32 ----
        float c_[4][4];
        #pragma unroll
        for (int nt = 0; nt < 4; nt++)
            #pragma unroll
            for (int q = 0; q < 4; q++) c_[nt][q] = 0.f;
        #pragma unroll
        for (int ks = 0; ks < 4; ks++) {
            uint32_t a4[4];
            ldsm4(a4, aQb + ks * 32);
            #pragma unroll
            for (int nt = 0; nt < 4; nt++) {
                uint32_t b2[2];
                ldsm2(b2, kBuf[cur] + bKo[nt] + ks * 32);
                mma_f16(c_[nt], a4, b2);
            }
        }
        const int rowA = i0 + rA, rowB = i0 + rB;
        float rmA = -1e30f, rmB = -1e30f;
        #pragma unroll
        for (int nt = 0; nt < 4; nt++) {
            int col = jt*64 + whalf*32 + nt*8 + tig*2;
            c_[nt][0] = (col     <= rowA) ? c_[nt][0]*0.125f : -1e30f;
            c_[nt][1] = (col + 1 <= rowA) ? c_[nt][1]*0.125f : -1e30f;
            c_[nt][2] = (col     <= rowB) ? c_[nt][2]*0.125f : -1e30f;
            c_[nt][3] = (col + 1 <= rowB) ? c_[nt][3]*0.125f : -1e30f;
            rmA = fmaxf(rmA, fmaxf(c_[nt][0], c_[nt][1]));
            rmB = fmaxf(rmB, fmaxf(c_[nt][2], c_[nt][3]));
        }
        rmA = fmaxf(rmA, __shfl_xor_sync(0xffffffffu, rmA, 1));
        rmA = fmaxf(rmA, __shfl_xor_sync(0xffffffffu, rmA, 2));
        rmB = fmaxf(rmB, __shfl_xor_sync(0xffffffffu, rmB, 1));
        rmB = fmaxf(rmB, __shfl_xor_sync(0xffffffffu, rmB, 2));
        if (tig == 0) { sMaxP[whalf*64 + rA] = rmA; sMaxP[whalf*64 + rB] = rmB; }
        __syncthreads();

        float newmA = fmaxf(sM[rA], fmaxf(sMaxP[rA], sMaxP[64 + rA]));
        float newmB = fmaxf(sM[rB], fmaxf(sMaxP[rB], sMaxP[64 + rB]));
        float corrA = __expf(sM[rA] - newmA);
        float corrB = __expf(sM[rB] - newmB);
        float sAcc = 0.f, sBcc = 0.f;
        #pragma unroll
        for (int nt = 0; nt < 4; nt++) {
            float p0 = __expf(c_[nt][0] - newmA);
            float p1 = __expf(c_[nt][1] - newmA);
            float p2 = __expf(c_[nt][2] - newmB);
            float p3 = __expf(c_[nt][3] - newmB);
            sAcc += p0 + p1; sBcc += p2 + p3;
            *(uint32_t*)&sP[rA*72 + whalf*32 + nt*8 + tig*2] = pk2h(p0, p1);
            *(uint32_t*)&sP[rB*72 + whalf*32 + nt*8 + tig*2] = pk2h(p2, p3);
        }
        sAcc += __shfl_xor_sync(0xffffffffu, sAcc, 1);
        sAcc += __shfl_xor_sync(0xffffffffu, sAcc, 2);
        sBcc += __shfl_xor_sync(0xffffffffu, sBcc, 1);
        sBcc += __shfl_xor_sync(0xffffffffu, sBcc, 2);
        if (tig == 0) { sSumP[whalf*64 + rA] = sAcc; sSumP[whalf*64 + rB] = sBcc; }
        if (whalf == 0 && tig == 0) { sCorr[rA] = corrA; sCorr[rB] = corrB; }
        __syncthreads();

        if (whalf == 0 && tig == 0) {
            sM[rA] = newmA; sL[rA] = sL[rA]*corrA + sSumP[rA] + sSumP[64 + rA];
            sM[rB] = newmB; sL[rB] = sL[rB]*corrB + sSumP[rB] + sSumP[64 + rB];
        }

        // ---- PV: warp (wband2, grp2) m32 x n16 ----
        #pragma unroll
        for (int mi = 0; mi < 2; mi++) {
            float cA = sCorr[r32 + mi*16 + g], cB = sCorr[r32 + mi*16 + g + 8];
            #pragma unroll
            for (int nt = 0; nt < 2; nt++) {
                o[mi][nt][0] *= cA; o[mi][nt][1] *= cA;
                o[mi][nt][2] *= cB; o[mi][nt][3] *= cB;
            }
        }
        #pragma unroll
        for (int ks = 0; ks < 4; ks++) {
            uint32_t a0[4], a1[4];
            ldsm4(a0, aPb2[0] + ks * 32);
            ldsm4(a1, aPb2[1] + ks * 32);
            #pragma unroll
            for (int nt = 0; nt < 2; nt++) {
                uint32_t b2[2];
                ldsm2t(b2, vBuf[cur] + bVo + ks * 2304 + (grp2*16 + nt*8) * 2);
                mma_f16(o[0][nt], a0, b2);
                mma_f16(o[1][nt], a1, b2);
            }
        }
    }

    __syncthreads();
    #pragma unroll
    for (int mi = 0; mi < 2; mi++) {
        const int rA2 = r32 + mi*16 + g, rB2 = rA2 + 8;
        const float invA = 1.f / sL[rA2];
        const float invB = 1.f / sL[rB2];
        #pragma unroll
        for (int nt = 0; nt < 2; nt++) {
            int col = grp2*16 + nt*8 + tig*2;
            *(uint32_t*)&g_sah[(size_t)(tbase+rA2)*512 + h*64 + col] =
                pk2h(o[mi][nt][0]*invA, o[mi][nt][1]*invA);
            *(uint32_t*)&g_sah[(size_t)(tbase+rB2)*512 + h*64 + col] =
                pk2h(o[mi][nt][2]*invB, o[mi][nt][3]*invB);
        }
    }
}

// ---------------------------------------------------------------------------
// RA flash v8: cp.async double-buffered; PV warp grid remapped to
// 2 row-bands x 8 col-groups (m32 x n72 per warp) to halve V smem reads.
// ---------------------------------------------------------------------------
#define RA8_SMEM ((2*64*72 + 2*64*72 + 2*64*584)*2 + 704*4)

__global__ void __launch_bounds__(512) ra_flash8()
{
    extern __shared__ char smraw[];
    __half* sQ  = (__half*)smraw;          // [64][72]
    __half* sK0 = sQ  + 64*72;             // [64][72] x2
    __half* sK1 = sK0 + 64*72;
    __half* sP  = sK1 + 64*72;             // [64][72]
    __half* sV0 = sP  + 64*72;             // [64][584] x2
    __half* sV1 = sV0 + 64*584;
    float* sM    = (float*)(smraw + (4*64*72 + 2*64*584)*2);
    float* sL    = sM + 64;
    float* sCorr = sL + 64;
    float* sMaxP = sCorr + 64;             // [4][64]
    float* sSumP = sMaxP + 256;            // [4][64]

    const int tid  = threadIdx.x;
    const int lane = tid & 31, wid = tid >> 5;
    const int g    = lane >> 2, tig = lane & 3;
    const int wband = wid & 3, wq = wid >> 2;         // S mapping
    const int wband2 = wid & 1, grp2 = wid >> 1;      // PV mapping (0..7)
    const int r0   = wband * 16;
    const int r32  = wband2 * 32;
    const int b    = blockIdx.y >> 3, h = blockIdx.y & 7;
    const int bx   = gridDim.x - 1 - blockIdx.x;
    const int i0   = bx * 64;
    const int tbase = b * SEQ + i0;

    if (tid < 64) { sM[tid] = -1e30f; sL[tid] = 0.f; }

    {
        int rr = tid >> 3, c8 = tid & 7;
        *(uint4*)&sQ[rr*72 + c8*8] =
            *(const uint4*)(g_projh + (size_t)(tbase+rr)*NC + COL_QA + h*64 + c8*8);
    }

    const uint32_t kBuf[2] = { sm_addr(sK0), sm_addr(sK1) };
    const uint32_t vBuf[2] = { sm_addr(sV0), sm_addr(sV1) };

    const int lrow = (lane & 7) + ((lane >> 3) & 1) * 8;
    const uint32_t aQb = sm_addr(&sQ[(r0 + lrow)*72 + (lane >> 4) * 8]);
    uint32_t aPb2[2];
    #pragma unroll
    for (int mi = 0; mi < 2; mi++)
        aPb2[mi] = sm_addr(&sP[(r32 + mi*16 + lrow)*72 + (lane >> 4) * 8]);
    uint32_t bKo[2];
    #pragma unroll
    for (int nt = 0; nt < 2; nt++)
        bKo[nt] = ((wq*16 + nt*8 + (lane & 7))*72 + ((lane >> 3) & 1) * 8) * 2;
    const uint32_t bVo = ((lane & 15) * 584) * 2;

    const int rA = r0 + g, rB = rA + 8;

    float o[2][9][4];
    #pragma unroll
    for (int mi = 0; mi < 2; mi++)
        #pragma unroll
        for (int nt = 0; nt < 9; nt++)
            #pragma unroll
            for (int c = 0; c < 4; c++) o[mi][nt][c] = 0.f;

    const int nJT = bx + 1;

    {
        const int jb = b * SEQ;
        {
            int rr = tid >> 3, c8 = tid & 7;
            cp16(kBuf[0] + (rr*72 + c8*8)*2,
                 g_projh + (size_t)(jb+rr)*NC + COL_KA + h*64 + c8*8);
        }
        for (int e = tid; e < 64 * 72; e += 512) {
            int rr = e / 72, c8 = e - rr * 72;
            const __half* src = (c8 < 8)
                ? g_svh + (size_t)(jb+rr)*512 + h*64 + c8*8
                : g_projh + (size_t)(jb+rr)*NC + COL_KR + (c8-8)*8;
            cp16(vBuf[0] + (rr*584 + c8*8)*2, src);
        }
        CP_COMMIT();
    }

    for (int jt = 0; jt < nJT; jt++) {
        const int cur = jt & 1, nxt = cur ^ 1;
        __syncthreads();
        if (jt + 1 < nJT) {
            const int jb = b * SEQ + (jt + 1) * 64;
            {
                int rr = tid >> 3, c8 = tid & 7;
                cp16(kBuf[nxt] + (rr*72 + c8*8)*2,
                     g_projh + (size_t)(jb+rr)*NC + COL_KA + h*64 + c8*8);
            }
            for (int e = tid; e < 64 * 72; e += 512) {
                int rr = e / 72, c8 = e - rr * 72;
                const __half* src = (c8 < 8)
                    ? g_svh + (size_t)(jb+rr)*512 + h*64 + c8*8
                    : g_projh + (size_t)(jb+rr)*NC + COL_KR + (c8-8)*8;
                cp16(vBuf[nxt] + (rr*584 + c8*8)*2, src);
            }
        }
        CP_COMMIT();
        CP_WAIT1();
        __syncthreads();

        // ---- S: warp (wband, wq) m16 x n16 ----
        float c_[2][4];
        #pragma unroll
        for (int nt = 0; nt < 2; nt++)
            #pragma unroll
            for (int q = 0; q < 4; q++) c_[nt][q] = 0.f;
        #pragma unroll
        for (int ks = 0; ks < 4; ks++) {
            uint32_t a4[4];
            ldsm4(a4, aQb + ks * 32);
            #pragma unroll
            for (int nt = 0; nt < 2; nt++) {
                uint32_t b2[2];
                ldsm2(b2, kBuf[cur] + bKo[nt] + ks * 32);
                mma_f16(c_[nt], a4, b2);
            }
        }
        const int rowA = i0 + rA, rowB = i0 + rB;
        float rmA = -1e30f, rmB = -1e30f;
        #pragma unroll
        for (int nt = 0; nt < 2; nt++) {
            int col = jt*64 + wq*16 + nt*8 + tig*2;
            c_[nt][0] = (col     <= rowA) ? c_[nt][0]*0.125f : -1e30f;
            c_[nt][1] = (col + 1 <= rowA) ? c_[nt][1]*0.125f : -1e30f;
            c_[nt][2] = (col     <= rowB) ? c_[nt][2]*0.125f : -1e30f;
            c_[nt][3] = (col + 1 <= rowB) ? c_[nt][3]*0.125f : -1e30f;
            rmA = fmaxf(rmA, fmaxf(c_[nt][0], c_[nt][1]));
            rmB = fmaxf(rmB, fmaxf(c_[nt][2], c_[nt][3]));
        }
        rmA = fmaxf(rmA, __shfl_xor_sync(0xffffffffu, rmA, 1));
        rmA = fmaxf(rmA, __shfl_xor_sync(0xffffffffu, rmA, 2));
        rmB = fmaxf(rmB, __shfl_xor_sync(0xffffffffu, rmB, 1));
        rmB = fmaxf(rmB, __shfl_xor_sync(0xffffffffu, rmB, 2));
        if (tig == 0) { sMaxP[wq*64 + rA] = rmA; sMaxP[wq*64 + rB] = rmB; }
        __syncthreads();

        float newmA = sM[rA], newmB = sM[rB];
        #pragma unroll
        for (int q2 = 0; q2 < 4; q2++) {
            newmA = fmaxf(newmA, sMaxP[q2*64 + rA]);
            newmB = fmaxf(newmB, sMaxP[q2*64 + rB]);
        }
        float corrA = __expf(sM[rA] - newmA);
        float corrB = __expf(sM[rB] - newmB);
        float sAcc = 0.f, sBcc = 0.f;
        #pragma unroll
        for (int nt = 0; nt < 2; nt++) {
            float p0 = __expf(c_[nt][0] - newmA);
            float p1 = __expf(c_[nt][1] - newmA);
            float p2 = __expf(c_[nt][2] - newmB);
            float p3 = __expf(c_[nt][3] - newmB);
            sAcc += p0 + p1; sBcc += p2 + p3;
            *(uint32_t*)&sP[rA*72 + wq*16 + nt*8 + tig*2] = pk2h(p0, p1);
            *(uint32_t*)&sP[rB*72 + wq*16 + nt*8 + tig*2] = pk2h(p2, p3);
        }
        sAcc += __shfl_xor_sync(0xffffffffu, sAcc, 1);
        sAcc += __shfl_xor_sync(0xffffffffu, sAcc, 2);
        sBcc += __shfl_xor_sync(0xffffffffu, sBcc, 1);
        sBcc += __shfl_xor_sync(0xffffffffu, sBcc, 2);
        if (tig == 0) { sSumP[wq*64 + rA] = sAcc; sSumP[wq*64 + rB] = sBcc; }
        if (wq == 0 && tig == 0) { sCorr[rA] = corrA; sCorr[rB] = corrB; }
        __syncthreads();

        if (wq == 0 && tig == 0) {
            float la = sL[rA]*corrA, lb = sL[rB]*corrB;
            #pragma unroll
            for (int q2 = 0; q2 < 4; q2++) {
                la += sSumP[q2*64 + rA];
                lb += sSumP[q2*64 + rB];
            }
            sM[rA] = newmA; sL[rA] = la;
            sM[rB] = newmB; sL[rB] = lb;
        }

        // ---- PV: warp (wband2, grp2) m32 x n72 ----
        #pragma unroll
        for (int mi = 0; mi < 2; mi++) {
            float cA = sCorr[r32 + mi*16 + g], cB = sCorr[r32 + mi*16 + g + 8];
            #pragma unroll
            for (int nt = 0; nt < 9; nt++) {
                o[mi][nt][0] *= cA; o[mi][nt][1] *= cA;
                o[mi][nt][2] *= cB; o[mi][nt][3] *= cB;
            }
        }
        #pragma unroll
        for (int ks = 0; ks < 4; ks++) {
            uint32_t a0[4], a1[4];
            ldsm4(a0, aPb2[0] + ks * 32);
            ldsm4(a1, aPb2[1] + ks * 32);
            #pragma unroll
            for (int nt = 0; nt < 9; nt++) {
                uint32_t b2[2];
                ldsm2t(b2, vBuf[cur] + bVo + ks * 18688 + (grp2*72 + nt*8) * 2);
                mma_f16(o[0][nt], a0, b2);
                mma_f16(o[1][nt], a1, b2);
            }
        }
    }

    __syncthreads();
    #pragma unroll
    for (int mi = 0; mi < 2; mi++) {
        const int rA2 = r32 + mi*16 + g, rB2 = rA2 + 8;
        const float invA = 1.f / sL[rA2];
        const float invB = 1.f / sL[rB2];
        const size_t akBase = ((size_t)blockIdx.y * SEQ + i0);
        #pragma unroll
        for (int nt = 0; nt < 9; nt++) {
            int col = grp2*72 + nt*8 + tig*2;
            if (col < 64) {
                *(float2*)&g_ra[(size_t)(tbase+rA2)*512 + h*64 + col] =
                    make_float2(o[mi][nt][0]*invA, o[mi][nt][1]*invA);
                *(float2*)&g_ra[(size_t)(tbase+rB2)*512 + h*64 + col] =
                    make_float2(o[mi][nt][2]*invB, o[mi][nt][3]*invB);
            } else {
                *(uint32_t*)&g_attkrh[(akBase + rA2)*512 + col - 64] =
                    pk2h(o[mi][nt][0]*invA, o[mi][nt][1]*invA);
                *(uint32_t*)&g_attkrh[(akBase + rB2)*512 + col - 64] =
                    pk2h(o[mi][nt][2]*invB, o[mi][nt][3]*invB);
            }
        }
    }
}

// ---------------------------------------------------------------------------
// ra_post v2 (unchanged)
// ---------------------------------------------------------------------------
__global__ void __launch_bounds__(256) ra_post2(const float* __restrict__ wr)
{
    __shared__ float swr[4096];
    const int tid = threadIdx.x;
    for (int i = tid; i < 4096; i += 256) {
        int h = i >> 9, rem = i & 511, d = rem >> 3, r = rem & 7;
        swr[h*512 + r*64 + d] = wr[i];
    }
    __syncthreads();

    const int lane = tid & 31;
    const int h    = tid >> 5;

    #pragma unroll
    for (int t = 0; t < 4; t++) {
        const int token = blockIdx.x * 4 + t;
        const int bb = token >> 11;
        const int ii = token & (SEQ - 1);

        const int r = lane >> 2, q = lane & 3;
        const __half2* q2 = (const __half2*)(g_projh + (size_t)token * NC + COL_QR + r*64 + q*16);
        const __half2* a2 = (const __half2*)(g_attkrh + (((size_t)(bb*8 + h)) * SEQ + ii) * 512 + r*64 + q*16);

        float part = 0.f;
        #pragma unroll
        for (int u = 0; u < 8; u++) {
            float2 qv = __half22float2(q2[u]);
            float2 av = __half22float2(a2[u]);
            part += qv.x*av.x + qv.y*av.y;
        }
        part += __shfl_xor_sync(0xffffffffu, part, 1);
        part += __shfl_xor_sync(0xffffffffu, part, 2);
        part *= 0.125f;

        float pr[8];
        #pragma unroll
        for (int r2 = 0; r2 < 8; r2++)
            pr[r2] = __shfl_sync(0xffffffffu, part, r2 << 2);

        const float2* sym = (const float2*)(g_ra + (size_t)token * 512 + h * 64 + lane * 2);
        float2 sv2 = *sym;
        float ro0 = 0.f, ro1 = 0.f;
        #pragma unroll
        for (int r2 = 0; r2 < 8; r2++) {
            float2 wv = *(const float2*)&swr[h*512 + r2*64 + lane*2];
            ro0 += pr[r2] * wv.x;
            ro1 += pr[r2] * wv.y;
        }
        *(uint32_t*)&g_rah[(size_t)token * 512 + h * 64 + lane * 2] =
            pk2h(sv2.x + ro0, sv2.y + ro1);
    }
}

// ---------------------------------------------------------------------------
extern "C" void kernel_launch(void* const* d_in, const int* in_sizes, int n_in,
                              void* d_out, int out_size)
{
    (void)in_sizes; (void)n_in; (void)out_size;
    const float* x      = (const float*)d_in[0];
    const float* symb   = (const float*)d_in[1];
    const float* fc     = (const float*)d_in[2];
    const float* fs     = (const float*)d_in[3];
    const float* wq_sa  = (const float*)d_in[4];
    const float* wk_sa  = (const float*)d_in[5];
    const float* wv_sa  = (const float*)d_in[6];
    const float* wo_sa  = (const float*)d_in[7];
    const float* wq_at  = (const float*)d_in[8];
    const float* wk_at  = (const float*)d_in[9];
    const float* wq_rel = (const float*)d_in[10];
    const float* wk_rel = (const float*)d_in[11];
    const float* wr     = (const float*)d_in[12];
    const float* wv_ra  = (const float*)d_in[13];
    const float* wo_ra  = (const float*)d_in[14];
    float* out = (float*)d_out;

    __half *h16, *projh, *svh, *sah, *rah;
    cudaGetSymbolAddress((void**)&h16,   g_h16);
    cudaGetSymbolAddress((void**)&projh, g_projh);
    cudaGetSymbolAddress((void**)&svh,   g_svh);
    cudaGetSymbolAddress((void**)&sah,   g_sah);
    cudaGetSymbolAddress((void**)&rah,   g_rah);

    cudaFuncSetAttribute(sa_flash8, cudaFuncAttributeMaxDynamicSharedMemorySize, SA8_SMEM);
    cudaFuncSetAttribute(ra_flash8, cudaFuncAttributeMaxDynamicSharedMemorySize, RA8_SMEM);

    // 0) convert all fp32 operands to the fp16 pool
    CvtArgs ca;
    const float* srcs[12] = { x, symb, wq_sa, wk_sa, wv_sa, wq_at, wk_at,
                              wq_rel, wk_rel, wv_ra, wo_sa, wo_ra };
    int sizes[12] = { NTOK*DM, NTOK*DM, W_SZ, W_SZ, W_SZ, W_SZ, W_SZ,
                      W_SZ, W_SZ, W_SZ, 512*512, 512*512 };
    int off = 0;
    for (int i = 0; i < 12; i++) { ca.src[i] = srcs[i]; ca.off[i] = off; off += sizes[i]; }
    ca.off[12] = off;
    cvt_kernel<<<(off / 4 + 255) / 256, 256>>>(ca);

    // 1) fused projections (blocks 0..6 from x, RoPE fused) + sv (block 7)
    W8h w8;
    for (int i = 0; i < 8; i++) w8.p[i] = h16 + OFF_W + i * W_SZ;
    gemm_h<<<dim3(32, NTOK / 128), 256>>>(h16 + OFF_X, h16 + OFF_SY, w8,
                                          nullptr, projh, svh, DM, NC, fc, fs);

    // 2) SA flash (pipelined, remapped PV)
    sa_flash8<<<dim3(SEQ / 64, BATCH * 8), 256, SA8_SMEM>>>();

    // 3) RA flash (pipelined, remapped PV) + rel post pass
    ra_flash8<<<dim3(SEQ / 64, BATCH * 8), 512, RA8_SMEM>>>();
    ra_post2<<<NTOK / 4, 256>>>(wr);

    // 4) both output projections in ONE launch (fp32 out)
    W8h wo;
    wo.p[0] = h16 + OFF_WOSA; wo.p[1] = h16 + OFF_WORA;
    for (int i = 2; i < 8; i++) wo.p[i] = h16 + OFF_WOSA;
    gemm_h<<<dim3(8, NTOK / 128), 256>>>(sah, rah, wo, out, nullptr, nullptr,
                                         512, 1024, nullptr, nullptr);
}

// round 16
// speedup vs baseline: 2.1361x; 1.0449x over previous
#include <cuda_runtime.h>
#include <cuda_fp16.h>
#include <cstdint>

#define BATCH 2
#define SEQ   2048
#define NTOK  (BATCH * SEQ)
#define DM    1024
#define NC    3584

#define COL_QSA 0
#define COL_KSA 512
#define COL_VSA 1024
#define COL_QA  1536
#define COL_KA  2048
#define COL_QR  2560
#define COL_KR  3072

// fp16 operand pool layout (halves)
#define OFF_X    0
#define OFF_SY   (NTOK*DM)
#define OFF_W    (2*NTOK*DM)
#define W_SZ     (512*DM)
#define OFF_WOSA (OFF_W + 8*W_SZ)
#define OFF_WORA (OFF_WOSA + 512*512)
#define H16_TOTAL (OFF_WORA + 512*512)

// Scratch (allocation-free rule: __device__ globals)
__device__ __half g_h16   [H16_TOTAL];
__device__ __half g_projh [NTOK * NC];
__device__ __half g_svh   [NTOK * 512];
__device__ __half g_sah   [NTOK * 512];
__device__ float  g_ra    [NTOK * 512];
__device__ __half g_rah   [NTOK * 512];
__device__ __half g_attkrh[16 * SEQ * 512];

struct W8h { const __half* p[8]; };
struct CvtArgs { const float* src[12]; int off[13]; };

// ---------------------------------------------------------------------------
// fp16 / mma / ldmatrix / cp.async helpers
// ---------------------------------------------------------------------------
__device__ __forceinline__ uint32_t pk2h(float a, float b) {
    __half2 h = __floats2half2_rn(a, b);
    return *reinterpret_cast<uint32_t*>(&h);
}
__device__ __forceinline__ void mma_f16(float* d, const uint32_t* a, const uint32_t* b) {
    asm volatile(
        "mma.sync.aligned.m16n8k16.row.col.f32.f16.f16.f32 "
        "{%0,%1,%2,%3}, {%4,%5,%6,%7}, {%8,%9}, {%0,%1,%2,%3};"
        : "+f"(d[0]), "+f"(d[1]), "+f"(d[2]), "+f"(d[3])
        : "r"(a[0]), "r"(a[1]), "r"(a[2]), "r"(a[3]), "r"(b[0]), "r"(b[1]));
}
__device__ __forceinline__ uint32_t sm_addr(const void* p) {
    return (uint32_t)__cvta_generic_to_shared(p);
}
__device__ __forceinline__ void ldsm4(uint32_t* r, uint32_t a) {
    asm volatile("ldmatrix.sync.aligned.m8n8.x4.shared.b16 {%0,%1,%2,%3}, [%4];"
        : "=r"(r[0]), "=r"(r[1]), "=r"(r[2]), "=r"(r[3]) : "r"(a));
}
__device__ __forceinline__ void ldsm2(uint32_t* r, uint32_t a) {
    asm volatile("ldmatrix.sync.aligned.m8n8.x2.shared.b16 {%0,%1}, [%2];"
        : "=r"(r[0]), "=r"(r[1]) : "r"(a));
}
__device__ __forceinline__ void ldsm2t(uint32_t* r, uint32_t a) {
    asm volatile("ldmatrix.sync.aligned.m8n8.x2.trans.shared.b16 {%0,%1}, [%2];"
        : "=r"(r[0]), "=r"(r[1]) : "r"(a));
}
__device__ __forceinline__ void cp16(uint32_t dst, const void* src) {
    asm volatile("cp.async.ca.shared.global [%0], [%1], 16;" :: "r"(dst), "l"(src));
}
#define CP_COMMIT() asm volatile("cp.async.commit_group;")
#define CP_WAIT1()  asm volatile("cp.async.wait_group 1;")

// ---------------------------------------------------------------------------
// cvt: fp32 -> fp16 pool
// ---------------------------------------------------------------------------
__global__ void __launch_bounds__(256) cvt_kernel(CvtArgs a)
{
    int e4 = (blockIdx.x * 256 + threadIdx.x) * 4;
    if (e4 >= a.off[12]) return;
    int seg = 0;
    #pragma unroll
    for (int s = 1; s < 12; s++) seg += (e4 >= a.off[s]);
    float4 v = *(const float4*)(a.src[seg] + (e4 - a.off[seg]));
    *(uint2*)&g_h16[e4] = make_uint2(pk2h(v.x, v.y), pk2h(v.z, v.w));
}

// ---------------------------------------------------------------------------
// fp16 tensor-core GEMM, 3-stage cp.async pipeline, ONE barrier per K-tile.
// Same fragment mapping / epilogue as the proven version.
// ---------------------------------------------------------------------------
#define GS_HALVES (128*40)              // one operand, one stage
#define GEMM_SMEM (3 * 2 * GS_HALVES * 2)   // 61440 bytes

__global__ void __launch_bounds__(256) gemm_h(
    const __half* __restrict__ A, const __half* __restrict__ A2,
    W8h w, float* __restrict__ C, __half* __restrict__ Ch,
    __half* __restrict__ Ch2, int K, int ldC,
    const float* __restrict__ fc, const float* __restrict__ fs)
{
    extern __shared__ __half sh[];      // [stage][A|B][128][40]

    const int tid   = threadIdx.x;
    const int lane  = tid & 31;
    const int wid   = tid >> 5;
    const int warpM = wid >> 2;
    const int warpN = wid & 3;
    const int g     = lane >> 2;
    const int tig   = lane & 3;

    const int mBase = blockIdx.y * 128;
    const int nBase = blockIdx.x * 128;
    const int blk   = nBase >> 9;
    const __half* Wm = w.p[blk];
    const bool projMode = (Ch != nullptr);
    const bool svBlk = projMode && (blk == 7);
    const __half* Ab = projMode ? (svBlk ? A2 : A) : (blk ? A2 : A);
    const int wrow  = nBase & 511;

    const __half* Aptr = Ab + (size_t)mBase * K;
    const __half* Bptr = Wm + (size_t)wrow  * K;

    float acc[4][4][4];
    #pragma unroll
    for (int mi = 0; mi < 4; mi++)
        #pragma unroll
        for (int ni = 0; ni < 4; ni++)
            #pragma unroll
            for (int c = 0; c < 4; c++) acc[mi][ni][c] = 0.f;

    // per-thread load coords (2 16B chunks per operand per stage)
    const int ldr = tid >> 2, ldq = tid & 3;

    // ldsm byte offsets within a stage (A at 0, B at +GS_HALVES*2)
    const int lrow = (lane & 7) + ((lane >> 3) & 1) * 8;
    uint32_t aOff[4], bOff[4];
    #pragma unroll
    for (int mi = 0; mi < 4; mi++)
        aOff[mi] = ((warpM*64 + mi*16 + lrow)*40 + (lane >> 4) * 8) * 2;
    #pragma unroll
    for (int ni = 0; ni < 4; ni++)
        bOff[ni] = GS_HALVES*2 + ((warpN*32 + ni*8 + (lane & 7))*40 + ((lane >> 3) & 1) * 8) * 2;

    const uint32_t shBase = sm_addr(sh);
    const uint32_t stageBytes = 2 * GS_HALVES * 2;

    const int nT = K >> 5;

    // issue loads for tile t into stage s (includes commit)
    auto load_tile = [&](int s, int t) {
        const int k0 = t << 5;
        uint32_t stA = shBase + s * stageBytes;
        uint32_t stB = stA + GS_HALVES * 2;
        cp16(stA + (ldr*40 + ldq*8)*2,        Aptr + (size_t)ldr * K + k0 + ldq*8);
        cp16(stA + ((ldr+64)*40 + ldq*8)*2,   Aptr + (size_t)(ldr+64) * K + k0 + ldq*8);
        cp16(stB + (ldr*40 + ldq*8)*2,        Bptr + (size_t)ldr * K + k0 + ldq*8);
        cp16(stB + ((ldr+64)*40 + ldq*8)*2,   Bptr + (size_t)(ldr+64) * K + k0 + ldq*8);
        CP_COMMIT();
    };

    load_tile(0, 0);
    load_tile(1, 1);

    for (int t = 0; t < nT; t++) {
        CP_WAIT1();
        __syncthreads();
        if (t + 2 < nT) load_tile((t + 2) % 3, t + 2);
        else            CP_COMMIT();            // empty group keeps WAIT1 honest

        const uint32_t stg = shBase + (t % 3) * stageBytes;
        #pragma unroll
        for (int ks = 0; ks < 2; ks++) {
            uint32_t a4[4][4], b2[4][2];
            #pragma unroll
            for (int mi = 0; mi < 4; mi++) ldsm4(a4[mi], stg + aOff[mi] + ks * 32);
            #pragma unroll
            for (int ni = 0; ni < 4; ni++) ldsm2(b2[ni], stg + bOff[ni] + ks * 32);
            #pragma unroll
            for (int mi = 0; mi < 4; mi++)
                #pragma unroll
                for (int ni = 0; ni < 4; ni++)
                    mma_f16(acc[mi][ni], a4[mi], b2[ni]);
        }
    }

    #pragma unroll
    for (int mi = 0; mi < 4; mi++) {
        int row = mBase + warpM * 64 + mi * 16 + g;
        int s0 = row & (SEQ - 1);
        int s1 = (row + 8) & (SEQ - 1);
        #pragma unroll
        for (int ni = 0; ni < 4; ni++) {
            int col = nBase + warpN * 32 + ni * 8 + tig * 2;
            float v0 = acc[mi][ni][0], v1 = acc[mi][ni][1];
            float v2 = acc[mi][ni][2], v3 = acc[mi][ni][3];
            if (projMode && !svBlk &&
                (col < 1024 || (col >= 1536 && col < 2560))) {
                int tt = (col & 63) >> 1;
                float c0 = fc[s0*32 + tt], sn0 = fs[s0*32 + tt];
                float c1 = fc[s1*32 + tt], sn1 = fs[s1*32 + tt];
                float n0 = v0*c0 - v1*sn0, n1 = v0*sn0 + v1*c0;
                float n2 = v2*c1 - v3*sn1, n3 = v2*sn1 + v3*c1;
                v0 = n0; v1 = n1; v2 = n2; v3 = n3;
            }
            if (projMode) {
                __half* dst = svBlk ? Ch2 : Ch;
                int ld     = svBlk ? 512 : ldC;
                int colOut = svBlk ? (col - 3584) : col;
                *(uint32_t*)&dst[(size_t)row * ld + colOut]       = pk2h(v0, v1);
                *(uint32_t*)&dst[(size_t)(row + 8) * ld + colOut] = pk2h(v2, v3);
            } else {
                *(float2*)&C[(size_t)row * ldC + col]       = make_float2(v0, v1);
                *(float2*)&C[(size_t)(row + 8) * ldC + col] = make_float2(v2, v3);
            }
        }
    }
}

// ---------------------------------------------------------------------------
// SA flash v8 + rescale skip
// ---------------------------------------------------------------------------
#define SA8_SMEM (6*64*72*2 + 448*4)

__global__ void __launch_bounds__(256) sa_flash8()
{
    extern __shared__ char smraw[];
    __half* sQ  = (__half*)smraw;
    __half* sK0 = sQ  + 64*72;
    __half* sK1 = sK0 + 64*72;
    __half* sP  = sK1 + 64*72;
    __half* sV0 = sP  + 64*72;
    __half* sV1 = sV0 + 64*72;
    float* sM    = (float*)(smraw + 6*64*72*2);
    float* sL    = sM + 64;
    float* sCorr = sL + 64;
    float* sMaxP = sCorr + 64;
    float* sSumP = sMaxP + 128;

    const int tid  = threadIdx.x;
    const int lane = tid & 31, wid = tid >> 5;
    const int g    = lane >> 2, tig = lane & 3;
    const int wband = wid & 3, whalf = wid >> 2;
    const int wband2 = wid & 1, grp2 = wid >> 1;
    const int r0   = wband * 16;
    const int r32  = wband2 * 32;
    const int b    = blockIdx.y >> 3, h = blockIdx.y & 7;
    const int bx   = gridDim.x - 1 - blockIdx.x;
    const int i0   = bx * 64;
    const int tbase = b * SEQ + i0;

    if (tid < 64) { sM[tid] = -1e30f; sL[tid] = 0.f; }

    #pragma unroll
    for (int u = 0; u < 2; u++) {
        int e = tid + (u << 8);
        int rr = e >> 3, c8 = e & 7;
        *(uint4*)&sQ[rr*72 + c8*8] =
            *(const uint4*)(g_projh + (size_t)(tbase+rr)*NC + COL_QSA + h*64 + c8*8);
    }

    const uint32_t kBuf[2] = { sm_addr(sK0), sm_addr(sK1) };
    const uint32_t vBuf[2] = { sm_addr(sV0), sm_addr(sV1) };

    const int lrow = (lane & 7) + ((lane >> 3) & 1) * 8;
    const uint32_t aQb = sm_addr(&sQ[(r0 + lrow)*72 + (lane >> 4) * 8]);
    uint32_t aPb2[2];
    #pragma unroll
    for (int mi = 0; mi < 2; mi++)
        aPb2[mi] = sm_addr(&sP[(r32 + mi*16 + lrow)*72 + (lane >> 4) * 8]);
    uint32_t bKo[4];
    #pragma unroll
    for (int nt = 0; nt < 4; nt++)
        bKo[nt] = ((whalf*32 + nt*8 + (lane & 7))*72 + ((lane >> 3) & 1) * 8) * 2;
    const uint32_t bVo = ((lane & 15) * 72) * 2;

    const int rA = r0 + g, rB = rA + 8;

    float o[2][2][4];
    #pragma unroll
    for (int mi = 0; mi < 2; mi++)
        #pragma unroll
        for (int nt = 0; nt < 2; nt++)
            #pragma unroll
            for (int c = 0; c < 4; c++) o[mi][nt][c] = 0.f;

    const int nJT = bx + 1;

    {
        const int jb = b * SEQ;
        #pragma unroll
        for (int u = 0; u < 2; u++) {
            int e = tid + (u << 8);
            int rr = e >> 3, c8 = e & 7;
            const __half* base = g_projh + (size_t)(jb+rr)*NC + h*64 + c8*8;
            cp16(kBuf[0] + (rr*72 + c8*8)*2, base + COL_KSA);
            cp16(vBuf[0] + (rr*72 + c8*8)*2, base + COL_VSA);
        }
        CP_COMMIT();
    }

    for (int jt = 0; jt < nJT; jt++) {
        const int cur = jt & 1, nxt = cur ^ 1;
        __syncthreads();
        if (jt + 1 < nJT) {
            const int jb = b * SEQ + (jt + 1) * 64;
            #pragma unroll
            for (int u = 0; u < 2; u++) {
                int e = tid + (u << 8);
                int rr = e >> 3, c8 = e & 7;
                const __half* base = g_projh + (size_t)(jb+rr)*NC + h*64 + c8*8;
                cp16(kBuf[nxt] + (rr*72 + c8*8)*2, base + COL_KSA);
                cp16(vBuf[nxt] + (rr*72 + c8*8)*2, base + COL_VSA);
            }
        }
        CP_COMMIT();
        CP_WAIT1();
        __syncthreads();

        float c_[4][4];
        #pragma unroll
        for (int nt = 0; nt < 4; nt++)
            #pragma unroll
            for (int q = 0; q < 4; q++) c_[nt][q] = 0.f;
        #pragma unroll
        for (int ks = 0; ks < 4; ks++) {
            uint32_t a4[4];
            ldsm4(a4, aQb + ks * 32);
            #pragma unroll
            for (int nt = 0; nt < 4; nt++) {
                uint32_t b2[2];
                ldsm2(b2, kBuf[cur] + bKo[nt] + ks * 32);
                mma_f16(c_[nt], a4, b2);
            }
        }
        const int rowA = i0 + rA, rowB = i0 + rB;
        float rmA = -1e30f, rmB = -1e30f;
        #pragma unroll
        for (int nt = 0; nt < 4; nt++) {
            int col = jt*64 + whalf*32 + nt*8 + tig*2;
            c_[nt][0] = (col     <= rowA) ? c_[nt][0]*0.125f : -1e30f;
            c_[nt][1] = (col + 1 <= rowA) ? c_[nt][1]*0.125f : -1e30f;
            c_[nt][2] = (col     <= rowB) ? c_[nt][2]*0.125f : -1e30f;
            c_[nt][3] = (col + 1 <= rowB) ? c_[nt][3]*0.125f : -1e30f;
            rmA = fmaxf(rmA, fmaxf(c_[nt][0], c_[nt][1]));
            rmB = fmaxf(rmB, fmaxf(c_[nt][2], c_[nt][3]));
        }
        rmA = fmaxf(rmA, __shfl_xor_sync(0xffffffffu, rmA, 1));
        rmA = fmaxf(rmA, __shfl_xor_sync(0xffffffffu, rmA, 2));
        rmB = fmaxf(rmB, __shfl_xor_sync(0xffffffffu, rmB, 1));
        rmB = fmaxf(rmB, __shfl_xor_sync(0xffffffffu, rmB, 2));
        if (tig == 0) { sMaxP[whalf*64 + rA] = rmA; sMaxP[whalf*64 + rB] = rmB; }
        __syncthreads();

        float newmA = fmaxf(sM[rA], fmaxf(sMaxP[rA], sMaxP[64 + rA]));
        float newmB = fmaxf(sM[rB], fmaxf(sMaxP[rB], sMaxP[64 + rB]));
        float corrA = __expf(sM[rA] - newmA);
        float corrB = __expf(sM[rB] - newmB);
        float sAcc = 0.f, sBcc = 0.f;
        #pragma unroll
        for (int nt = 0; nt < 4; nt++) {
            float p0 = __expf(c_[nt][0] - newmA);
            float p1 = __expf(c_[nt][1] - newmA);
            float p2 = __expf(c_[nt][2] - newmB);
            float p3 = __expf(c_[nt][3] - newmB);
            sAcc += p0 + p1; sBcc += p2 + p3;
            *(uint32_t*)&sP[rA*72 + whalf*32 + nt*8 + tig*2] = pk2h(p0, p1);
            *(uint32_t*)&sP[rB*72 + whalf*32 + nt*8 + tig*2] = pk2h(p2, p3);
        }
        sAcc += __shfl_xor_sync(0xffffffffu, sAcc, 1);
        sAcc += __shfl_xor_sync(0xffffffffu, sAcc, 2);
        sBcc += __shfl_xor_sync(0xffffffffu, sBcc, 1);
        sBcc += __shfl_xor_sync(0xffffffffu, sBcc, 2);
        if (tig == 0) { sSumP[whalf*64 + rA] = sAcc; sSumP[whalf*64 + rB] = sBcc; }
        if (whalf == 0 && tig == 0) { sCorr[rA] = corrA; sCorr[rB] = corrB; }
        __syncthreads();

        if (whalf == 0 && tig == 0) {
            sM[rA] = newmA; sL[rA] = sL[rA]*corrA + sSumP[rA] + sSumP[64 + rA];
            sM[rB] = newmB; sL[rB] = sL[rB]*corrB + sSumP[rB] + sSumP[64 + rB];
        }

        // ---- PV (rescale skipped when all corr == 1) ----
        {
            float c00 = sCorr[r32 + g],      c01 = sCorr[r32 + g + 8];
            float c10 = sCorr[r32 + 16 + g], c11 = sCorr[r32 + 16 + g + 8];
            bool any = (c00 != 1.f) || (c01 != 1.f) || (c10 != 1.f) || (c11 != 1.f);
            if (__any_sync(0xffffffffu, any)) {
                #pragma unroll
                for (int nt = 0; nt < 2; nt++) {
                    o[0][nt][0] *= c00; o[0][nt][1] *= c00;
                    o[0][nt][2] *= c01; o[0][nt][3] *= c01;
                    o[1][nt][0] *= c10; o[1][nt][1] *= c10;
                    o[1][nt][2] *= c11; o[1][nt][3] *= c11;
                }
            }
        }
        #pragma unroll
        for (int ks = 0; ks < 4; ks++) {
            uint32_t a0[4], a1[4];
            ldsm4(a0, aPb2[0] + ks * 32);
            ldsm4(a1, aPb2[1] + ks * 32);
            #pragma unroll
            for (int nt = 0; nt < 2; nt++) {
                uint32_t b2[2];
                ldsm2t(b2, vBuf[cur] + bVo + ks * 2304 + (grp2*16 + nt*8) * 2);
                mma_f16(o[0][nt], a0, b2);
                mma_f16(o[1][nt], a1, b2);
            }
        }
    }

    __syncthreads();
    #pragma unroll
    for (int mi = 0; mi < 2; mi++) {
        const int rA2 = r32 + mi*16 + g, rB2 = rA2 + 8;
        const float invA = 1.f / sL[rA2];
        const float invB = 1.f / sL[rB2];
        #pragma unroll
        for (int nt = 0; nt < 2; nt++) {
            int col = grp2*16 + nt*8 + tig*2;
            *(uint32_t*)&g_sah[(size_t)(tbase+rA2)*512 + h*64 + col] =
                pk2h(o[mi][nt][0]*invA, o[mi][nt][1]*invA);
            *(uint32_t*)&g_sah[(size_t)(tbase+rB2)*512 + h*64 + col] =
                pk2h(o[mi][nt][2]*invB, o[mi][nt][3]*invB);
        }
    }
}

// ---------------------------------------------------------------------------
// RA flash v8 + rescale skip
// ---------------------------------------------------------------------------
#define RA8_SMEM ((2*64*72 + 2*64*72 + 2*64*584)*2 + 704*4)

__global__ void __launch_bounds__(512) ra_flash8()
{
    extern __shared__ char smraw[];
    __half* sQ  = (__half*)smraw;
    __half* sK0 = sQ  + 64*72;
    __half* sK1 = sK0 + 64*72;
    __half* sP  = sK1 + 64*72;
    __half* sV0 = sP  + 64*72;
    __half* sV1 = sV0 + 64*584;
    float* sM    = (float*)(smraw + (4*64*72 + 2*64*584)*2);
    float* sL    = sM + 64;
    float* sCorr = sL + 64;
    float* sMaxP = sCorr + 64;
    float* sSumP = sMaxP + 256;

    const int tid  = threadIdx.x;
    const int lane = tid & 31, wid = tid >> 5;
    const int g    = lane >> 2, tig = lane & 3;
    const int wband = wid & 3, wq = wid >> 2;
    const int wband2 = wid & 1, grp2 = wid >> 1;
    const int r0   = wband * 16;
    const int r32  = wband2 * 32;
    const int b    = blockIdx.y >> 3, h = blockIdx.y & 7;
    const int bx   = gridDim.x - 1 - blockIdx.x;
    const int i0   = bx * 64;
    const int tbase = b * SEQ + i0;

    if (tid < 64) { sM[tid] = -1e30f; sL[tid] = 0.f; }

    {
        int rr = tid >> 3, c8 = tid & 7;
        *(uint4*)&sQ[rr*72 + c8*8] =
            *(const uint4*)(g_projh + (size_t)(tbase+rr)*NC + COL_QA + h*64 + c8*8);
    }

    const uint32_t kBuf[2] = { sm_addr(sK0), sm_addr(sK1) };
    const uint32_t vBuf[2] = { sm_addr(sV0), sm_addr(sV1) };

    const int lrow = (lane & 7) + ((lane >> 3) & 1) * 8;
    const uint32_t aQb = sm_addr(&sQ[(r0 + lrow)*72 + (lane >> 4) * 8]);
    uint32_t aPb2[2];
    #pragma unroll
    for (int mi = 0; mi < 2; mi++)
        aPb2[mi] = sm_addr(&sP[(r32 + mi*16 + lrow)*72 + (lane >> 4) * 8]);
    uint32_t bKo[2];
    #pragma unroll
    for (int nt = 0; nt < 2; nt++)
        bKo[nt] = ((wq*16 + nt*8 + (lane & 7))*72 + ((lane >> 3) & 1) * 8) * 2;
    const uint32_t bVo = ((lane & 15) * 584) * 2;

    const int rA = r0 + g, rB = rA + 8;

    float o[2][9][4];
    #pragma unroll
    for (int mi = 0; mi < 2; mi++)
        #pragma unroll
        for (int nt = 0; nt < 9; nt++)
            #pragma unroll
            for (int c = 0; c < 4; c++) o[mi][nt][c] = 0.f;

    const int nJT = bx + 1;

    {
        const int jb = b * SEQ;
        {
            int rr = tid >> 3, c8 = tid & 7;
            cp16(kBuf[0] + (rr*72 + c8*8)*2,
                 g_projh + (size_t)(jb+rr)*NC + COL_KA + h*64 + c8*8);
        }
        for (int e = tid; e < 64 * 72; e += 512) {
            int rr = e / 72, c8 = e - rr * 72;
            const __half* src = (c8 < 8)
                ? g_svh + (size_t)(jb+rr)*512 + h*64 + c8*8
                : g_projh + (size_t)(jb+rr)*NC + COL_KR + (c8-8)*8;
            cp16(vBuf[0] + (rr*584 + c8*8)*2, src);
        }
        CP_COMMIT();
    }

    for (int jt = 0; jt < nJT; jt++) {
        const int cur = jt & 1, nxt = cur ^ 1;
        __syncthreads();
        if (jt + 1 < nJT) {
            const int jb = b * SEQ + (jt + 1) * 64;
            {
                int rr = tid >> 3, c8 = tid & 7;
                cp16(kBuf[nxt] + (rr*72 + c8*8)*2,
                     g_projh + (size_t)(jb+rr)*NC + COL_KA + h*64 + c8*8);
            }
            for (int e = tid; e < 64 * 72; e += 512) {
                int rr = e / 72, c8 = e - rr * 72;
                const __half* src = (c8 < 8)
                    ? g_svh + (size_t)(jb+rr)*512 + h*64 + c8*8
                    : g_projh + (size_t)(jb+rr)*NC + COL_KR + (c8-8)*8;
                cp16(vBuf[nxt] + (rr*584 + c8*8)*2, src);
            }
        }
        CP_COMMIT();
        CP_WAIT1();
        __syncthreads();

        float c_[2][4];
        #pragma unroll
        for (int nt = 0; nt < 2; nt++)
            #pragma unroll
            for (int q = 0; q < 4; q++) c_[nt][q] = 0.f;
        #pragma unroll
        for (int ks = 0; ks < 4; ks++) {
            uint32_t a4[4];
            ldsm4(a4, aQb + ks * 32);
            #pragma unroll
            for (int nt = 0; nt < 2; nt++) {
                uint32_t b2[2];
                ldsm2(b2, kBuf[cur] + bKo[nt] + ks * 32);
                mma_f16(c_[nt], a4, b2);
            }
        }
        const int rowA = i0 + rA, rowB = i0 + rB;
        float rmA = -1e30f, rmB = -1e30f;
        #pragma unroll
        for (int nt = 0; nt < 2; nt++) {
            int col = jt*64 + wq*16 + nt*8 + tig*2;
            c_[nt][0] = (col     <= rowA) ? c_[nt][0]*0.125f : -1e30f;
            c_[nt][1] = (col + 1 <= rowA) ? c_[nt][1]*0.125f : -1e30f;
            c_[nt][2] = (col     <= rowB) ? c_[nt][2]*0.125f : -1e30f;
            c_[nt][3] = (col + 1 <= rowB) ? c_[nt][3]*0.125f : -1e30f;
            rmA = fmaxf(rmA, fmaxf(c_[nt][0], c_[nt][1]));
            rmB = fmaxf(rmB, fmaxf(c_[nt][2], c_[nt][3]));
        }
        rmA = fmaxf(rmA, __shfl_xor_sync(0xffffffffu, rmA, 1));
        rmA = fmaxf(rmA, __shfl_xor_sync(0xffffffffu, rmA, 2));
        rmB = fmaxf(rmB, __shfl_xor_sync(0xffffffffu, rmB, 1));
        rmB = fmaxf(rmB, __shfl_xor_sync(0xffffffffu, rmB, 2));
        if (tig == 0) { sMaxP[wq*64 + rA] = rmA; sMaxP[wq*64 + rB] = rmB; }
        __syncthreads();

        float newmA = sM[rA], newmB = sM[rB];
        #pragma unroll
        for (int q2 = 0; q2 < 4; q2++) {
            newmA = fmaxf(newmA, sMaxP[q2*64 + rA]);
            newmB = fmaxf(newmB, sMaxP[q2*64 + rB]);
        }
        float corrA = __expf(sM[rA] - newmA);
        float corrB = __expf(sM[rB] - newmB);
        float sAcc = 0.f, sBcc = 0.f;
        #pragma unroll
        for (int nt = 0; nt < 2; nt++) {
            float p0 = __expf(c_[nt][0] - newmA);
            float p1 = __expf(c_[nt][1] - newmA);
            float p2 = __expf(c_[nt][2] - newmB);
            float p3 = __expf(c_[nt][3] - newmB);
            sAcc += p0 + p1; sBcc += p2 + p3;
            *(uint32_t*)&sP[rA*72 + wq*16 + nt*8 + tig*2] = pk2h(p0, p1);
            *(uint32_t*)&sP[rB*72 + wq*16 + nt*8 + tig*2] = pk2h(p2, p3);
        }
        sAcc += __shfl_xor_sync(0xffffffffu, sAcc, 1);
        sAcc += __shfl_xor_sync(0xffffffffu, sAcc, 2);
        sBcc += __shfl_xor_sync(0xffffffffu, sBcc, 1);
        sBcc += __shfl_xor_sync(0xffffffffu, sBcc, 2);
        if (tig == 0) { sSumP[wq*64 + rA] = sAcc; sSumP[wq*64 + rB] = sBcc; }
        if (wq == 0 && tig == 0) { sCorr[rA] = corrA; sCorr[rB] = corrB; }
        __syncthreads();

        if (wq == 0 && tig == 0) {
            float la = sL[rA]*corrA, lb = sL[rB]*corrB;
            #pragma unroll
            for (int q2 = 0; q2 < 4; q2++) {
                la += sSumP[q2*64 + rA];
                lb += sSumP[q2*64 + rB];
            }
            sM[rA] = newmA; sL[rA] = la;
            sM[rB] = newmB; sL[rB] = lb;
        }

        // ---- PV (rescale skipped when all corr == 1) ----
        {
            float c00 = sCorr[r32 + g],      c01 = sCorr[r32 + g + 8];
            float c10 = sCorr[r32 + 16 + g], c11 = sCorr[r32 + 16 + g + 8];
            bool any = (c00 != 1.f) || (c01 != 1.f) || (c10 != 1.f) || (c11 != 1.f);
            if (__any_sync(0xffffffffu, any)) {
                #pragma unroll
                for (int nt = 0; nt < 9; nt++) {
                    o[0][nt][0] *= c00; o[0][nt][1] *= c00;
                    o[0][nt][2] *= c01; o[0][nt][3] *= c01;
                    o[1][nt][0] *= c10; o[1][nt][1] *= c10;
                    o[1][nt][2] *= c11; o[1][nt][3] *= c11;
                }
            }
        }
        #pragma unroll
        for (int ks = 0; ks < 4; ks++) {
            uint32_t a0[4], a1[4];
            ldsm4(a0, aPb2[0] + ks * 32);
            ldsm4(a1, aPb2[1] + ks * 32);
            #pragma unroll
            for (int nt = 0; nt < 9; nt++) {
                uint32_t b2[2];
                ldsm2t(b2, vBuf[cur] + bVo + ks * 18688 + (grp2*72 + nt*8) * 2);
                mma_f16(o[0][nt], a0, b2);
                mma_f16(o[1][nt], a1, b2);
            }
        }
    }

    __syncthreads();
    #pragma unroll
    for (int mi = 0; mi < 2; mi++) {
        const int rA2 = r32 + mi*16 + g, rB2 = rA2 + 8;
        const float invA = 1.f / sL[rA2];
        const float invB = 1.f / sL[rB2];
        const size_t akBase = ((size_t)blockIdx.y * SEQ + i0);
        #pragma unroll
        for (int nt = 0; nt < 9; nt++) {
            int col = grp2*72 + nt*8 + tig*2;
            if (col < 64) {
                *(float2*)&g_ra[(size_t)(tbase+rA2)*512 + h*64 + col] =
                    make_float2(o[mi][nt][0]*invA, o[mi][nt][1]*invA);
                *(float2*)&g_ra[(size_t)(tbase+rB2)*512 + h*64 + col] =
                    make_float2(o[mi][nt][2]*invB, o[mi][nt][3]*invB);
            } else {
                *(uint32_t*)&g_attkrh[(akBase + rA2)*512 + col - 64] =
                    pk2h(o[mi][nt][0]*invA, o[mi][nt][1]*invA);
                *(uint32_t*)&g_attkrh[(akBase + rB2)*512 + col - 64] =
                    pk2h(o[mi][nt][2]*invB, o[mi][nt][3]*invB);
            }
        }
    }
}

// ---------------------------------------------------------------------------
// ra_post v2 (unchanged)
// ---------------------------------------------------------------------------
__global__ void __launch_bounds__(256) ra_post2(const float* __restrict__ wr)
{
    __shared__ float swr[4096];
    const int tid = threadIdx.x;
    for (int i = tid; i < 4096; i += 256) {
        int h = i >> 9, rem = i & 511, d = rem >> 3, r = rem & 7;
        swr[h*512 + r*64 + d] = wr[i];
    }
    __syncthreads();

    const int lane = tid & 31;
    const int h    = tid >> 5;

    #pragma unroll
    for (int t = 0; t < 4; t++) {
        const int token = blockIdx.x * 4 + t;
        const int bb = token >> 11;
        const int ii = token & (SEQ - 1);

        const int r = lane >> 2, q = lane & 3;
        const __half2* q2 = (const __half2*)(g_projh + (size_t)token * NC + COL_QR + r*64 + q*16);
        const __half2* a2 = (const __half2*)(g_attkrh + (((size_t)(bb*8 + h)) * SEQ + ii) * 512 + r*64 + q*16);

        float part = 0.f;
        #pragma unroll
        for (int u = 0; u < 8; u++) {
            float2 qv = __half22float2(q2[u]);
            float2 av = __half22float2(a2[u]);
            part += qv.x*av.x + qv.y*av.y;
        }
        part += __shfl_xor_sync(0xffffffffu, part, 1);
        part += __shfl_xor_sync(0xffffffffu, part, 2);
        part *= 0.125f;

        float pr[8];
        #pragma unroll
        for (int r2 = 0; r2 < 8; r2++)
            pr[r2] = __shfl_sync(0xffffffffu, part, r2 << 2);

        const float2* sym = (const float2*)(g_ra + (size_t)token * 512 + h * 64 + lane * 2);
        float2 sv2 = *sym;
        float ro0 = 0.f, ro1 = 0.f;
        #pragma unroll
        for (int r2 = 0; r2 < 8; r2++) {
            float2 wv = *(const float2*)&swr[h*512 + r2*64 + lane*2];
            ro0 += pr[r2] * wv.x;
            ro1 += pr[r2] * wv.y;
        }
        *(uint32_t*)&g_rah[(size_t)token * 512 + h * 64 + lane * 2] =
            pk2h(sv2.x + ro0, sv2.y + ro1);
    }
}

// ---------------------------------------------------------------------------
extern "C" void kernel_launch(void* const* d_in, const int* in_sizes, int n_in,
                              void* d_out, int out_size)
{
    (void)in_sizes; (void)n_in; (void)out_size;
    const float* x      = (const float*)d_in[0];
    const float* symb   = (const float*)d_in[1];
    const float* fc     = (const float*)d_in[2];
    const float* fs     = (const float*)d_in[3];
    const float* wq_sa  = (const float*)d_in[4];
    const float* wk_sa  = (const float*)d_in[5];
    const float* wv_sa  = (const float*)d_in[6];
    const float* wo_sa  = (const float*)d_in[7];
    const float* wq_at  = (const float*)d_in[8];
    const float* wk_at  = (const float*)d_in[9];
    const float* wq_rel = (const float*)d_in[10];
    const float* wk_rel = (const float*)d_in[11];
    const float* wr     = (const float*)d_in[12];
    const float* wv_ra  = (const float*)d_in[13];
    const float* wo_ra  = (const float*)d_in[14];
    float* out = (float*)d_out;

    __half *h16, *projh, *svh, *sah, *rah;
    cudaGetSymbolAddress((void**)&h16,   g_h16);
    cudaGetSymbolAddress((void**)&projh, g_projh);
    cudaGetSymbolAddress((void**)&svh,   g_svh);
    cudaGetSymbolAddress((void**)&sah,   g_sah);
    cudaGetSymbolAddress((void**)&rah,   g_rah);

    cudaFuncSetAttribute(gemm_h,    cudaFuncAttributeMaxDynamicSharedMemorySize, GEMM_SMEM);
    cudaFuncSetAttribute(sa_flash8, cudaFuncAttributeMaxDynamicSharedMemorySize, SA8_SMEM);
    cudaFuncSetAttribute(ra_flash8, cudaFuncAttributeMaxDynamicSharedMemorySize, RA8_SMEM);

    // 0) convert all fp32 operands to the fp16 pool
    CvtArgs ca;
    const float* srcs[12] = { x, symb, wq_sa, wk_sa, wv_sa, wq_at, wk_at,
                              wq_rel, wk_rel, wv_ra, wo_sa, wo_ra };
    int sizes[12] = { NTOK*DM, NTOK*DM, W_SZ, W_SZ, W_SZ, W_SZ, W_SZ,
                      W_SZ, W_SZ, W_SZ, 512*512, 512*512 };
    int off = 0;
    for (int i = 0; i < 12; i++) { ca.src[i] = srcs[i]; ca.off[i] = off; off += sizes[i]; }
    ca.off[12] = off;
    cvt_kernel<<<(off / 4 + 255) / 256, 256>>>(ca);

    // 1) fused projections (blocks 0..6 from x, RoPE fused) + sv (block 7)
    W8h w8;
    for (int i = 0; i < 8; i++) w8.p[i] = h16 + OFF_W + i * W_SZ;
    gemm_h<<<dim3(32, NTOK / 128), 256, GEMM_SMEM>>>(h16 + OFF_X, h16 + OFF_SY, w8,
                                          nullptr, projh, svh, DM, NC, fc, fs);

    // 2) SA flash (pipelined, rescale-skip)
    sa_flash8<<<dim3(SEQ / 64, BATCH * 8), 256, SA8_SMEM>>>();

    // 3) RA flash (pipelined, rescale-skip) + rel post pass
    ra_flash8<<<dim3(SEQ / 64, BATCH * 8), 512, RA8_SMEM>>>();
    ra_post2<<<NTOK / 4, 256>>>(wr);

    // 4) both output projections in ONE launch (fp32 out)
    W8h wo;
    wo.p[0] = h16 + OFF_WOSA; wo.p[1] = h16 + OFF_WORA;
    for (int i = 2; i < 8; i++) wo.p[i] = h16 + OFF_WOSA;
    gemm_h<<<dim3(8, NTOK / 128), 256, GEMM_SMEM>>>(sah, rah, wo, out, nullptr, nullptr,
                                         512, 1024, nullptr, nullptr);
}